// round 1
// baseline (speedup 1.0000x reference)
#include <cuda_runtime.h>
#include <math.h>

#define NN 50000
#define EE 800000
#define IND 256
#define HIDD 64
#define H0 4
#define OUT1 256
#define NCLS 64
#define NEG 0.2f

// ---------------- scratch (device globals; no allocation allowed) ----------
__device__ float g_ft[NN * 256];    // layer0 ft, reused as layer1 ft
__device__ float g_rst[NN * 256];   // aggregation target (both layers)
__device__ float g_h1[NN * 256];    // layer0 output / layer1 residual input
__device__ float g_e[EE * H0];      // per-edge logits -> exp weights
__device__ float g_el[NN * H0];
__device__ float g_er[NN * H0];
__device__ float g_emax[NN * H0];
__device__ float g_asum[NN * H0];

// ---------------- helpers ---------------------------------------------------
__device__ __forceinline__ void atomicMaxFloat(float* addr, float v) {
    if (v >= 0.0f) atomicMax((int*)addr, __float_as_int(v));
    else           atomicMin((unsigned int*)addr, __float_as_uint(v));
}

// ---------------- SGEMM: C[Nr,M] = A[Nr,K] @ B[K,M] (+bias) ----------------
// BM=64 BN=64 BK=16, 256 threads, 4x4 micro-tile per thread.
__global__ void sgemm_kernel(const float* __restrict__ A,
                             const float* __restrict__ B,
                             float* __restrict__ Cm,
                             int Nr, int K, int M,
                             const float* __restrict__ bias) {
    const int BM = 64, BN = 64, BK = 16, TM = 4, TN = 4;
    __shared__ float As[BK][BM];
    __shared__ float Bs[BK][BN];
    int tid = threadIdx.x;
    int tx = tid % (BN / TN);   // 0..15
    int ty = tid / (BN / TN);   // 0..15
    int rowBase = blockIdx.y * BM;
    int colBase = blockIdx.x * BN;

    float acc[TM][TN];
#pragma unroll
    for (int i = 0; i < TM; i++)
#pragma unroll
        for (int j = 0; j < TN; j++) acc[i][j] = 0.0f;

    for (int k0 = 0; k0 < K; k0 += BK) {
        // load A tile (BM x BK), store transposed
#pragma unroll
        for (int i = tid; i < BM * BK; i += 256) {
            int m = i / BK, kk = i % BK;
            int gr = rowBase + m;
            As[kk][m] = (gr < Nr) ? A[(long)gr * K + k0 + kk] : 0.0f;
        }
        // load B tile (BK x BN)
#pragma unroll
        for (int i = tid; i < BK * BN; i += 256) {
            int kk = i / BN, n = i % BN;
            Bs[kk][n] = B[(long)(k0 + kk) * M + colBase + n];
        }
        __syncthreads();
#pragma unroll
        for (int kk = 0; kk < BK; kk++) {
            float a[TM], b[TN];
#pragma unroll
            for (int i = 0; i < TM; i++) a[i] = As[kk][ty * TM + i];
#pragma unroll
            for (int j = 0; j < TN; j++) b[j] = Bs[kk][tx * TN + j];
#pragma unroll
            for (int i = 0; i < TM; i++)
#pragma unroll
                for (int j = 0; j < TN; j++) acc[i][j] += a[i] * b[j];
        }
        __syncthreads();
    }
#pragma unroll
    for (int i = 0; i < TM; i++) {
        int gr = rowBase + ty * TM + i;
        if (gr >= Nr) continue;
#pragma unroll
        for (int j = 0; j < TN; j++) {
            int gc = colBase + tx * TN + j;
            float v = acc[i][j];
            if (bias) v += bias[gc];
            Cm[(long)gr * M + gc] = v;
        }
    }
}

// ---------------- layer 0 kernels -------------------------------------------
__global__ void el_er0_kernel(const float* __restrict__ ft,
                              const float* __restrict__ al,
                              const float* __restrict__ ar,
                              float* __restrict__ el, float* __restrict__ er,
                              float* __restrict__ emax, float* __restrict__ asum) {
    int i = blockIdx.x * blockDim.x + threadIdx.x;   // n*H0 + h
    if (i >= NN * H0) return;
    int h = i & (H0 - 1);
    const float* f = ft + (long)i * HIDD;
    const float* pal = al + h * HIDD;
    const float* par = ar + h * HIDD;
    float sl = 0.0f, sr = 0.0f;
#pragma unroll 8
    for (int d = 0; d < HIDD; d++) { float v = f[d]; sl += v * pal[d]; sr += v * par[d]; }
    el[i] = sl; er[i] = sr;
    emax[i] = -INFINITY;
    asum[i] = 0.0f;
}

__global__ void edge_max0_kernel(const int* __restrict__ src, const int* __restrict__ dst,
                                 const float* __restrict__ el, const float* __restrict__ er,
                                 float* __restrict__ ebuf, float* __restrict__ emax) {
    int i = blockIdx.x * blockDim.x + threadIdx.x;   // edge*H0 + h
    if (i >= EE * H0) return;
    int eidx = i >> 2;
    int h = i & 3;
    int s = src[eidx], d = dst[eidx];
    float v = el[s * H0 + h] + er[d * H0 + h];
    v = (v >= 0.0f) ? v : NEG * v;
    ebuf[i] = v;
    atomicMaxFloat(&emax[d * H0 + h], v);
}

__global__ void edge_exp0_kernel(const int* __restrict__ dst,
                                 float* __restrict__ ebuf,
                                 const float* __restrict__ emax,
                                 float* __restrict__ asum) {
    int i = blockIdx.x * blockDim.x + threadIdx.x;
    if (i >= EE * H0) return;
    int eidx = i >> 2;
    int h = i & 3;
    int d = dst[eidx];
    float a = expf(ebuf[i] - emax[d * H0 + h]);
    ebuf[i] = a;
    atomicAdd(&asum[d * H0 + h], a);
}

__global__ void fill_zero_kernel(float* __restrict__ p, int n) {
    int i = blockIdx.x * blockDim.x + threadIdx.x;
    if (i < n) p[i] = 0.0f;
}

__global__ void scatter0_kernel(const int* __restrict__ src, const int* __restrict__ dst,
                                const float* __restrict__ ebuf, const float* __restrict__ asum,
                                const float* __restrict__ ft, float* __restrict__ rst) {
    int eidx = blockIdx.x;
    int t = threadIdx.x;           // 0..255 feature index
    int h = t >> 6;
    int s = src[eidx], d = dst[eidx];
    float alpha = ebuf[eidx * H0 + h] / asum[d * H0 + h];
    atomicAdd(&rst[(long)d * 256 + t], alpha * ft[(long)s * 256 + t]);
}

__global__ void bias_elu_kernel(const float* __restrict__ rst,
                                const float* __restrict__ b0,
                                float* __restrict__ h1) {
    int i = blockIdx.x * blockDim.x + threadIdx.x;
    if (i >= NN * 256) return;
    float v = rst[i] + b0[i & 255];
    h1[i] = (v > 0.0f) ? v : expm1f(v);
}

// ---------------- layer 1 kernels (H=1, D=256) -------------------------------
__global__ void el_er1_kernel(const float* __restrict__ ft,
                              const float* __restrict__ al,
                              const float* __restrict__ ar,
                              float* __restrict__ el, float* __restrict__ er,
                              float* __restrict__ emax, float* __restrict__ asum) {
    int n = blockIdx.x * (blockDim.x >> 5) + (threadIdx.x >> 5);
    int lane = threadIdx.x & 31;
    if (n >= NN) return;
    float sl = 0.0f, sr = 0.0f;
    const float* f = ft + (long)n * 256;
#pragma unroll
    for (int d = lane; d < 256; d += 32) { float v = f[d]; sl += v * al[d]; sr += v * ar[d]; }
#pragma unroll
    for (int o = 16; o; o >>= 1) {
        sl += __shfl_down_sync(0xffffffffu, sl, o);
        sr += __shfl_down_sync(0xffffffffu, sr, o);
    }
    if (lane == 0) { el[n] = sl; er[n] = sr; emax[n] = -INFINITY; asum[n] = 0.0f; }
}

__global__ void edge_max1_kernel(const int* __restrict__ src, const int* __restrict__ dst,
                                 const float* __restrict__ el, const float* __restrict__ er,
                                 float* __restrict__ ebuf, float* __restrict__ emax) {
    int e = blockIdx.x * blockDim.x + threadIdx.x;
    if (e >= EE) return;
    int s = src[e], d = dst[e];
    float v = el[s] + er[d];
    v = (v >= 0.0f) ? v : NEG * v;
    ebuf[e] = v;
    atomicMaxFloat(&emax[d], v);
}

__global__ void edge_exp1_kernel(const int* __restrict__ dst,
                                 float* __restrict__ ebuf,
                                 const float* __restrict__ emax,
                                 float* __restrict__ asum) {
    int e = blockIdx.x * blockDim.x + threadIdx.x;
    if (e >= EE) return;
    int d = dst[e];
    float a = expf(ebuf[e] - emax[d]);
    ebuf[e] = a;
    atomicAdd(&asum[d], a);
}

__global__ void scatter1_kernel(const int* __restrict__ src, const int* __restrict__ dst,
                                const float* __restrict__ ebuf, const float* __restrict__ asum,
                                const float* __restrict__ ft, float* __restrict__ rst) {
    int eidx = blockIdx.x;
    int t = threadIdx.x;
    int s = src[eidx], d = dst[eidx];
    float alpha = ebuf[eidx] / asum[d];
    atomicAdd(&rst[(long)d * 256 + t], alpha * ft[(long)s * 256 + t]);
}

__global__ void final_h_kernel(const float* __restrict__ rst,
                               const float* __restrict__ h1,
                               const float* __restrict__ b1,
                               float* __restrict__ hout) {
    int i = blockIdx.x * blockDim.x + threadIdx.x;
    if (i >= NN * 256) return;
    hout[i] = rst[i] + h1[i] + b1[i & 255];
}

// ---------------- launch -----------------------------------------------------
extern "C" void kernel_launch(void* const* d_in, const int* in_sizes, int n_in,
                              void* d_out, int out_size) {
    const float* x   = (const float*)d_in[0];
    const int*   src = (const int*)  d_in[1];
    const int*   dst = (const int*)  d_in[2];
    const float* W0  = (const float*)d_in[3];
    const float* al0 = (const float*)d_in[4];
    const float* ar0 = (const float*)d_in[5];
    const float* b0  = (const float*)d_in[6];
    const float* W1  = (const float*)d_in[7];
    const float* al1 = (const float*)d_in[8];
    const float* ar1 = (const float*)d_in[9];
    const float* b1  = (const float*)d_in[10];
    const float* Wl  = (const float*)d_in[11];
    const float* bl  = (const float*)d_in[12];

    float* out    = (float*)d_out;
    float* logits = out;                 // [NN, NCLS]
    float* hout   = out + (long)NN * NCLS;  // [NN, OUT1]

    float *ft, *rst, *h1v, *ebuf, *el, *er, *emax, *asum;
    cudaGetSymbolAddress((void**)&ft,   g_ft);
    cudaGetSymbolAddress((void**)&rst,  g_rst);
    cudaGetSymbolAddress((void**)&h1v,  g_h1);
    cudaGetSymbolAddress((void**)&ebuf, g_e);
    cudaGetSymbolAddress((void**)&el,   g_el);
    cudaGetSymbolAddress((void**)&er,   g_er);
    cudaGetSymbolAddress((void**)&emax, g_emax);
    cudaGetSymbolAddress((void**)&asum, g_asum);

    const int T = 256;
    dim3 gemmGrid(256 / 64, (NN + 63) / 64);

    // ---- layer 0 ----
    sgemm_kernel<<<gemmGrid, T>>>(x, W0, ft, NN, IND, 256, nullptr);
    el_er0_kernel<<<(NN * H0 + T - 1) / T, T>>>(ft, al0, ar0, el, er, emax, asum);
    edge_max0_kernel<<<(EE * H0 + T - 1) / T, T>>>(src, dst, el, er, ebuf, emax);
    edge_exp0_kernel<<<(EE * H0 + T - 1) / T, T>>>(dst, ebuf, emax, asum);
    fill_zero_kernel<<<(NN * 256 + T - 1) / T, T>>>(rst, NN * 256);
    scatter0_kernel<<<EE, T>>>(src, dst, ebuf, asum, ft, rst);
    bias_elu_kernel<<<(NN * 256 + T - 1) / T, T>>>(rst, b0, h1v);

    // ---- layer 1 ----
    sgemm_kernel<<<gemmGrid, T>>>(h1v, W1, ft, NN, 256, 256, nullptr);
    el_er1_kernel<<<(NN + 7) / 8, T>>>(ft, al1, ar1, el, er, emax, asum);
    edge_max1_kernel<<<(EE + T - 1) / T, T>>>(src, dst, el, er, ebuf, emax);
    edge_exp1_kernel<<<(EE + T - 1) / T, T>>>(dst, ebuf, emax, asum);
    fill_zero_kernel<<<(NN * 256 + T - 1) / T, T>>>(rst, NN * 256);
    scatter1_kernel<<<EE, T>>>(src, dst, ebuf, asum, ft, rst);
    final_h_kernel<<<(NN * 256 + T - 1) / T, T>>>(rst, h1v, b1, hout);

    // ---- classifier ----
    dim3 clsGrid(NCLS / 64, (NN + 63) / 64);
    sgemm_kernel<<<clsGrid, T>>>(hout, Wl, logits, NN, OUT1, NCLS, bl);
}

// round 2
// speedup vs baseline: 2.7055x; 2.7055x over previous
#include <cuda_runtime.h>
#include <math.h>

#define NN 50000
#define EE 800000
#define IND 256
#define HIDD 64
#define H0 4
#define OUT1 256
#define NCLS 64
#define NEG 0.2f
#define NEGBIG -1e30f

// ---------------- scratch (device globals; no allocation allowed) ----------
__device__ float g_ft[NN * 256];    // projected features (both layers)
__device__ float g_h1[NN * 256];    // layer0 output / layer1 residual input
__device__ float g_el[NN * H0];
__device__ float g_er[NN * H0];
__device__ int   g_cnt[NN];         // histogram, then reused as fill cursor
__device__ int   g_rowptr[NN + 1];
__device__ int   g_bsum[64];
__device__ int   g_adj[EE];         // src node per CSR slot (grouped by dst)

// =================== CSR build ==============================================
__global__ void zero_cnt_kernel(int* cnt) {
    int i = blockIdx.x * blockDim.x + threadIdx.x;
    if (i < NN) cnt[i] = 0;
}

__global__ void hist_kernel(const int* __restrict__ dst, int* __restrict__ cnt) {
    int e = blockIdx.x * blockDim.x + threadIdx.x;
    if (e < EE) atomicAdd(&cnt[dst[e]], 1);
}

// block-wise exclusive scan (1024 per block), emits block sums
__global__ void scan_block_kernel(const int* __restrict__ cnt,
                                  int* __restrict__ rowptr,
                                  int* __restrict__ bsum) {
    __shared__ int sh[1024];
    int t = threadIdx.x;
    int i = blockIdx.x * 1024 + t;
    int v = (i < NN) ? cnt[i] : 0;
    sh[t] = v;
    __syncthreads();
    for (int off = 1; off < 1024; off <<= 1) {
        int add = (t >= off) ? sh[t - off] : 0;
        __syncthreads();
        sh[t] += add;
        __syncthreads();
    }
    if (i < NN) rowptr[i] = sh[t] - v;     // exclusive
    if (t == 1023) bsum[blockIdx.x] = sh[t];
}

__global__ void scan_bsum_kernel(int* __restrict__ bsum, int nb) {
    __shared__ int sh[64];
    int t = threadIdx.x;   // 64 threads
    int v = (t < nb) ? bsum[t] : 0;
    sh[t] = v;
    __syncthreads();
    for (int off = 1; off < 64; off <<= 1) {
        int add = (t >= off) ? sh[t - off] : 0;
        __syncthreads();
        sh[t] += add;
        __syncthreads();
    }
    if (t < nb) bsum[t] = sh[t] - v;       // exclusive
}

__global__ void scan_add_kernel(int* __restrict__ rowptr,
                                const int* __restrict__ bsum,
                                int* __restrict__ cursor) {
    int i = blockIdx.x * blockDim.x + threadIdx.x;
    if (i < NN) {
        int r = rowptr[i] + bsum[i >> 10];
        rowptr[i] = r;
        cursor[i] = r;
    }
    if (i == 0) rowptr[NN] = EE;
}

__global__ void csr_fill_kernel(const int* __restrict__ src,
                                const int* __restrict__ dst,
                                int* __restrict__ cursor,
                                int* __restrict__ adj) {
    int e = blockIdx.x * blockDim.x + threadIdx.x;
    if (e >= EE) return;
    int pos = atomicAdd(&cursor[dst[e]], 1);
    adj[pos] = src[e];
}

// =================== SGEMM (float4, 8x8 micro-tile) =========================
// C[Nr,M] = A[Nr,K] @ B[K,M] (+bias). K % BK == 0, M % BN == 0.
template<int BM, int BN, int BK, int TM, int TN>
__global__ void __launch_bounds__(256)
sgemm_t(const float* __restrict__ A, const float* __restrict__ B,
        float* __restrict__ C, int Nr, int K, int M,
        const float* __restrict__ bias) {
    __shared__ float As[BK][BM];
    __shared__ float Bs[BK][BN];
    const int tid = threadIdx.x;
    const int tx = tid % (BN / TN);
    const int ty = tid / (BN / TN);
    const int rowBase = blockIdx.y * BM;
    const int colBase = blockIdx.x * BN;

    float acc[TM][TN];
#pragma unroll
    for (int i = 0; i < TM; i++)
#pragma unroll
        for (int j = 0; j < TN; j++) acc[i][j] = 0.0f;

    for (int k0 = 0; k0 < K; k0 += BK) {
        // A tile: BM x BK, float4 along K, stored transposed
#pragma unroll
        for (int i = tid; i < BM * (BK / 4); i += 256) {
            int m  = i / (BK / 4);
            int kq = (i % (BK / 4)) * 4;
            int gr = rowBase + m;
            float4 v = (gr < Nr)
                ? *(const float4*)(A + (size_t)gr * K + k0 + kq)
                : make_float4(0.f, 0.f, 0.f, 0.f);
            As[kq + 0][m] = v.x;
            As[kq + 1][m] = v.y;
            As[kq + 2][m] = v.z;
            As[kq + 3][m] = v.w;
        }
        // B tile: BK x BN, float4 along N
#pragma unroll
        for (int i = tid; i < BK * (BN / 4); i += 256) {
            int kk = i / (BN / 4);
            int nq = (i % (BN / 4)) * 4;
            *(float4*)(&Bs[kk][nq]) =
                *(const float4*)(B + (size_t)(k0 + kk) * M + colBase + nq);
        }
        __syncthreads();
#pragma unroll
        for (int kk = 0; kk < BK; kk++) {
            float a[TM], b[TN];
#pragma unroll
            for (int i = 0; i < TM; i += 4)
                *(float4*)&a[i] = *(const float4*)&As[kk][ty * TM + i];
#pragma unroll
            for (int j = 0; j < TN; j += 4)
                *(float4*)&b[j] = *(const float4*)&Bs[kk][tx * TN + j];
#pragma unroll
            for (int i = 0; i < TM; i++)
#pragma unroll
                for (int j = 0; j < TN; j++) acc[i][j] += a[i] * b[j];
        }
        __syncthreads();
    }
#pragma unroll
    for (int i = 0; i < TM; i++) {
        int gr = rowBase + ty * TM + i;
        if (gr >= Nr) continue;
#pragma unroll
        for (int j = 0; j < TN; j++) {
            int gc = colBase + tx * TN + j;
            float v = acc[i][j];
            if (bias) v += bias[gc];
            C[(size_t)gr * M + gc] = v;
        }
    }
}

// =================== attention coefficients =================================
__global__ void el_er0_kernel(const float* __restrict__ ft,
                              const float* __restrict__ al,
                              const float* __restrict__ ar,
                              float* __restrict__ el, float* __restrict__ er) {
    int i = blockIdx.x * blockDim.x + threadIdx.x;   // n*H0 + h
    if (i >= NN * H0) return;
    int h = i & (H0 - 1);
    const float* f = ft + (size_t)i * HIDD;
    const float* pal = al + h * HIDD;
    const float* par = ar + h * HIDD;
    float sl = 0.0f, sr = 0.0f;
#pragma unroll 8
    for (int d = 0; d < HIDD; d++) { float v = f[d]; sl += v * pal[d]; sr += v * par[d]; }
    el[i] = sl;
    er[i] = sr;
}

__global__ void el_er1_kernel(const float* __restrict__ ft,
                              const float* __restrict__ al,
                              const float* __restrict__ ar,
                              float* __restrict__ el, float* __restrict__ er) {
    int n = blockIdx.x * (blockDim.x >> 5) + (threadIdx.x >> 5);
    int lane = threadIdx.x & 31;
    if (n >= NN) return;
    float sl = 0.0f, sr = 0.0f;
    const float* f = ft + (size_t)n * 256;
#pragma unroll
    for (int d = lane; d < 256; d += 32) { float v = f[d]; sl += v * al[d]; sr += v * ar[d]; }
#pragma unroll
    for (int o = 16; o; o >>= 1) {
        sl += __shfl_down_sync(0xffffffffu, sl, o);
        sr += __shfl_down_sync(0xffffffffu, sr, o);
    }
    if (lane == 0) { el[n] = sl; er[n] = sr; }
}

// =================== aggregation: one block per dst node ====================
// layer 0: H=4 heads x 64 feats, fused bias + ELU
__global__ void __launch_bounds__(256)
agg0_kernel(const int* __restrict__ rowptr, const int* __restrict__ adj,
            const float* __restrict__ el, const float* __restrict__ er,
            const float* __restrict__ ft, const float* __restrict__ b0,
            float* __restrict__ h1) {
    const int d = blockIdx.x;
    const int t = threadIdx.x;
    const int h = t >> 6;
    const int start = rowptr[d], end = rowptr[d + 1];

    __shared__ int   s_src[64];
    __shared__ float s_alpha[64 * 4];
    __shared__ float s_m[4], s_sum[4];

    // ---- phase A: online softmax stats (warp 0) ----
    if (t < 32) {
        float4 erd = *(const float4*)(er + (size_t)d * 4);
        float m[4] = {NEGBIG, NEGBIG, NEGBIG, NEGBIG};
        float su[4] = {0.f, 0.f, 0.f, 0.f};
        for (int j = start + t; j < end; j += 32) {
            int s = adj[j];
            float4 e4 = *(const float4*)(el + (size_t)s * 4);
            float v[4];
            v[0] = e4.x + erd.x; v[1] = e4.y + erd.y;
            v[2] = e4.z + erd.z; v[3] = e4.w + erd.w;
#pragma unroll
            for (int k = 0; k < 4; k++) {
                float vv = (v[k] >= 0.f) ? v[k] : NEG * v[k];
                float mn = fmaxf(m[k], vv);
                su[k] = su[k] * expf(m[k] - mn) + expf(vv - mn);
                m[k] = mn;
            }
        }
#pragma unroll
        for (int off = 16; off; off >>= 1) {
#pragma unroll
            for (int k = 0; k < 4; k++) {
                float m2 = __shfl_down_sync(0xffffffffu, m[k], off);
                float s2 = __shfl_down_sync(0xffffffffu, su[k], off);
                float mn = fmaxf(m[k], m2);
                su[k] = su[k] * expf(m[k] - mn) + s2 * expf(m2 - mn);
                m[k] = mn;
            }
        }
        if (t == 0) {
#pragma unroll
            for (int k = 0; k < 4; k++) { s_m[k] = m[k]; s_sum[k] = su[k]; }
        }
    }
    __syncthreads();

    // ---- phase B: weighted gather-accumulate ----
    float acc = 0.0f;
    float4 erd = *(const float4*)(er + (size_t)d * 4);
    for (int c = start; c < end; c += 64) {
        int nchunk = min(64, end - c);
        if (t < nchunk) {
            int s = adj[c + t];
            s_src[t] = s;
            float4 e4 = *(const float4*)(el + (size_t)s * 4);
            float v[4];
            v[0] = e4.x + erd.x; v[1] = e4.y + erd.y;
            v[2] = e4.z + erd.z; v[3] = e4.w + erd.w;
#pragma unroll
            for (int k = 0; k < 4; k++) {
                float vv = (v[k] >= 0.f) ? v[k] : NEG * v[k];
                s_alpha[t * 4 + k] = expf(vv - s_m[k]) / s_sum[k];
            }
        }
        __syncthreads();
        // 2-way unrolled to expose memory-level parallelism
        int j = 0;
        for (; j + 2 <= nchunk; j += 2) {
            int s0 = s_src[j], s1 = s_src[j + 1];
            float a0 = s_alpha[j * 4 + h], a1 = s_alpha[(j + 1) * 4 + h];
            float f0 = ft[(size_t)s0 * 256 + t];
            float f1 = ft[(size_t)s1 * 256 + t];
            acc += a0 * f0 + a1 * f1;
        }
        if (j < nchunk) {
            int s0 = s_src[j];
            acc += s_alpha[j * 4 + h] * ft[(size_t)s0 * 256 + t];
        }
        __syncthreads();
    }
    float v = acc + b0[t];
    h1[(size_t)d * 256 + t] = (v > 0.f) ? v : expm1f(v);
}

// layer 1: H=1, D=256, fused residual + bias, writes final h
__global__ void __launch_bounds__(256)
agg1_kernel(const int* __restrict__ rowptr, const int* __restrict__ adj,
            const float* __restrict__ el, const float* __restrict__ er,
            const float* __restrict__ ft, const float* __restrict__ h1,
            const float* __restrict__ b1, float* __restrict__ hout) {
    const int d = blockIdx.x;
    const int t = threadIdx.x;
    const int start = rowptr[d], end = rowptr[d + 1];

    __shared__ int   s_src[128];
    __shared__ float s_alpha[128];
    __shared__ float s_m, s_sum;

    if (t < 32) {
        float erd = er[d];
        float m = NEGBIG, su = 0.f;
        for (int j = start + t; j < end; j += 32) {
            int s = adj[j];
            float v = el[s] + erd;
            v = (v >= 0.f) ? v : NEG * v;
            float mn = fmaxf(m, v);
            su = su * expf(m - mn) + expf(v - mn);
            m = mn;
        }
#pragma unroll
        for (int off = 16; off; off >>= 1) {
            float m2 = __shfl_down_sync(0xffffffffu, m, off);
            float s2 = __shfl_down_sync(0xffffffffu, su, off);
            float mn = fmaxf(m, m2);
            su = su * expf(m - mn) + s2 * expf(m2 - mn);
            m = mn;
        }
        if (t == 0) { s_m = m; s_sum = su; }
    }
    __syncthreads();

    float acc = 0.0f;
    float erd = er[d];
    for (int c = start; c < end; c += 128) {
        int nchunk = min(128, end - c);
        if (t < nchunk) {
            int s = adj[c + t];
            s_src[t] = s;
            float v = el[s] + erd;
            v = (v >= 0.f) ? v : NEG * v;
            s_alpha[t] = expf(v - s_m) / s_sum;
        }
        __syncthreads();
        int j = 0;
        for (; j + 2 <= nchunk; j += 2) {
            int s0 = s_src[j], s1 = s_src[j + 1];
            float a0 = s_alpha[j], a1 = s_alpha[j + 1];
            float f0 = ft[(size_t)s0 * 256 + t];
            float f1 = ft[(size_t)s1 * 256 + t];
            acc += a0 * f0 + a1 * f1;
        }
        if (j < nchunk) acc += s_alpha[j] * ft[(size_t)s_src[j] * 256 + t];
        __syncthreads();
    }
    hout[(size_t)d * 256 + t] = acc + h1[(size_t)d * 256 + t] + b1[t];
}

// =================== launch ==================================================
extern "C" void kernel_launch(void* const* d_in, const int* in_sizes, int n_in,
                              void* d_out, int out_size) {
    const float* x   = (const float*)d_in[0];
    const int*   src = (const int*)  d_in[1];
    const int*   dst = (const int*)  d_in[2];
    const float* W0  = (const float*)d_in[3];
    const float* al0 = (const float*)d_in[4];
    const float* ar0 = (const float*)d_in[5];
    const float* b0  = (const float*)d_in[6];
    const float* W1  = (const float*)d_in[7];
    const float* al1 = (const float*)d_in[8];
    const float* ar1 = (const float*)d_in[9];
    const float* b1  = (const float*)d_in[10];
    const float* Wl  = (const float*)d_in[11];
    const float* bl  = (const float*)d_in[12];

    float* out    = (float*)d_out;
    float* logits = out;                      // [NN, NCLS]
    float* hout   = out + (size_t)NN * NCLS;  // [NN, OUT1]

    float *ft, *h1v, *el, *er;
    int *cnt, *rowptr, *bsum, *adj;
    cudaGetSymbolAddress((void**)&ft,     g_ft);
    cudaGetSymbolAddress((void**)&h1v,    g_h1);
    cudaGetSymbolAddress((void**)&el,     g_el);
    cudaGetSymbolAddress((void**)&er,     g_er);
    cudaGetSymbolAddress((void**)&cnt,    g_cnt);
    cudaGetSymbolAddress((void**)&rowptr, g_rowptr);
    cudaGetSymbolAddress((void**)&bsum,   g_bsum);
    cudaGetSymbolAddress((void**)&adj,    g_adj);

    const int T = 256;
    const int NB_SCAN = (NN + 1023) / 1024;   // 49

    // ---- CSR build (graph shared by both layers) ----
    zero_cnt_kernel<<<(NN + T - 1) / T, T>>>(cnt);
    hist_kernel<<<(EE + T - 1) / T, T>>>(dst, cnt);
    scan_block_kernel<<<NB_SCAN, 1024>>>(cnt, rowptr, bsum);
    scan_bsum_kernel<<<1, 64>>>(bsum, NB_SCAN);
    scan_add_kernel<<<(NN + T - 1) / T, T>>>(rowptr, bsum, cnt);
    csr_fill_kernel<<<(EE + T - 1) / T, T>>>(src, dst, cnt, adj);

    // ---- layer 0 ----
    {
        dim3 grid(256 / 128, (NN + 127) / 128);
        sgemm_t<128, 128, 8, 8, 8><<<grid, 256>>>(x, W0, ft, NN, IND, 256, nullptr);
    }
    el_er0_kernel<<<(NN * H0 + T - 1) / T, T>>>(ft, al0, ar0, el, er);
    agg0_kernel<<<NN, 256>>>(rowptr, adj, el, er, ft, b0, h1v);

    // ---- layer 1 ----
    {
        dim3 grid(256 / 128, (NN + 127) / 128);
        sgemm_t<128, 128, 8, 8, 8><<<grid, 256>>>(h1v, W1, ft, NN, 256, 256, nullptr);
    }
    el_er1_kernel<<<(NN + 7) / 8, T>>>(ft, al1, ar1, el, er);
    agg1_kernel<<<NN, 256>>>(rowptr, adj, el, er, ft, h1v, b1, hout);

    // ---- classifier ----
    {
        dim3 grid(1, (NN + 127) / 128);
        sgemm_t<128, 64, 8, 8, 4><<<grid, 256>>>(hout, Wl, logits, NN, OUT1, NCLS, bl);
    }
}

// round 3
// speedup vs baseline: 3.1615x; 1.1685x over previous
#include <cuda_runtime.h>
#include <math.h>
#include <stdint.h>

#define NN 50000
#define EE 800000
#define IND 256
#define HIDD 64
#define H0 4
#define OUT1 256
#define NCLS 64
#define NEG 0.2f
#define NEGBIG -1e30f

// ---------------- scratch (device globals; no allocation allowed) ----------
__device__ float g_ft[NN * 256];    // projected features (both layers)
__device__ float g_h1[NN * 256];    // layer0 output / layer1 residual input
__device__ float g_el[NN * H0];
__device__ float g_er[NN * H0];
__device__ int   g_cnt[NN];         // histogram, then reused as fill cursor
__device__ int   g_rowptr[NN + 1];
__device__ int   g_bsum[64];
__device__ int   g_adj[EE];         // src node per CSR slot (grouped by dst)

// =================== CSR build ==============================================
__global__ void zero_cnt_kernel(int* cnt) {
    int i = blockIdx.x * blockDim.x + threadIdx.x;
    if (i < NN) cnt[i] = 0;
}

__global__ void hist_kernel(const int* __restrict__ dst, int* __restrict__ cnt) {
    int e = blockIdx.x * blockDim.x + threadIdx.x;
    if (e < EE) atomicAdd(&cnt[dst[e]], 1);
}

__global__ void scan_block_kernel(const int* __restrict__ cnt,
                                  int* __restrict__ rowptr,
                                  int* __restrict__ bsum) {
    __shared__ int sh[1024];
    int t = threadIdx.x;
    int i = blockIdx.x * 1024 + t;
    int v = (i < NN) ? cnt[i] : 0;
    sh[t] = v;
    __syncthreads();
    for (int off = 1; off < 1024; off <<= 1) {
        int add = (t >= off) ? sh[t - off] : 0;
        __syncthreads();
        sh[t] += add;
        __syncthreads();
    }
    if (i < NN) rowptr[i] = sh[t] - v;
    if (t == 1023) bsum[blockIdx.x] = sh[t];
}

__global__ void scan_bsum_kernel(int* __restrict__ bsum, int nb) {
    __shared__ int sh[64];
    int t = threadIdx.x;
    int v = (t < nb) ? bsum[t] : 0;
    sh[t] = v;
    __syncthreads();
    for (int off = 1; off < 64; off <<= 1) {
        int add = (t >= off) ? sh[t - off] : 0;
        __syncthreads();
        sh[t] += add;
        __syncthreads();
    }
    if (t < nb) bsum[t] = sh[t] - v;
}

__global__ void scan_add_kernel(int* __restrict__ rowptr,
                                const int* __restrict__ bsum,
                                int* __restrict__ cursor) {
    int i = blockIdx.x * blockDim.x + threadIdx.x;
    if (i < NN) {
        int r = rowptr[i] + bsum[i >> 10];
        rowptr[i] = r;
        cursor[i] = r;
    }
    if (i == 0) rowptr[NN] = EE;
}

__global__ void csr_fill_kernel(const int* __restrict__ src,
                                const int* __restrict__ dst,
                                int* __restrict__ cursor,
                                int* __restrict__ adj) {
    int e = blockIdx.x * blockDim.x + threadIdx.x;
    if (e >= EE) return;
    int pos = atomicAdd(&cursor[dst[e]], 1);
    adj[pos] = src[e];
}

// =================== TF32 tensor-core GEMM (3xTF32 split) ===================
__device__ __forceinline__ uint32_t f2tf32(float v) {
    uint32_t r;
    asm("cvt.rna.tf32.f32 %0, %1;" : "=r"(r) : "f"(v));
    return r;
}
__device__ __forceinline__ void tf32split(float v, uint32_t& hi, uint32_t& lo) {
    hi = f2tf32(v);
    lo = f2tf32(v - __uint_as_float(hi));
}

#define MMA_TF32(d, a, b) \
    asm volatile("mma.sync.aligned.m16n8k8.row.col.f32.tf32.tf32.f32 " \
                 "{%0,%1,%2,%3}, {%4,%5,%6,%7}, {%8,%9}, {%0,%1,%2,%3};" \
                 : "+f"(d[0]), "+f"(d[1]), "+f"(d[2]), "+f"(d[3]) \
                 : "r"(a[0]), "r"(a[1]), "r"(a[2]), "r"(a[3]), \
                   "r"(b[0]), "r"(b[1]))

// C[Nr,M] = A[Nr,K] @ B[K,M] (+bias). K%16==0, M%BN==0. 256 threads.
template<int BM, int BN, int WARPS_M, int WARPS_N>
__global__ void __launch_bounds__(256)
gemm_tf32_kernel(const float* __restrict__ A, const float* __restrict__ B,
                 float* __restrict__ C, int Nr, int K, int M,
                 const float* __restrict__ bias) {
    constexpr int WM = BM / WARPS_M;
    constexpr int WN = BN / WARPS_N;
    constexpr int MF = WM / 16;
    constexpr int NF = WN / 8;
    constexpr int BK = 16;
    constexpr int LDA = BM + 8;
    constexpr int LDB = BN + 8;

    __shared__ uint32_t Ah[BK][LDA];
    __shared__ uint32_t Al[BK][LDA];
    __shared__ uint32_t Bhs[BK][LDB];
    __shared__ uint32_t Bls[BK][LDB];

    const int tid = threadIdx.x;
    const int lane = tid & 31;
    const int warp = tid >> 5;
    const int wm = warp / WARPS_N;
    const int wn = warp % WARPS_N;
    const int rowBase = blockIdx.y * BM;
    const int colBase = blockIdx.x * BN;
    const int g  = lane >> 2;   // group 0..7
    const int tg = lane & 3;    // thread-in-group 0..3

    float acc[MF][NF][4];
#pragma unroll
    for (int i = 0; i < MF; i++)
#pragma unroll
        for (int j = 0; j < NF; j++)
#pragma unroll
            for (int k = 0; k < 4; k++) acc[i][j][k] = 0.0f;

    for (int k0 = 0; k0 < K; k0 += BK) {
        // A tile: BM x 16, float4 along K
#pragma unroll
        for (int idx = tid; idx < BM * 4; idx += 256) {
            int m  = idx >> 2;
            int kq = (idx & 3) << 2;
            int gr = rowBase + m;
            float4 v = (gr < Nr)
                ? *(const float4*)(A + (size_t)gr * K + k0 + kq)
                : make_float4(0.f, 0.f, 0.f, 0.f);
            uint32_t h, l;
            tf32split(v.x, h, l); Ah[kq + 0][m] = h; Al[kq + 0][m] = l;
            tf32split(v.y, h, l); Ah[kq + 1][m] = h; Al[kq + 1][m] = l;
            tf32split(v.z, h, l); Ah[kq + 2][m] = h; Al[kq + 2][m] = l;
            tf32split(v.w, h, l); Ah[kq + 3][m] = h; Al[kq + 3][m] = l;
        }
        // B tile: 16 x BN, float4 along N
#pragma unroll
        for (int idx = tid; idx < 4 * BN; idx += 256) {
            int kk = idx / (BN / 4);
            int nq = (idx % (BN / 4)) * 4;
            float4 v = *(const float4*)(B + (size_t)(k0 + kk) * M + colBase + nq);
            uint32_t h, l;
            tf32split(v.x, h, l); Bhs[kk][nq + 0] = h; Bls[kk][nq + 0] = l;
            tf32split(v.y, h, l); Bhs[kk][nq + 1] = h; Bls[kk][nq + 1] = l;
            tf32split(v.z, h, l); Bhs[kk][nq + 2] = h; Bls[kk][nq + 2] = l;
            tf32split(v.w, h, l); Bhs[kk][nq + 3] = h; Bls[kk][nq + 3] = l;
        }
        __syncthreads();

#pragma unroll
        for (int ks = 0; ks < 2; ks++) {
            const int kk = ks * 8;
            uint32_t ah[MF][4], al[MF][4], bh[NF][2], bl[NF][2];
#pragma unroll
            for (int mf = 0; mf < MF; mf++) {
                int r0 = wm * WM + mf * 16 + g;
                ah[mf][0] = Ah[kk + tg][r0];
                ah[mf][1] = Ah[kk + tg][r0 + 8];
                ah[mf][2] = Ah[kk + tg + 4][r0];
                ah[mf][3] = Ah[kk + tg + 4][r0 + 8];
                al[mf][0] = Al[kk + tg][r0];
                al[mf][1] = Al[kk + tg][r0 + 8];
                al[mf][2] = Al[kk + tg + 4][r0];
                al[mf][3] = Al[kk + tg + 4][r0 + 8];
            }
#pragma unroll
            for (int nf = 0; nf < NF; nf++) {
                int c0 = wn * WN + nf * 8 + g;
                bh[nf][0] = Bhs[kk + tg][c0];
                bh[nf][1] = Bhs[kk + tg + 4][c0];
                bl[nf][0] = Bls[kk + tg][c0];
                bl[nf][1] = Bls[kk + tg + 4][c0];
            }
#pragma unroll
            for (int mf = 0; mf < MF; mf++)
#pragma unroll
                for (int nf = 0; nf < NF; nf++) {
                    MMA_TF32(acc[mf][nf], al[mf], bh[nf]);
                    MMA_TF32(acc[mf][nf], ah[mf], bl[nf]);
                    MMA_TF32(acc[mf][nf], ah[mf], bh[nf]);
                }
        }
        __syncthreads();
    }

    // epilogue
#pragma unroll
    for (int mf = 0; mf < MF; mf++) {
#pragma unroll
        for (int nf = 0; nf < NF; nf++) {
            int row = rowBase + wm * WM + mf * 16 + g;
            int col = colBase + wn * WN + nf * 8 + tg * 2;
            float b0v = bias ? bias[col]     : 0.0f;
            float b1v = bias ? bias[col + 1] : 0.0f;
            if (row < Nr) {
                float2 o = make_float2(acc[mf][nf][0] + b0v, acc[mf][nf][1] + b1v);
                *(float2*)(C + (size_t)row * M + col) = o;
            }
            if (row + 8 < Nr) {
                float2 o = make_float2(acc[mf][nf][2] + b0v, acc[mf][nf][3] + b1v);
                *(float2*)(C + (size_t)(row + 8) * M + col) = o;
            }
        }
    }
}

// =================== attention coefficients =================================
__global__ void el_er0_kernel(const float* __restrict__ ft,
                              const float* __restrict__ al,
                              const float* __restrict__ ar,
                              float* __restrict__ el, float* __restrict__ er) {
    int i = blockIdx.x * blockDim.x + threadIdx.x;   // n*H0 + h
    if (i >= NN * H0) return;
    int h = i & (H0 - 1);
    const float* f = ft + (size_t)i * HIDD;
    const float* pal = al + h * HIDD;
    const float* par = ar + h * HIDD;
    float sl = 0.0f, sr = 0.0f;
#pragma unroll 8
    for (int d = 0; d < HIDD; d++) { float v = f[d]; sl += v * pal[d]; sr += v * par[d]; }
    el[i] = sl;
    er[i] = sr;
}

__global__ void el_er1_kernel(const float* __restrict__ ft,
                              const float* __restrict__ al,
                              const float* __restrict__ ar,
                              float* __restrict__ el, float* __restrict__ er) {
    int n = blockIdx.x * (blockDim.x >> 5) + (threadIdx.x >> 5);
    int lane = threadIdx.x & 31;
    if (n >= NN) return;
    float sl = 0.0f, sr = 0.0f;
    const float* f = ft + (size_t)n * 256;
#pragma unroll
    for (int d = lane; d < 256; d += 32) { float v = f[d]; sl += v * al[d]; sr += v * ar[d]; }
#pragma unroll
    for (int o = 16; o; o >>= 1) {
        sl += __shfl_down_sync(0xffffffffu, sl, o);
        sr += __shfl_down_sync(0xffffffffu, sr, o);
    }
    if (lane == 0) { el[n] = sl; er[n] = sr; }
}

// =================== aggregation: one block per dst node ====================
__global__ void __launch_bounds__(256)
agg0_kernel(const int* __restrict__ rowptr, const int* __restrict__ adj,
            const float* __restrict__ el, const float* __restrict__ er,
            const float* __restrict__ ft, const float* __restrict__ b0,
            float* __restrict__ h1) {
    const int d = blockIdx.x;
    const int t = threadIdx.x;
    const int h = t >> 6;
    const int start = rowptr[d], end = rowptr[d + 1];

    __shared__ int   s_src[64];
    __shared__ float s_alpha[64 * 4];
    __shared__ float s_m[4], s_sum[4];

    if (t < 32) {
        float4 erd = *(const float4*)(er + (size_t)d * 4);
        float m[4] = {NEGBIG, NEGBIG, NEGBIG, NEGBIG};
        float su[4] = {0.f, 0.f, 0.f, 0.f};
        for (int j = start + t; j < end; j += 32) {
            int s = adj[j];
            float4 e4 = *(const float4*)(el + (size_t)s * 4);
            float v[4];
            v[0] = e4.x + erd.x; v[1] = e4.y + erd.y;
            v[2] = e4.z + erd.z; v[3] = e4.w + erd.w;
#pragma unroll
            for (int k = 0; k < 4; k++) {
                float vv = (v[k] >= 0.f) ? v[k] : NEG * v[k];
                float mn = fmaxf(m[k], vv);
                su[k] = su[k] * expf(m[k] - mn) + expf(vv - mn);
                m[k] = mn;
            }
        }
#pragma unroll
        for (int off = 16; off; off >>= 1) {
#pragma unroll
            for (int k = 0; k < 4; k++) {
                float m2 = __shfl_down_sync(0xffffffffu, m[k], off);
                float s2 = __shfl_down_sync(0xffffffffu, su[k], off);
                float mn = fmaxf(m[k], m2);
                su[k] = su[k] * expf(m[k] - mn) + s2 * expf(m2 - mn);
                m[k] = mn;
            }
        }
        if (t == 0) {
#pragma unroll
            for (int k = 0; k < 4; k++) { s_m[k] = m[k]; s_sum[k] = su[k]; }
        }
    }
    __syncthreads();

    float acc = 0.0f;
    float4 erd = *(const float4*)(er + (size_t)d * 4);
    for (int c = start; c < end; c += 64) {
        int nchunk = min(64, end - c);
        if (t < nchunk) {
            int s = adj[c + t];
            s_src[t] = s;
            float4 e4 = *(const float4*)(el + (size_t)s * 4);
            float v[4];
            v[0] = e4.x + erd.x; v[1] = e4.y + erd.y;
            v[2] = e4.z + erd.z; v[3] = e4.w + erd.w;
#pragma unroll
            for (int k = 0; k < 4; k++) {
                float vv = (v[k] >= 0.f) ? v[k] : NEG * v[k];
                s_alpha[t * 4 + k] = expf(vv - s_m[k]) / s_sum[k];
            }
        }
        __syncthreads();
        int j = 0;
        for (; j + 2 <= nchunk; j += 2) {
            int s0 = s_src[j], s1 = s_src[j + 1];
            float a0 = s_alpha[j * 4 + h], a1 = s_alpha[(j + 1) * 4 + h];
            float f0 = ft[(size_t)s0 * 256 + t];
            float f1 = ft[(size_t)s1 * 256 + t];
            acc += a0 * f0 + a1 * f1;
        }
        if (j < nchunk) {
            acc += s_alpha[j * 4 + h] * ft[(size_t)s_src[j] * 256 + t];
        }
        __syncthreads();
    }
    float v = acc + b0[t];
    h1[(size_t)d * 256 + t] = (v > 0.f) ? v : expm1f(v);
}

__global__ void __launch_bounds__(256)
agg1_kernel(const int* __restrict__ rowptr, const int* __restrict__ adj,
            const float* __restrict__ el, const float* __restrict__ er,
            const float* __restrict__ ft, const float* __restrict__ h1,
            const float* __restrict__ b1, float* __restrict__ hout) {
    const int d = blockIdx.x;
    const int t = threadIdx.x;
    const int start = rowptr[d], end = rowptr[d + 1];

    __shared__ int   s_src[128];
    __shared__ float s_alpha[128];
    __shared__ float s_m, s_sum;

    if (t < 32) {
        float erd = er[d];
        float m = NEGBIG, su = 0.f;
        for (int j = start + t; j < end; j += 32) {
            int s = adj[j];
            float v = el[s] + erd;
            v = (v >= 0.f) ? v : NEG * v;
            float mn = fmaxf(m, v);
            su = su * expf(m - mn) + expf(v - mn);
            m = mn;
        }
#pragma unroll
        for (int off = 16; off; off >>= 1) {
            float m2 = __shfl_down_sync(0xffffffffu, m, off);
            float s2 = __shfl_down_sync(0xffffffffu, su, off);
            float mn = fmaxf(m, m2);
            su = su * expf(m - mn) + s2 * expf(m2 - mn);
            m = mn;
        }
        if (t == 0) { s_m = m; s_sum = su; }
    }
    __syncthreads();

    float acc = 0.0f;
    float erd = er[d];
    for (int c = start; c < end; c += 128) {
        int nchunk = min(128, end - c);
        if (t < nchunk) {
            int s = adj[c + t];
            s_src[t] = s;
            float v = el[s] + erd;
            v = (v >= 0.f) ? v : NEG * v;
            s_alpha[t] = expf(v - s_m) / s_sum;
        }
        __syncthreads();
        int j = 0;
        for (; j + 2 <= nchunk; j += 2) {
            int s0 = s_src[j], s1 = s_src[j + 1];
            float a0 = s_alpha[j], a1 = s_alpha[j + 1];
            float f0 = ft[(size_t)s0 * 256 + t];
            float f1 = ft[(size_t)s1 * 256 + t];
            acc += a0 * f0 + a1 * f1;
        }
        if (j < nchunk) acc += s_alpha[j] * ft[(size_t)s_src[j] * 256 + t];
        __syncthreads();
    }
    hout[(size_t)d * 256 + t] = acc + h1[(size_t)d * 256 + t] + b1[t];
}

// =================== launch ==================================================
extern "C" void kernel_launch(void* const* d_in, const int* in_sizes, int n_in,
                              void* d_out, int out_size) {
    const float* x   = (const float*)d_in[0];
    const int*   src = (const int*)  d_in[1];
    const int*   dst = (const int*)  d_in[2];
    const float* W0  = (const float*)d_in[3];
    const float* al0 = (const float*)d_in[4];
    const float* ar0 = (const float*)d_in[5];
    const float* b0  = (const float*)d_in[6];
    const float* W1  = (const float*)d_in[7];
    const float* al1 = (const float*)d_in[8];
    const float* ar1 = (const float*)d_in[9];
    const float* b1  = (const float*)d_in[10];
    const float* Wl  = (const float*)d_in[11];
    const float* bl  = (const float*)d_in[12];

    float* out    = (float*)d_out;
    float* logits = out;                      // [NN, NCLS]
    float* hout   = out + (size_t)NN * NCLS;  // [NN, OUT1]

    float *ft, *h1v, *el, *er;
    int *cnt, *rowptr, *bsum, *adj;
    cudaGetSymbolAddress((void**)&ft,     g_ft);
    cudaGetSymbolAddress((void**)&h1v,    g_h1);
    cudaGetSymbolAddress((void**)&el,     g_el);
    cudaGetSymbolAddress((void**)&er,     g_er);
    cudaGetSymbolAddress((void**)&cnt,    g_cnt);
    cudaGetSymbolAddress((void**)&rowptr, g_rowptr);
    cudaGetSymbolAddress((void**)&bsum,   g_bsum);
    cudaGetSymbolAddress((void**)&adj,    g_adj);

    const int T = 256;
    const int NB_SCAN = (NN + 1023) / 1024;   // 49

    // ---- CSR build ----
    zero_cnt_kernel<<<(NN + T - 1) / T, T>>>(cnt);
    hist_kernel<<<(EE + T - 1) / T, T>>>(dst, cnt);
    scan_block_kernel<<<NB_SCAN, 1024>>>(cnt, rowptr, bsum);
    scan_bsum_kernel<<<1, 64>>>(bsum, NB_SCAN);
    scan_add_kernel<<<(NN + T - 1) / T, T>>>(rowptr, bsum, cnt);
    csr_fill_kernel<<<(EE + T - 1) / T, T>>>(src, dst, cnt, adj);

    // ---- layer 0 ----
    {
        dim3 grid(256 / 128, (NN + 127) / 128);
        gemm_tf32_kernel<128, 128, 2, 4><<<grid, 256>>>(x, W0, ft, NN, IND, 256, nullptr);
    }
    el_er0_kernel<<<(NN * H0 + T - 1) / T, T>>>(ft, al0, ar0, el, er);
    agg0_kernel<<<NN, 256>>>(rowptr, adj, el, er, ft, b0, h1v);

    // ---- layer 1 ----
    {
        dim3 grid(256 / 128, (NN + 127) / 128);
        gemm_tf32_kernel<128, 128, 2, 4><<<grid, 256>>>(h1v, W1, ft, NN, 256, 256, nullptr);
    }
    el_er1_kernel<<<(NN + 7) / 8, T>>>(ft, al1, ar1, el, er);
    agg1_kernel<<<NN, 256>>>(rowptr, adj, el, er, ft, h1v, b1, hout);

    // ---- classifier ----
    {
        dim3 grid(64 / 64, (NN + 127) / 128);
        gemm_tf32_kernel<128, 64, 4, 2><<<grid, 256>>>(hout, Wl, logits, NN, OUT1, NCLS, bl);
    }
}

// round 4
// speedup vs baseline: 3.6254x; 1.1467x over previous
#include <cuda_runtime.h>
#include <math.h>
#include <stdint.h>

#define NN 50000
#define EE 800000
#define IND 256
#define HIDD 64
#define H0 4
#define OUT1 256
#define NCLS 64
#define NEG 0.2f
#define NEGBIG -1e30f

// ---------------- scratch (device globals; no allocation allowed) ----------
__device__ float g_ft[NN * 256];
__device__ float g_h1[NN * 256];
__device__ float g_el[NN * H0];
__device__ float g_er[NN * H0];
__device__ int   g_cnt[NN];
__device__ int   g_rowptr[NN + 1];
__device__ int   g_bsum[64];
__device__ int   g_adj[EE];

// =================== CSR build ==============================================
__global__ void hist_kernel(const int* __restrict__ dst, int* __restrict__ cnt) {
    int e = blockIdx.x * blockDim.x + threadIdx.x;
    if (e < EE) atomicAdd(&cnt[dst[e]], 1);
}

__global__ void scan_block_kernel(const int* __restrict__ cnt,
                                  int* __restrict__ rowptr,
                                  int* __restrict__ bsum) {
    __shared__ int sh[1024];
    int t = threadIdx.x;
    int i = blockIdx.x * 1024 + t;
    int v = (i < NN) ? cnt[i] : 0;
    sh[t] = v;
    __syncthreads();
    for (int off = 1; off < 1024; off <<= 1) {
        int add = (t >= off) ? sh[t - off] : 0;
        __syncthreads();
        sh[t] += add;
        __syncthreads();
    }
    if (i < NN) rowptr[i] = sh[t] - v;
    if (t == 1023) bsum[blockIdx.x] = sh[t];
}

__global__ void scan_bsum_kernel(int* __restrict__ bsum, int nb) {
    __shared__ int sh[64];
    int t = threadIdx.x;
    int v = (t < nb) ? bsum[t] : 0;
    sh[t] = v;
    __syncthreads();
    for (int off = 1; off < 64; off <<= 1) {
        int add = (t >= off) ? sh[t - off] : 0;
        __syncthreads();
        sh[t] += add;
        __syncthreads();
    }
    if (t < nb) bsum[t] = sh[t] - v;
}

__global__ void scan_add_kernel(int* __restrict__ rowptr,
                                const int* __restrict__ bsum,
                                int* __restrict__ cursor) {
    int i = blockIdx.x * blockDim.x + threadIdx.x;
    if (i < NN) {
        int r = rowptr[i] + bsum[i >> 10];
        rowptr[i] = r;
        cursor[i] = r;
    }
    if (i == 0) rowptr[NN] = EE;
}

__global__ void csr_fill_kernel(const int* __restrict__ src,
                                const int* __restrict__ dst,
                                int* __restrict__ cursor,
                                int* __restrict__ adj) {
    int e = blockIdx.x * blockDim.x + threadIdx.x;
    if (e >= EE) return;
    int pos = atomicAdd(&cursor[dst[e]], 1);
    adj[pos] = src[e];
}

// =================== TF32 tensor-core GEMM (cp.async, 2-stage) ==============
__device__ __forceinline__ uint32_t f2tf32(float v) {
    uint32_t r;
    asm("cvt.rna.tf32.f32 %0, %1;" : "=r"(r) : "f"(v));
    return r;
}
__device__ __forceinline__ void tf32split(float v, uint32_t& hi, uint32_t& lo) {
    hi = f2tf32(v);
    lo = f2tf32(v - __uint_as_float(hi));
}
__device__ __forceinline__ void cp16(float* s, const float* g, int src_sz) {
    uint32_t sa = (uint32_t)__cvta_generic_to_shared(s);
    asm volatile("cp.async.cg.shared.global [%0], [%1], 16, %2;"
                 :: "r"(sa), "l"(g), "r"(src_sz));
}

#define MMA_TF32(d, a, b) \
    asm volatile("mma.sync.aligned.m16n8k8.row.col.f32.tf32.tf32.f32 " \
                 "{%0,%1,%2,%3}, {%4,%5,%6,%7}, {%8,%9}, {%0,%1,%2,%3};" \
                 : "+f"(d[0]), "+f"(d[1]), "+f"(d[2]), "+f"(d[3]) \
                 : "r"(a[0]), "r"(a[1]), "r"(a[2]), "r"(a[3]), \
                   "r"(b[0]), "r"(b[1]))

// C[Nr,M] = A[Nr,K] @ B[K,M] (+bias). K%16==0, cols in-bounds. 256 threads.
template<int BM, int BN, int WARPS_M, int WARPS_N>
__global__ void __launch_bounds__(256, 2)
gemm_tf32_async(const float* __restrict__ A, const float* __restrict__ B,
                float* __restrict__ C, int Nr, int K, int M,
                const float* __restrict__ bias) {
    constexpr int WM = BM / WARPS_M;
    constexpr int WN = BN / WARPS_N;
    constexpr int MF = WM / 16;
    constexpr int NF = WN / 8;
    constexpr int LDA = 20;            // 16 data + 4 pad (80B, 16B-aligned rows)
    constexpr int LDB = BN + 8;        // 16B-aligned rows, conflict-free frags
    constexpr int ASTG = BM * LDA;
    constexpr int BSTG = 16 * LDB;

    __shared__ float Asm[2 * ASTG];
    __shared__ float Bsm[2 * BSTG];

    const int tid  = threadIdx.x;
    const int lane = tid & 31;
    const int warp = tid >> 5;
    const int wm = warp / WARPS_N;
    const int wn = warp % WARPS_N;
    const int rowBase = blockIdx.y * BM;
    const int colBase = blockIdx.x * BN;
    const int g  = lane >> 2;
    const int tg = lane & 3;

    float acc[MF][NF][4];
#pragma unroll
    for (int i = 0; i < MF; i++)
#pragma unroll
        for (int j = 0; j < NF; j++)
#pragma unroll
            for (int k = 0; k < 4; k++) acc[i][j][k] = 0.0f;

    auto load_tile = [&](int stage, int k0) {
#pragma unroll
        for (int c = tid; c < BM * 4; c += 256) {
            int m = c >> 2, kq = (c & 3) << 2;
            int gr = rowBase + m;
            int grc = (gr < Nr) ? gr : (Nr - 1);
            cp16(Asm + stage * ASTG + m * LDA + kq,
                 A + (size_t)grc * K + k0 + kq, (gr < Nr) ? 16 : 0);
        }
#pragma unroll
        for (int c = tid; c < 4 * BN; c += 256) {
            int kk = c / (BN / 4), nq = (c % (BN / 4)) << 2;
            cp16(Bsm + stage * BSTG + kk * LDB + nq,
                 B + (size_t)(k0 + kk) * M + colBase + nq, 16);
        }
        asm volatile("cp.async.commit_group;" ::: "memory");
    };

    const int NIT = K / 16;
    load_tile(0, 0);

    for (int it = 0; it < NIT; it++) {
        const int s = it & 1;
        if (it + 1 < NIT) {
            load_tile(s ^ 1, (it + 1) * 16);
            asm volatile("cp.async.wait_group 1;" ::: "memory");
        } else {
            asm volatile("cp.async.wait_group 0;" ::: "memory");
        }
        __syncthreads();

        const float* As_ = Asm + s * ASTG;
        const float* Bs_ = Bsm + s * BSTG;
#pragma unroll
        for (int ks = 0; ks < 2; ks++) {
            const int kk = ks * 8;
            uint32_t bh[NF][2], bl[NF][2];
#pragma unroll
            for (int nf = 0; nf < NF; nf++) {
                int c0 = wn * WN + nf * 8 + g;
                float f0 = Bs_[(kk + tg) * LDB + c0];
                float f1 = Bs_[(kk + tg + 4) * LDB + c0];
                tf32split(f0, bh[nf][0], bl[nf][0]);
                tf32split(f1, bh[nf][1], bl[nf][1]);
            }
#pragma unroll
            for (int mf = 0; mf < MF; mf++) {
                int r0 = wm * WM + mf * 16 + g;
                float f0 = As_[r0 * LDA + kk + tg];
                float f1 = As_[(r0 + 8) * LDA + kk + tg];
                float f2 = As_[r0 * LDA + kk + tg + 4];
                float f3 = As_[(r0 + 8) * LDA + kk + tg + 4];
                uint32_t ah[4], al[4];
                tf32split(f0, ah[0], al[0]);
                tf32split(f1, ah[1], al[1]);
                tf32split(f2, ah[2], al[2]);
                tf32split(f3, ah[3], al[3]);
#pragma unroll
                for (int nf = 0; nf < NF; nf++) {
                    MMA_TF32(acc[mf][nf], al, bh[nf]);
                    MMA_TF32(acc[mf][nf], ah, bl[nf]);
                    MMA_TF32(acc[mf][nf], ah, bh[nf]);
                }
            }
        }
        __syncthreads();
    }

    // epilogue
#pragma unroll
    for (int mf = 0; mf < MF; mf++) {
#pragma unroll
        for (int nf = 0; nf < NF; nf++) {
            int row = rowBase + wm * WM + mf * 16 + g;
            int col = colBase + wn * WN + nf * 8 + tg * 2;
            float b0v = bias ? bias[col]     : 0.0f;
            float b1v = bias ? bias[col + 1] : 0.0f;
            if (row < Nr) {
                float2 o = make_float2(acc[mf][nf][0] + b0v, acc[mf][nf][1] + b1v);
                *(float2*)(C + (size_t)row * M + col) = o;
            }
            if (row + 8 < Nr) {
                float2 o = make_float2(acc[mf][nf][2] + b0v, acc[mf][nf][3] + b1v);
                *(float2*)(C + (size_t)(row + 8) * M + col) = o;
            }
        }
    }
}

// =================== attention coefficients =================================
__global__ void el_er0_kernel(const float* __restrict__ ft,
                              const float* __restrict__ al,
                              const float* __restrict__ ar,
                              float* __restrict__ el, float* __restrict__ er) {
    int i = blockIdx.x * blockDim.x + threadIdx.x;
    if (i >= NN * H0) return;
    int h = i & (H0 - 1);
    const float* f = ft + (size_t)i * HIDD;
    const float* pal = al + h * HIDD;
    const float* par = ar + h * HIDD;
    float sl = 0.0f, sr = 0.0f;
#pragma unroll 8
    for (int d = 0; d < HIDD; d++) { float v = f[d]; sl += v * pal[d]; sr += v * par[d]; }
    el[i] = sl;
    er[i] = sr;
}

__global__ void el_er1_kernel(const float* __restrict__ ft,
                              const float* __restrict__ al,
                              const float* __restrict__ ar,
                              float* __restrict__ el, float* __restrict__ er) {
    int n = blockIdx.x * (blockDim.x >> 5) + (threadIdx.x >> 5);
    int lane = threadIdx.x & 31;
    if (n >= NN) return;
    float sl = 0.0f, sr = 0.0f;
    const float* f = ft + (size_t)n * 256;
#pragma unroll
    for (int d = lane; d < 256; d += 32) { float v = f[d]; sl += v * al[d]; sr += v * ar[d]; }
#pragma unroll
    for (int o = 16; o; o >>= 1) {
        sl += __shfl_down_sync(0xffffffffu, sl, o);
        sr += __shfl_down_sync(0xffffffffu, sr, o);
    }
    if (lane == 0) { el[n] = sl; er[n] = sr; }
}

// =================== aggregation: one block per dst node ====================
__global__ void __launch_bounds__(256)
agg0_kernel(const int* __restrict__ rowptr, const int* __restrict__ adj,
            const float* __restrict__ el, const float* __restrict__ er,
            const float* __restrict__ ft, const float* __restrict__ b0,
            float* __restrict__ h1) {
    const int d = blockIdx.x;
    const int t = threadIdx.x;
    const int h = t >> 6;
    const int start = rowptr[d], end = rowptr[d + 1];

    __shared__ int   s_src[64];
    __shared__ float s_alpha[64 * 4];
    __shared__ float s_m[4], s_sum[4];

    if (t < 32) {
        float4 erd = *(const float4*)(er + (size_t)d * 4);
        float m[4] = {NEGBIG, NEGBIG, NEGBIG, NEGBIG};
        float su[4] = {0.f, 0.f, 0.f, 0.f};
        for (int j = start + t; j < end; j += 32) {
            int s = adj[j];
            float4 e4 = *(const float4*)(el + (size_t)s * 4);
            float v[4];
            v[0] = e4.x + erd.x; v[1] = e4.y + erd.y;
            v[2] = e4.z + erd.z; v[3] = e4.w + erd.w;
#pragma unroll
            for (int k = 0; k < 4; k++) {
                float vv = (v[k] >= 0.f) ? v[k] : NEG * v[k];
                float mn = fmaxf(m[k], vv);
                su[k] = su[k] * expf(m[k] - mn) + expf(vv - mn);
                m[k] = mn;
            }
        }
#pragma unroll
        for (int off = 16; off; off >>= 1) {
#pragma unroll
            for (int k = 0; k < 4; k++) {
                float m2 = __shfl_down_sync(0xffffffffu, m[k], off);
                float s2 = __shfl_down_sync(0xffffffffu, su[k], off);
                float mn = fmaxf(m[k], m2);
                su[k] = su[k] * expf(m[k] - mn) + s2 * expf(m2 - mn);
                m[k] = mn;
            }
        }
        if (t == 0) {
#pragma unroll
            for (int k = 0; k < 4; k++) { s_m[k] = m[k]; s_sum[k] = su[k]; }
        }
    }
    __syncthreads();

    float acc = 0.0f;
    float4 erd = *(const float4*)(er + (size_t)d * 4);
    for (int c = start; c < end; c += 64) {
        int nchunk = min(64, end - c);
        if (t < nchunk) {
            int s = adj[c + t];
            s_src[t] = s;
            float4 e4 = *(const float4*)(el + (size_t)s * 4);
            float v[4];
            v[0] = e4.x + erd.x; v[1] = e4.y + erd.y;
            v[2] = e4.z + erd.z; v[3] = e4.w + erd.w;
#pragma unroll
            for (int k = 0; k < 4; k++) {
                float vv = (v[k] >= 0.f) ? v[k] : NEG * v[k];
                s_alpha[t * 4 + k] = expf(vv - s_m[k]) / s_sum[k];
            }
        }
        __syncthreads();
        int j = 0;
        for (; j + 4 <= nchunk; j += 4) {
            int s0 = s_src[j], s1 = s_src[j + 1], s2 = s_src[j + 2], s3 = s_src[j + 3];
            float a0 = s_alpha[j * 4 + h],       a1 = s_alpha[(j + 1) * 4 + h];
            float a2 = s_alpha[(j + 2) * 4 + h], a3 = s_alpha[(j + 3) * 4 + h];
            float f0 = ft[(size_t)s0 * 256 + t];
            float f1 = ft[(size_t)s1 * 256 + t];
            float f2 = ft[(size_t)s2 * 256 + t];
            float f3 = ft[(size_t)s3 * 256 + t];
            acc += a0 * f0 + a1 * f1 + a2 * f2 + a3 * f3;
        }
        for (; j < nchunk; j++)
            acc += s_alpha[j * 4 + h] * ft[(size_t)s_src[j] * 256 + t];
        __syncthreads();
    }
    float v = acc + b0[t];
    h1[(size_t)d * 256 + t] = (v > 0.f) ? v : expm1f(v);
}

__global__ void __launch_bounds__(256)
agg1_kernel(const int* __restrict__ rowptr, const int* __restrict__ adj,
            const float* __restrict__ el, const float* __restrict__ er,
            const float* __restrict__ ft, const float* __restrict__ h1,
            const float* __restrict__ b1, float* __restrict__ hout) {
    const int d = blockIdx.x;
    const int t = threadIdx.x;
    const int start = rowptr[d], end = rowptr[d + 1];

    __shared__ int   s_src[128];
    __shared__ float s_alpha[128];
    __shared__ float s_m, s_sum;

    if (t < 32) {
        float erd = er[d];
        float m = NEGBIG, su = 0.f;
        for (int j = start + t; j < end; j += 32) {
            int s = adj[j];
            float v = el[s] + erd;
            v = (v >= 0.f) ? v : NEG * v;
            float mn = fmaxf(m, v);
            su = su * expf(m - mn) + expf(v - mn);
            m = mn;
        }
#pragma unroll
        for (int off = 16; off; off >>= 1) {
            float m2 = __shfl_down_sync(0xffffffffu, m, off);
            float s2 = __shfl_down_sync(0xffffffffu, su, off);
            float mn = fmaxf(m, m2);
            su = su * expf(m - mn) + s2 * expf(m2 - mn);
            m = mn;
        }
        if (t == 0) { s_m = m; s_sum = su; }
    }
    __syncthreads();

    float acc = 0.0f;
    float erd = er[d];
    for (int c = start; c < end; c += 128) {
        int nchunk = min(128, end - c);
        if (t < nchunk) {
            int s = adj[c + t];
            s_src[t] = s;
            float v = el[s] + erd;
            v = (v >= 0.f) ? v : NEG * v;
            s_alpha[t] = expf(v - s_m) / s_sum;
        }
        __syncthreads();
        int j = 0;
        for (; j + 4 <= nchunk; j += 4) {
            int s0 = s_src[j], s1 = s_src[j + 1], s2 = s_src[j + 2], s3 = s_src[j + 3];
            float a0 = s_alpha[j],     a1 = s_alpha[j + 1];
            float a2 = s_alpha[j + 2], a3 = s_alpha[j + 3];
            float f0 = ft[(size_t)s0 * 256 + t];
            float f1 = ft[(size_t)s1 * 256 + t];
            float f2 = ft[(size_t)s2 * 256 + t];
            float f3 = ft[(size_t)s3 * 256 + t];
            acc += a0 * f0 + a1 * f1 + a2 * f2 + a3 * f3;
        }
        for (; j < nchunk; j++)
            acc += s_alpha[j] * ft[(size_t)s_src[j] * 256 + t];
        __syncthreads();
    }
    hout[(size_t)d * 256 + t] = acc + h1[(size_t)d * 256 + t] + b1[t];
}

// =================== launch ==================================================
extern "C" void kernel_launch(void* const* d_in, const int* in_sizes, int n_in,
                              void* d_out, int out_size) {
    const float* x   = (const float*)d_in[0];
    const int*   src = (const int*)  d_in[1];
    const int*   dst = (const int*)  d_in[2];
    const float* W0  = (const float*)d_in[3];
    const float* al0 = (const float*)d_in[4];
    const float* ar0 = (const float*)d_in[5];
    const float* b0  = (const float*)d_in[6];
    const float* W1  = (const float*)d_in[7];
    const float* al1 = (const float*)d_in[8];
    const float* ar1 = (const float*)d_in[9];
    const float* b1  = (const float*)d_in[10];
    const float* Wl  = (const float*)d_in[11];
    const float* bl  = (const float*)d_in[12];

    float* out    = (float*)d_out;
    float* logits = out;                      // [NN, NCLS]
    float* hout   = out + (size_t)NN * NCLS;  // [NN, OUT1]

    float *ft, *h1v, *el, *er;
    int *cnt, *rowptr, *bsum, *adj;
    cudaGetSymbolAddress((void**)&ft,     g_ft);
    cudaGetSymbolAddress((void**)&h1v,    g_h1);
    cudaGetSymbolAddress((void**)&el,     g_el);
    cudaGetSymbolAddress((void**)&er,     g_er);
    cudaGetSymbolAddress((void**)&cnt,    g_cnt);
    cudaGetSymbolAddress((void**)&rowptr, g_rowptr);
    cudaGetSymbolAddress((void**)&bsum,   g_bsum);
    cudaGetSymbolAddress((void**)&adj,    g_adj);

    // streams/events created once, on the (uncaptured) correctness call
    static cudaStream_t s_side = nullptr;
    static cudaEvent_t  ev_fork = nullptr, ev_join = nullptr;
    if (s_side == nullptr) {
        cudaStreamCreateWithFlags(&s_side, cudaStreamNonBlocking);
        cudaEventCreateWithFlags(&ev_fork, cudaEventDisableTiming);
        cudaEventCreateWithFlags(&ev_join, cudaEventDisableTiming);
    }

    const int T = 256;
    const int NB_SCAN = (NN + 1023) / 1024;   // 49

    // ---- fork: CSR build on side stream ----
    cudaEventRecord(ev_fork, 0);
    cudaStreamWaitEvent(s_side, ev_fork, 0);
    cudaMemsetAsync(cnt, 0, NN * sizeof(int), s_side);
    hist_kernel<<<(EE + T - 1) / T, T, 0, s_side>>>(dst, cnt);
    scan_block_kernel<<<NB_SCAN, 1024, 0, s_side>>>(cnt, rowptr, bsum);
    scan_bsum_kernel<<<1, 64, 0, s_side>>>(bsum, NB_SCAN);
    scan_add_kernel<<<(NN + T - 1) / T, T, 0, s_side>>>(rowptr, bsum, cnt);
    csr_fill_kernel<<<(EE + T - 1) / T, T, 0, s_side>>>(src, dst, cnt, adj);
    cudaEventRecord(ev_join, s_side);

    // ---- main stream: layer 0 projection (overlaps CSR build) ----
    {
        dim3 grid(256 / 128, (NN + 127) / 128);
        gemm_tf32_async<128, 128, 2, 4><<<grid, 256>>>(x, W0, ft, NN, IND, 256, nullptr);
    }
    el_er0_kernel<<<(NN * H0 + T - 1) / T, T>>>(ft, al0, ar0, el, er);

    // ---- join, then aggregate ----
    cudaStreamWaitEvent(0, ev_join, 0);
    agg0_kernel<<<NN, 256>>>(rowptr, adj, el, er, ft, b0, h1v);

    // ---- layer 1 ----
    {
        dim3 grid(256 / 128, (NN + 127) / 128);
        gemm_tf32_async<128, 128, 2, 4><<<grid, 256>>>(h1v, W1, ft, NN, 256, 256, nullptr);
    }
    el_er1_kernel<<<(NN + 7) / 8, T>>>(ft, al1, ar1, el, er);
    agg1_kernel<<<NN, 256>>>(rowptr, adj, el, er, ft, h1v, b1, hout);

    // ---- classifier ----
    {
        dim3 grid(1, (NN + 127) / 128);
        gemm_tf32_async<128, 64, 4, 2><<<grid, 256>>>(hout, Wl, logits, NN, OUT1, NCLS, bl);
    }
}

// round 5
// speedup vs baseline: 4.3364x; 1.1961x over previous
#include <cuda_runtime.h>
#include <math.h>
#include <stdint.h>

#define NN 50000
#define EE 800000
#define IND 256
#define HIDD 64
#define H0 4
#define OUT1 256
#define NCLS 64
#define NEG 0.2f
#define NEGBIG -1e30f

// ---------------- scratch (device globals; no allocation allowed) ----------
__device__ float g_ft[NN * 256];
__device__ float g_h1[NN * 256];
__device__ float g_el[NN * H0];
__device__ float g_er[NN * H0];
__device__ int   g_cnt[NN];
__device__ int   g_rowptr[NN + 1];
__device__ int   g_bsum[64];
__device__ int   g_adj[EE];

// =================== CSR build ==============================================
__global__ void hist_kernel(const int* __restrict__ dst, int* __restrict__ cnt) {
    int e = blockIdx.x * blockDim.x + threadIdx.x;
    if (e < EE) atomicAdd(&cnt[dst[e]], 1);
}

__global__ void scan_block_kernel(const int* __restrict__ cnt,
                                  int* __restrict__ rowptr,
                                  int* __restrict__ bsum) {
    __shared__ int sh[1024];
    int t = threadIdx.x;
    int i = blockIdx.x * 1024 + t;
    int v = (i < NN) ? cnt[i] : 0;
    sh[t] = v;
    __syncthreads();
    for (int off = 1; off < 1024; off <<= 1) {
        int add = (t >= off) ? sh[t - off] : 0;
        __syncthreads();
        sh[t] += add;
        __syncthreads();
    }
    if (i < NN) rowptr[i] = sh[t] - v;
    if (t == 1023) bsum[blockIdx.x] = sh[t];
}

__global__ void scan_bsum_kernel(int* __restrict__ bsum, int nb) {
    __shared__ int sh[64];
    int t = threadIdx.x;
    int v = (t < nb) ? bsum[t] : 0;
    sh[t] = v;
    __syncthreads();
    for (int off = 1; off < 64; off <<= 1) {
        int add = (t >= off) ? sh[t - off] : 0;
        __syncthreads();
        sh[t] += add;
        __syncthreads();
    }
    if (t < nb) bsum[t] = sh[t] - v;
}

__global__ void scan_add_kernel(int* __restrict__ rowptr,
                                const int* __restrict__ bsum,
                                int* __restrict__ cursor) {
    int i = blockIdx.x * blockDim.x + threadIdx.x;
    if (i < NN) {
        int r = rowptr[i] + bsum[i >> 10];
        rowptr[i] = r;
        cursor[i] = r;
    }
    if (i == 0) rowptr[NN] = EE;
}

__global__ void csr_fill_kernel(const int* __restrict__ src,
                                const int* __restrict__ dst,
                                int* __restrict__ cursor,
                                int* __restrict__ adj) {
    int e = blockIdx.x * blockDim.x + threadIdx.x;
    if (e >= EE) return;
    int pos = atomicAdd(&cursor[dst[e]], 1);
    adj[pos] = src[e];
}

// =================== BF16 3-term split tensor-core GEMM =====================
// pack two floats to bf16x2 (lo = f0, hi = f1)
__device__ __forceinline__ uint32_t packbf(float f0, float f1) {
    uint32_t r;
    asm("cvt.rn.bf16x2.f32 %0, %1, %2;" : "=r"(r) : "f"(f1), "f"(f0));
    return r;
}
// split pair into hi/lo bf16x2
__device__ __forceinline__ void bfsplit2(float f0, float f1,
                                         uint32_t& h, uint32_t& l) {
    h = packbf(f0, f1);
    float h0 = __uint_as_float(h << 16);
    float h1 = __uint_as_float(h & 0xffff0000u);
    l = packbf(f0 - h0, f1 - h1);
}

#define MMA_BF16(d, a, b) \
    asm volatile("mma.sync.aligned.m16n8k16.row.col.f32.bf16.bf16.f32 " \
                 "{%0,%1,%2,%3}, {%4,%5,%6,%7}, {%8,%9}, {%0,%1,%2,%3};" \
                 : "+f"(d[0]), "+f"(d[1]), "+f"(d[2]), "+f"(d[3]) \
                 : "r"(a[0]), "r"(a[1]), "r"(a[2]), "r"(a[3]), \
                   "r"(b[0]), "r"(b[1]))

// C[Nr,M] = A[Nr,K] @ B[K,M] (+bias). K%16==0, block cols in-bounds.
// 256 threads. Smem holds bf16 hi/lo split, layout [kpair][m|n], stride 136.
template<int BM, int BN, int WARPS_M, int WARPS_N>
__global__ void __launch_bounds__(256, 2)
gemm_bf16x3(const float* __restrict__ A, const float* __restrict__ B,
            float* __restrict__ C, int Nr, int K, int M,
            const float* __restrict__ bias) {
    constexpr int WM = BM / WARPS_M;
    constexpr int WN = BN / WARPS_N;
    constexpr int MF = WM / 16;
    constexpr int NF = WN / 8;
    constexpr int LD = 136;            // stride (words); tg*8+g hits 32 banks
    constexpr int STG = 8 * LD;        // 8 k-pairs per 16-K tile
    constexpr int BQ = BN / 4;         // B n-quads per k-pair-row

    __shared__ uint32_t Ah[2][STG], Al[2][STG];
    __shared__ uint32_t Bh[2][STG], Bl[2][STG];

    const int tid  = threadIdx.x;
    const int lane = tid & 31;
    const int warp = tid >> 5;
    const int wm = warp / WARPS_N;
    const int wn = warp % WARPS_N;
    const int rowBase = blockIdx.y * BM;
    const int colBase = blockIdx.x * BN;
    const int g  = lane >> 2;
    const int tg = lane & 3;

    float acc[MF][NF][4];
#pragma unroll
    for (int i = 0; i < MF; i++)
#pragma unroll
        for (int j = 0; j < NF; j++)
#pragma unroll
            for (int k = 0; k < 4; k++) acc[i][j][k] = 0.0f;

    // prefetch registers
    float4 ra[2];                 // A: 2 quads / thread
    float4 rb0, rb1;              // B: row pair (k=2kp, 2kp+1), 4 n's
    const int am[2]  = { (tid) >> 2, (tid + 256) >> 2 };
    const int akq[2] = { (tid & 3) << 2, (tid & 3) << 2 };
    const bool bact = tid < 8 * BQ;
    const int bkp = bact ? tid / BQ : 0;
    const int bnq = bact ? (tid % BQ) << 2 : 0;

    auto ldg_tile = [&](int k0) {
#pragma unroll
        for (int i = 0; i < 2; i++) {
            int gr = rowBase + am[i];
            int grc = (gr < Nr) ? gr : (Nr - 1);
            ra[i] = *(const float4*)(A + (size_t)grc * K + k0 + akq[i]);
        }
        if (bact) {
            rb0 = *(const float4*)(B + (size_t)(k0 + 2 * bkp)     * M + colBase + bnq);
            rb1 = *(const float4*)(B + (size_t)(k0 + 2 * bkp + 1) * M + colBase + bnq);
        }
    };

    auto sts_tile = [&](int s) {
#pragma unroll
        for (int i = 0; i < 2; i++) {
            int kp0 = (akq[i] >> 1);       // = (tid&3)*2
            uint32_t h, l;
            bfsplit2(ra[i].x, ra[i].y, h, l);
            Ah[s][kp0 * LD + am[i]] = h;
            Al[s][kp0 * LD + am[i]] = l;
            bfsplit2(ra[i].z, ra[i].w, h, l);
            Ah[s][(kp0 + 1) * LD + am[i]] = h;
            Al[s][(kp0 + 1) * LD + am[i]] = l;
        }
        if (bact) {
            const float* p0 = &rb0.x;
            const float* p1 = &rb1.x;
            uint32_t hh[4], ll[4];
#pragma unroll
            for (int j = 0; j < 4; j++) bfsplit2(p0[j], p1[j], hh[j], ll[j]);
            *(uint4*)&Bh[s][bkp * LD + bnq] = make_uint4(hh[0], hh[1], hh[2], hh[3]);
            *(uint4*)&Bl[s][bkp * LD + bnq] = make_uint4(ll[0], ll[1], ll[2], ll[3]);
        }
    };

    const int NIT = K / 16;
    ldg_tile(0);

    for (int it = 0; it < NIT; it++) {
        const int s = it & 1;
        sts_tile(s);
        __syncthreads();
        if (it + 1 < NIT) ldg_tile((it + 1) * 16);

        uint32_t bh[NF][2], bl[NF][2];
#pragma unroll
        for (int nf = 0; nf < NF; nf++) {
            int c0 = wn * WN + nf * 8 + g;
            bh[nf][0] = Bh[s][tg * LD + c0];
            bh[nf][1] = Bh[s][(tg + 4) * LD + c0];
            bl[nf][0] = Bl[s][tg * LD + c0];
            bl[nf][1] = Bl[s][(tg + 4) * LD + c0];
        }
#pragma unroll
        for (int mf = 0; mf < MF; mf++) {
            int r0 = wm * WM + mf * 16 + g;
            uint32_t ah[4], al[4];
            ah[0] = Ah[s][tg * LD + r0];
            ah[1] = Ah[s][tg * LD + r0 + 8];
            ah[2] = Ah[s][(tg + 4) * LD + r0];
            ah[3] = Ah[s][(tg + 4) * LD + r0 + 8];
            al[0] = Al[s][tg * LD + r0];
            al[1] = Al[s][tg * LD + r0 + 8];
            al[2] = Al[s][(tg + 4) * LD + r0];
            al[3] = Al[s][(tg + 4) * LD + r0 + 8];
#pragma unroll
            for (int nf = 0; nf < NF; nf++) {
                MMA_BF16(acc[mf][nf], al, bh[nf]);
                MMA_BF16(acc[mf][nf], ah, bl[nf]);
                MMA_BF16(acc[mf][nf], ah, bh[nf]);
            }
        }
        // single sync per iter: next sts targets the other buffer, whose
        // readers (iter it-1) all finished before this iter's sync.
    }

    // epilogue
#pragma unroll
    for (int mf = 0; mf < MF; mf++) {
#pragma unroll
        for (int nf = 0; nf < NF; nf++) {
            int row = rowBase + wm * WM + mf * 16 + g;
            int col = colBase + wn * WN + nf * 8 + tg * 2;
            float b0v = bias ? bias[col]     : 0.0f;
            float b1v = bias ? bias[col + 1] : 0.0f;
            if (row < Nr) {
                float2 o = make_float2(acc[mf][nf][0] + b0v, acc[mf][nf][1] + b1v);
                *(float2*)(C + (size_t)row * M + col) = o;
            }
            if (row + 8 < Nr) {
                float2 o = make_float2(acc[mf][nf][2] + b0v, acc[mf][nf][3] + b1v);
                *(float2*)(C + (size_t)(row + 8) * M + col) = o;
            }
        }
    }
}

// =================== attention coefficients =================================
__global__ void el_er0_kernel(const float* __restrict__ ft,
                              const float* __restrict__ al,
                              const float* __restrict__ ar,
                              float* __restrict__ el, float* __restrict__ er) {
    int i = blockIdx.x * blockDim.x + threadIdx.x;
    if (i >= NN * H0) return;
    int h = i & (H0 - 1);
    const float* f = ft + (size_t)i * HIDD;
    const float* pal = al + h * HIDD;
    const float* par = ar + h * HIDD;
    float sl = 0.0f, sr = 0.0f;
#pragma unroll 8
    for (int d = 0; d < HIDD; d++) { float v = f[d]; sl += v * pal[d]; sr += v * par[d]; }
    el[i] = sl;
    er[i] = sr;
}

__global__ void el_er1_kernel(const float* __restrict__ ft,
                              const float* __restrict__ al,
                              const float* __restrict__ ar,
                              float* __restrict__ el, float* __restrict__ er) {
    int n = blockIdx.x * (blockDim.x >> 5) + (threadIdx.x >> 5);
    int lane = threadIdx.x & 31;
    if (n >= NN) return;
    float sl = 0.0f, sr = 0.0f;
    const float* f = ft + (size_t)n * 256;
#pragma unroll
    for (int d = lane; d < 256; d += 32) { float v = f[d]; sl += v * al[d]; sr += v * ar[d]; }
#pragma unroll
    for (int o = 16; o; o >>= 1) {
        sl += __shfl_down_sync(0xffffffffu, sl, o);
        sr += __shfl_down_sync(0xffffffffu, sr, o);
    }
    if (lane == 0) { el[n] = sl; er[n] = sr; }
}

// =================== aggregation: one block per dst node ====================
__global__ void __launch_bounds__(256)
agg0_kernel(const int* __restrict__ rowptr, const int* __restrict__ adj,
            const float* __restrict__ el, const float* __restrict__ er,
            const float* __restrict__ ft, const float* __restrict__ b0,
            float* __restrict__ h1) {
    const int d = blockIdx.x;
    const int t = threadIdx.x;
    const int h = t >> 6;
    const int start = rowptr[d], end = rowptr[d + 1];

    __shared__ int   s_src[64];
    __shared__ float s_alpha[64 * 4];
    __shared__ float s_m[4], s_sum[4];

    if (t < 32) {
        float4 erd = *(const float4*)(er + (size_t)d * 4);
        float m[4] = {NEGBIG, NEGBIG, NEGBIG, NEGBIG};
        float su[4] = {0.f, 0.f, 0.f, 0.f};
        for (int j = start + t; j < end; j += 32) {
            int s = adj[j];
            float4 e4 = *(const float4*)(el + (size_t)s * 4);
            float v[4];
            v[0] = e4.x + erd.x; v[1] = e4.y + erd.y;
            v[2] = e4.z + erd.z; v[3] = e4.w + erd.w;
#pragma unroll
            for (int k = 0; k < 4; k++) {
                float vv = (v[k] >= 0.f) ? v[k] : NEG * v[k];
                float mn = fmaxf(m[k], vv);
                su[k] = su[k] * expf(m[k] - mn) + expf(vv - mn);
                m[k] = mn;
            }
        }
#pragma unroll
        for (int off = 16; off; off >>= 1) {
#pragma unroll
            for (int k = 0; k < 4; k++) {
                float m2 = __shfl_down_sync(0xffffffffu, m[k], off);
                float s2 = __shfl_down_sync(0xffffffffu, su[k], off);
                float mn = fmaxf(m[k], m2);
                su[k] = su[k] * expf(m[k] - mn) + s2 * expf(m2 - mn);
                m[k] = mn;
            }
        }
        if (t == 0) {
#pragma unroll
            for (int k = 0; k < 4; k++) { s_m[k] = m[k]; s_sum[k] = su[k]; }
        }
    }
    __syncthreads();

    float acc = 0.0f;
    float4 erd = *(const float4*)(er + (size_t)d * 4);
    for (int c = start; c < end; c += 64) {
        int nchunk = min(64, end - c);
        if (t < nchunk) {
            int s = adj[c + t];
            s_src[t] = s;
            float4 e4 = *(const float4*)(el + (size_t)s * 4);
            float v[4];
            v[0] = e4.x + erd.x; v[1] = e4.y + erd.y;
            v[2] = e4.z + erd.z; v[3] = e4.w + erd.w;
#pragma unroll
            for (int k = 0; k < 4; k++) {
                float vv = (v[k] >= 0.f) ? v[k] : NEG * v[k];
                s_alpha[t * 4 + k] = expf(vv - s_m[k]) / s_sum[k];
            }
        }
        __syncthreads();
        int j = 0;
        for (; j + 4 <= nchunk; j += 4) {
            int s0 = s_src[j], s1 = s_src[j + 1], s2 = s_src[j + 2], s3 = s_src[j + 3];
            float a0 = s_alpha[j * 4 + h],       a1 = s_alpha[(j + 1) * 4 + h];
            float a2 = s_alpha[(j + 2) * 4 + h], a3 = s_alpha[(j + 3) * 4 + h];
            float f0 = ft[(size_t)s0 * 256 + t];
            float f1 = ft[(size_t)s1 * 256 + t];
            float f2 = ft[(size_t)s2 * 256 + t];
            float f3 = ft[(size_t)s3 * 256 + t];
            acc += a0 * f0 + a1 * f1 + a2 * f2 + a3 * f3;
        }
        for (; j < nchunk; j++)
            acc += s_alpha[j * 4 + h] * ft[(size_t)s_src[j] * 256 + t];
        __syncthreads();
    }
    float v = acc + b0[t];
    h1[(size_t)d * 256 + t] = (v > 0.f) ? v : expm1f(v);
}

__global__ void __launch_bounds__(256)
agg1_kernel(const int* __restrict__ rowptr, const int* __restrict__ adj,
            const float* __restrict__ el, const float* __restrict__ er,
            const float* __restrict__ ft, const float* __restrict__ h1,
            const float* __restrict__ b1, float* __restrict__ hout) {
    const int d = blockIdx.x;
    const int t = threadIdx.x;
    const int start = rowptr[d], end = rowptr[d + 1];

    __shared__ int   s_src[128];
    __shared__ float s_alpha[128];
    __shared__ float s_m, s_sum;

    if (t < 32) {
        float erd = er[d];
        float m = NEGBIG, su = 0.f;
        for (int j = start + t; j < end; j += 32) {
            int s = adj[j];
            float v = el[s] + erd;
            v = (v >= 0.f) ? v : NEG * v;
            float mn = fmaxf(m, v);
            su = su * expf(m - mn) + expf(v - mn);
            m = mn;
        }
#pragma unroll
        for (int off = 16; off; off >>= 1) {
            float m2 = __shfl_down_sync(0xffffffffu, m, off);
            float s2 = __shfl_down_sync(0xffffffffu, su, off);
            float mn = fmaxf(m, m2);
            su = su * expf(m - mn) + s2 * expf(m2 - mn);
            m = mn;
        }
        if (t == 0) { s_m = m; s_sum = su; }
    }
    __syncthreads();

    float acc = 0.0f;
    float erd = er[d];
    for (int c = start; c < end; c += 128) {
        int nchunk = min(128, end - c);
        if (t < nchunk) {
            int s = adj[c + t];
            s_src[t] = s;
            float v = el[s] + erd;
            v = (v >= 0.f) ? v : NEG * v;
            s_alpha[t] = expf(v - s_m) / s_sum;
        }
        __syncthreads();
        int j = 0;
        for (; j + 4 <= nchunk; j += 4) {
            int s0 = s_src[j], s1 = s_src[j + 1], s2 = s_src[j + 2], s3 = s_src[j + 3];
            float a0 = s_alpha[j],     a1 = s_alpha[j + 1];
            float a2 = s_alpha[j + 2], a3 = s_alpha[j + 3];
            float f0 = ft[(size_t)s0 * 256 + t];
            float f1 = ft[(size_t)s1 * 256 + t];
            float f2 = ft[(size_t)s2 * 256 + t];
            float f3 = ft[(size_t)s3 * 256 + t];
            acc += a0 * f0 + a1 * f1 + a2 * f2 + a3 * f3;
        }
        for (; j < nchunk; j++)
            acc += s_alpha[j] * ft[(size_t)s_src[j] * 256 + t];
        __syncthreads();
    }
    hout[(size_t)d * 256 + t] = acc + h1[(size_t)d * 256 + t] + b1[t];
}

// =================== launch ==================================================
extern "C" void kernel_launch(void* const* d_in, const int* in_sizes, int n_in,
                              void* d_out, int out_size) {
    const float* x   = (const float*)d_in[0];
    const int*   src = (const int*)  d_in[1];
    const int*   dst = (const int*)  d_in[2];
    const float* W0  = (const float*)d_in[3];
    const float* al0 = (const float*)d_in[4];
    const float* ar0 = (const float*)d_in[5];
    const float* b0  = (const float*)d_in[6];
    const float* W1  = (const float*)d_in[7];
    const float* al1 = (const float*)d_in[8];
    const float* ar1 = (const float*)d_in[9];
    const float* b1  = (const float*)d_in[10];
    const float* Wl  = (const float*)d_in[11];
    const float* bl  = (const float*)d_in[12];

    float* out    = (float*)d_out;
    float* logits = out;                      // [NN, NCLS]
    float* hout   = out + (size_t)NN * NCLS;  // [NN, OUT1]

    float *ft, *h1v, *el, *er;
    int *cnt, *rowptr, *bsum, *adj;
    cudaGetSymbolAddress((void**)&ft,     g_ft);
    cudaGetSymbolAddress((void**)&h1v,    g_h1);
    cudaGetSymbolAddress((void**)&el,     g_el);
    cudaGetSymbolAddress((void**)&er,     g_er);
    cudaGetSymbolAddress((void**)&cnt,    g_cnt);
    cudaGetSymbolAddress((void**)&rowptr, g_rowptr);
    cudaGetSymbolAddress((void**)&bsum,   g_bsum);
    cudaGetSymbolAddress((void**)&adj,    g_adj);

    static cudaStream_t s_side = nullptr;
    static cudaEvent_t  ev_fork = nullptr, ev_join = nullptr;
    if (s_side == nullptr) {
        cudaStreamCreateWithFlags(&s_side, cudaStreamNonBlocking);
        cudaEventCreateWithFlags(&ev_fork, cudaEventDisableTiming);
        cudaEventCreateWithFlags(&ev_join, cudaEventDisableTiming);
    }

    const int T = 256;
    const int NB_SCAN = (NN + 1023) / 1024;   // 49

    // ---- fork: CSR build on side stream ----
    cudaEventRecord(ev_fork, 0);
    cudaStreamWaitEvent(s_side, ev_fork, 0);
    cudaMemsetAsync(cnt, 0, NN * sizeof(int), s_side);
    hist_kernel<<<(EE + T - 1) / T, T, 0, s_side>>>(dst, cnt);
    scan_block_kernel<<<NB_SCAN, 1024, 0, s_side>>>(cnt, rowptr, bsum);
    scan_bsum_kernel<<<1, 64, 0, s_side>>>(bsum, NB_SCAN);
    scan_add_kernel<<<(NN + T - 1) / T, T, 0, s_side>>>(rowptr, bsum, cnt);
    csr_fill_kernel<<<(EE + T - 1) / T, T, 0, s_side>>>(src, dst, cnt, adj);
    cudaEventRecord(ev_join, s_side);

    // ---- main stream: layer 0 projection (overlaps CSR build) ----
    {
        dim3 grid(256 / 128, (NN + 127) / 128);
        gemm_bf16x3<128, 128, 2, 4><<<grid, 256>>>(x, W0, ft, NN, IND, 256, nullptr);
    }
    el_er0_kernel<<<(NN * H0 + T - 1) / T, T>>>(ft, al0, ar0, el, er);

    // ---- join, then aggregate ----
    cudaStreamWaitEvent(0, ev_join, 0);
    agg0_kernel<<<NN, 256>>>(rowptr, adj, el, er, ft, b0, h1v);

    // ---- layer 1 ----
    {
        dim3 grid(256 / 128, (NN + 127) / 128);
        gemm_bf16x3<128, 128, 2, 4><<<grid, 256>>>(h1v, W1, ft, NN, 256, 256, nullptr);
    }
    el_er1_kernel<<<(NN + 7) / 8, T>>>(ft, al1, ar1, el, er);
    agg1_kernel<<<NN, 256>>>(rowptr, adj, el, er, ft, h1v, b1, hout);

    // ---- classifier ----
    {
        dim3 grid(1, (NN + 127) / 128);
        gemm_bf16x3<128, 64, 4, 2><<<grid, 256>>>(hout, Wl, logits, NN, OUT1, NCLS, bl);
    }
}

// round 6
// speedup vs baseline: 5.8623x; 1.3519x over previous
#include <cuda_runtime.h>
#include <math.h>
#include <stdint.h>

#define NN 50000
#define EE 800000
#define IND 256
#define HIDD 64
#define H0 4
#define OUT1 256
#define NCLS 64
#define NEG 0.2f
#define NEGBIG -1e30f

// ---------------- scratch (device globals; no allocation allowed) ----------
__device__ float g_ft[NN * 256];
__device__ float g_h1[NN * 256];
__device__ float g_el[NN * H0];
__device__ float g_er[NN * H0];
__device__ float g_wel0[8 * 256];   // [j][k] projection vectors layer0
__device__ float g_wel1[2 * 256];   // [j][k] layer1
__device__ int   g_cnt[NN];
__device__ int   g_rowptr[NN + 1];
__device__ int   g_bsum[64];
__device__ int   g_adj[EE];

// =================== CSR build ==============================================
__global__ void hist_kernel(const int* __restrict__ dst, int* __restrict__ cnt) {
    int e = blockIdx.x * blockDim.x + threadIdx.x;
    if (e < EE) atomicAdd(&cnt[dst[e]], 1);
}

__global__ void scan_block_kernel(const int* __restrict__ cnt,
                                  int* __restrict__ rowptr,
                                  int* __restrict__ bsum) {
    __shared__ int sh[1024];
    int t = threadIdx.x;
    int i = blockIdx.x * 1024 + t;
    int v = (i < NN) ? cnt[i] : 0;
    sh[t] = v;
    __syncthreads();
    for (int off = 1; off < 1024; off <<= 1) {
        int add = (t >= off) ? sh[t - off] : 0;
        __syncthreads();
        sh[t] += add;
        __syncthreads();
    }
    if (i < NN) rowptr[i] = sh[t] - v;
    if (t == 1023) bsum[blockIdx.x] = sh[t];
}

__global__ void scan_bsum_kernel(int* __restrict__ bsum, int nb) {
    __shared__ int sh[64];
    int t = threadIdx.x;
    int v = (t < nb) ? bsum[t] : 0;
    sh[t] = v;
    __syncthreads();
    for (int off = 1; off < 64; off <<= 1) {
        int add = (t >= off) ? sh[t - off] : 0;
        __syncthreads();
        sh[t] += add;
        __syncthreads();
    }
    if (t < nb) bsum[t] = sh[t] - v;
}

__global__ void scan_add_kernel(int* __restrict__ rowptr,
                                const int* __restrict__ bsum,
                                int* __restrict__ cursor) {
    int i = blockIdx.x * blockDim.x + threadIdx.x;
    if (i < NN) {
        int r = rowptr[i] + bsum[i >> 10];
        rowptr[i] = r;
        cursor[i] = r;
    }
    if (i == 0) rowptr[NN] = EE;
}

__global__ void csr_fill_kernel(const int* __restrict__ src,
                                const int* __restrict__ dst,
                                int* __restrict__ cursor,
                                int* __restrict__ adj) {
    int e = blockIdx.x * blockDim.x + threadIdx.x;
    if (e >= EE) return;
    int pos = atomicAdd(&cursor[dst[e]], 1);
    adj[pos] = src[e];
}

// =================== attention projection prep ==============================
// wel0[j][k] = sum_d W0[k, j*64+d]*al0[j,d]  (j<4), ar0 for j>=4
// wel1[0][k] = sum_d W1[k,d]*al1[d]; wel1[1][k] with ar1
__global__ void prep_wel_kernel(const float* __restrict__ W0,
                                const float* __restrict__ al0,
                                const float* __restrict__ ar0,
                                const float* __restrict__ W1,
                                const float* __restrict__ al1,
                                const float* __restrict__ ar1,
                                float* __restrict__ wel0,
                                float* __restrict__ wel1) {
    int k = threadIdx.x;   // 0..255
    if (blockIdx.x == 0) {
#pragma unroll
        for (int j = 0; j < 4; j++) {
            float sl = 0.f, sr = 0.f;
            for (int d = 0; d < 64; d++) {
                float wv = W0[k * 256 + j * 64 + d];
                sl += wv * al0[j * 64 + d];
                sr += wv * ar0[j * 64 + d];
            }
            wel0[j * 256 + k] = sl;
            wel0[(4 + j) * 256 + k] = sr;
        }
    } else {
        float sl = 0.f, sr = 0.f;
        for (int d = 0; d < 256; d++) {
            float wv = W1[k * 256 + d];
            sl += wv * al1[d];
            sr += wv * ar1[d];
        }
        wel1[k] = sl;
        wel1[256 + k] = sr;
    }
}

// el/er = X @ WelT (skinny). One warp per node, 8 warps/block.
template<int HJ>   // heads; J = 2*HJ outputs
__global__ void __launch_bounds__(256)
eler_gemm_kernel(const float* __restrict__ X, const float* __restrict__ WelT,
                 float* __restrict__ el, float* __restrict__ er) {
    constexpr int J = 2 * HJ;
    __shared__ float w[J][256];
    int tid = threadIdx.x;
    for (int i = tid; i < J * 256; i += 256) ((float*)w)[i] = WelT[i];
    __syncthreads();
    int n = blockIdx.x * 8 + (tid >> 5);
    int lane = tid & 31;
    if (n >= NN) return;
    const float* xr = X + (size_t)n * 256;
    float acc[J];
#pragma unroll
    for (int j = 0; j < J; j++) acc[j] = 0.f;
#pragma unroll
    for (int it = 0; it < 8; it++) {
        float xv = xr[lane + it * 32];
#pragma unroll
        for (int j = 0; j < J; j++) acc[j] += xv * w[j][lane + it * 32];
    }
#pragma unroll
    for (int o = 16; o; o >>= 1)
#pragma unroll
        for (int j = 0; j < J; j++) acc[j] += __shfl_xor_sync(0xffffffffu, acc[j], o);
    if (lane == 0) {
#pragma unroll
        for (int j = 0; j < HJ; j++) el[n * HJ + j] = acc[j];
#pragma unroll
        for (int j = 0; j < HJ; j++) er[n * HJ + j] = acc[HJ + j];
    }
}

// =================== BF16 3-term split tensor-core GEMM =====================
__device__ __forceinline__ uint32_t packbf(float f0, float f1) {
    uint32_t r;
    asm("cvt.rn.bf16x2.f32 %0, %1, %2;" : "=r"(r) : "f"(f1), "f"(f0));
    return r;
}
__device__ __forceinline__ void bfsplit2(float f0, float f1,
                                         uint32_t& h, uint32_t& l) {
    h = packbf(f0, f1);
    float h0 = __uint_as_float(h << 16);
    float h1 = __uint_as_float(h & 0xffff0000u);
    l = packbf(f0 - h0, f1 - h1);
}

#define MMA_BF16(d, a, b) \
    asm volatile("mma.sync.aligned.m16n8k16.row.col.f32.bf16.bf16.f32 " \
                 "{%0,%1,%2,%3}, {%4,%5,%6,%7}, {%8,%9}, {%0,%1,%2,%3};" \
                 : "+f"(d[0]), "+f"(d[1]), "+f"(d[2]), "+f"(d[3]) \
                 : "r"(a[0]), "r"(a[1]), "r"(a[2]), "r"(a[3]), \
                   "r"(b[0]), "r"(b[1]))

template<int BM, int BN, int WARPS_M, int WARPS_N>
__global__ void __launch_bounds__(256, 2)
gemm_bf16x3(const float* __restrict__ A, const float* __restrict__ B,
            float* __restrict__ C, int Nr, int K, int M,
            const float* __restrict__ bias) {
    constexpr int WM = BM / WARPS_M;
    constexpr int WN = BN / WARPS_N;
    constexpr int MF = WM / 16;
    constexpr int NF = WN / 8;
    constexpr int LD = 136;
    constexpr int STG = 8 * LD;
    constexpr int BQ = BN / 4;

    __shared__ uint32_t Ah[2][STG], Al[2][STG];
    __shared__ uint32_t Bh[2][STG], Bl[2][STG];

    const int tid  = threadIdx.x;
    const int lane = tid & 31;
    const int warp = tid >> 5;
    const int wm = warp / WARPS_N;
    const int wn = warp % WARPS_N;
    const int rowBase = blockIdx.y * BM;
    const int colBase = blockIdx.x * BN;
    const int g  = lane >> 2;
    const int tg = lane & 3;

    float acc[MF][NF][4];
#pragma unroll
    for (int i = 0; i < MF; i++)
#pragma unroll
        for (int j = 0; j < NF; j++)
#pragma unroll
            for (int k = 0; k < 4; k++) acc[i][j][k] = 0.0f;

    float4 ra[2];
    float4 rb0, rb1;
    const int am[2]  = { (tid) >> 2, (tid + 256) >> 2 };
    const int akq[2] = { (tid & 3) << 2, (tid & 3) << 2 };
    const bool bact = tid < 8 * BQ;
    const int bkp = bact ? tid / BQ : 0;
    const int bnq = bact ? (tid % BQ) << 2 : 0;

    auto ldg_tile = [&](int k0) {
#pragma unroll
        for (int i = 0; i < 2; i++) {
            int gr = rowBase + am[i];
            int grc = (gr < Nr) ? gr : (Nr - 1);
            ra[i] = *(const float4*)(A + (size_t)grc * K + k0 + akq[i]);
        }
        if (bact) {
            rb0 = *(const float4*)(B + (size_t)(k0 + 2 * bkp)     * M + colBase + bnq);
            rb1 = *(const float4*)(B + (size_t)(k0 + 2 * bkp + 1) * M + colBase + bnq);
        }
    };

    auto sts_tile = [&](int s) {
#pragma unroll
        for (int i = 0; i < 2; i++) {
            int kp0 = (akq[i] >> 1);
            uint32_t h, l;
            bfsplit2(ra[i].x, ra[i].y, h, l);
            Ah[s][kp0 * LD + am[i]] = h;
            Al[s][kp0 * LD + am[i]] = l;
            bfsplit2(ra[i].z, ra[i].w, h, l);
            Ah[s][(kp0 + 1) * LD + am[i]] = h;
            Al[s][(kp0 + 1) * LD + am[i]] = l;
        }
        if (bact) {
            const float* p0 = &rb0.x;
            const float* p1 = &rb1.x;
            uint32_t hh[4], ll[4];
#pragma unroll
            for (int j = 0; j < 4; j++) bfsplit2(p0[j], p1[j], hh[j], ll[j]);
            *(uint4*)&Bh[s][bkp * LD + bnq] = make_uint4(hh[0], hh[1], hh[2], hh[3]);
            *(uint4*)&Bl[s][bkp * LD + bnq] = make_uint4(ll[0], ll[1], ll[2], ll[3]);
        }
    };

    const int NIT = K / 16;
    ldg_tile(0);

    for (int it = 0; it < NIT; it++) {
        const int s = it & 1;
        sts_tile(s);
        __syncthreads();
        if (it + 1 < NIT) ldg_tile((it + 1) * 16);

        uint32_t bh[NF][2], bl[NF][2];
#pragma unroll
        for (int nf = 0; nf < NF; nf++) {
            int c0 = wn * WN + nf * 8 + g;
            bh[nf][0] = Bh[s][tg * LD + c0];
            bh[nf][1] = Bh[s][(tg + 4) * LD + c0];
            bl[nf][0] = Bl[s][tg * LD + c0];
            bl[nf][1] = Bl[s][(tg + 4) * LD + c0];
        }
#pragma unroll
        for (int mf = 0; mf < MF; mf++) {
            int r0 = wm * WM + mf * 16 + g;
            uint32_t ah[4], al[4];
            ah[0] = Ah[s][tg * LD + r0];
            ah[1] = Ah[s][tg * LD + r0 + 8];
            ah[2] = Ah[s][(tg + 4) * LD + r0];
            ah[3] = Ah[s][(tg + 4) * LD + r0 + 8];
            al[0] = Al[s][tg * LD + r0];
            al[1] = Al[s][tg * LD + r0 + 8];
            al[2] = Al[s][(tg + 4) * LD + r0];
            al[3] = Al[s][(tg + 4) * LD + r0 + 8];
#pragma unroll
            for (int nf = 0; nf < NF; nf++) {
                MMA_BF16(acc[mf][nf], al, bh[nf]);
                MMA_BF16(acc[mf][nf], ah, bl[nf]);
                MMA_BF16(acc[mf][nf], ah, bh[nf]);
            }
        }
    }

#pragma unroll
    for (int mf = 0; mf < MF; mf++) {
#pragma unroll
        for (int nf = 0; nf < NF; nf++) {
            int row = rowBase + wm * WM + mf * 16 + g;
            int col = colBase + wn * WN + nf * 8 + tg * 2;
            float b0v = bias ? bias[col]     : 0.0f;
            float b1v = bias ? bias[col + 1] : 0.0f;
            if (row < Nr) {
                float2 o = make_float2(acc[mf][nf][0] + b0v, acc[mf][nf][1] + b1v);
                *(float2*)(C + (size_t)row * M + col) = o;
            }
            if (row + 8 < Nr) {
                float2 o = make_float2(acc[mf][nf][2] + b0v, acc[mf][nf][3] + b1v);
                *(float2*)(C + (size_t)(row + 8) * M + col) = o;
            }
        }
    }
}

// =================== aggregation: 64 threads per dst node, float4 ==========
__global__ void __launch_bounds__(64)
agg0_kernel(const int* __restrict__ rowptr, const int* __restrict__ adj,
            const float* __restrict__ el, const float* __restrict__ er,
            const float* __restrict__ ft, const float* __restrict__ b0,
            float* __restrict__ h1) {
    const int d = blockIdx.x;
    const int t = threadIdx.x;          // 0..63
    const int w = t >> 5;
    const int lane = t & 31;
    const int h = t >> 4;               // feature block 4t..4t+3, head = t/16
    const int start = rowptr[d], end = rowptr[d + 1];

    __shared__ int   s_src[64];
    __shared__ float s_alpha[64 * 4];
    __shared__ float s_mw[2][4], s_sw[2][4];
    __shared__ float s_m[4], s_sum[4];

    float4 erd = *(const float4*)(er + (size_t)d * 4);

    // ---- phase A: online softmax, both warps scan stride-64 ----
    {
        float m[4] = {NEGBIG, NEGBIG, NEGBIG, NEGBIG};
        float su[4] = {0.f, 0.f, 0.f, 0.f};
        for (int j = start + t; j < end; j += 64) {
            int s = adj[j];
            float4 e4 = *(const float4*)(el + (size_t)s * 4);
            float v[4];
            v[0] = e4.x + erd.x; v[1] = e4.y + erd.y;
            v[2] = e4.z + erd.z; v[3] = e4.w + erd.w;
#pragma unroll
            for (int k = 0; k < 4; k++) {
                float vv = (v[k] >= 0.f) ? v[k] : NEG * v[k];
                float mn = fmaxf(m[k], vv);
                su[k] = su[k] * expf(m[k] - mn) + expf(vv - mn);
                m[k] = mn;
            }
        }
#pragma unroll
        for (int off = 16; off; off >>= 1) {
#pragma unroll
            for (int k = 0; k < 4; k++) {
                float m2 = __shfl_xor_sync(0xffffffffu, m[k], off);
                float s2 = __shfl_xor_sync(0xffffffffu, su[k], off);
                float mn = fmaxf(m[k], m2);
                su[k] = su[k] * expf(m[k] - mn) + s2 * expf(m2 - mn);
                m[k] = mn;
            }
        }
        if (lane == 0) {
#pragma unroll
            for (int k = 0; k < 4; k++) { s_mw[w][k] = m[k]; s_sw[w][k] = su[k]; }
        }
    }
    __syncthreads();
    if (t == 0) {
#pragma unroll
        for (int k = 0; k < 4; k++) {
            float m0 = s_mw[0][k], m1 = s_mw[1][k];
            float mn = fmaxf(m0, m1);
            s_m[k] = mn;
            s_sum[k] = s_sw[0][k] * expf(m0 - mn) + s_sw[1][k] * expf(m1 - mn);
        }
    }
    __syncthreads();

    // ---- phase B: float4 weighted gather ----
    float4 acc = make_float4(0.f, 0.f, 0.f, 0.f);
    for (int c = start; c < end; c += 64) {
        int nchunk = min(64, end - c);
        if (t < nchunk) {
            int s = adj[c + t];
            s_src[t] = s;
            float4 e4 = *(const float4*)(el + (size_t)s * 4);
            float v[4];
            v[0] = e4.x + erd.x; v[1] = e4.y + erd.y;
            v[2] = e4.z + erd.z; v[3] = e4.w + erd.w;
#pragma unroll
            for (int k = 0; k < 4; k++) {
                float vv = (v[k] >= 0.f) ? v[k] : NEG * v[k];
                s_alpha[t * 4 + k] = expf(vv - s_m[k]) / s_sum[k];
            }
        }
        __syncthreads();
        int j = 0;
        for (; j + 4 <= nchunk; j += 4) {
            float a0 = s_alpha[j * 4 + h],       a1 = s_alpha[(j + 1) * 4 + h];
            float a2 = s_alpha[(j + 2) * 4 + h], a3 = s_alpha[(j + 3) * 4 + h];
            float4 f0 = *(const float4*)(ft + (size_t)s_src[j]     * 256 + 4 * t);
            float4 f1 = *(const float4*)(ft + (size_t)s_src[j + 1] * 256 + 4 * t);
            float4 f2 = *(const float4*)(ft + (size_t)s_src[j + 2] * 256 + 4 * t);
            float4 f3 = *(const float4*)(ft + (size_t)s_src[j + 3] * 256 + 4 * t);
            acc.x += a0 * f0.x + a1 * f1.x + a2 * f2.x + a3 * f3.x;
            acc.y += a0 * f0.y + a1 * f1.y + a2 * f2.y + a3 * f3.y;
            acc.z += a0 * f0.z + a1 * f1.z + a2 * f2.z + a3 * f3.z;
            acc.w += a0 * f0.w + a1 * f1.w + a2 * f2.w + a3 * f3.w;
        }
        for (; j < nchunk; j++) {
            float a = s_alpha[j * 4 + h];
            float4 f = *(const float4*)(ft + (size_t)s_src[j] * 256 + 4 * t);
            acc.x += a * f.x; acc.y += a * f.y; acc.z += a * f.z; acc.w += a * f.w;
        }
        __syncthreads();
    }
    float4 bb = *(const float4*)(b0 + 4 * t);
    float4 o;
    o.x = acc.x + bb.x; o.y = acc.y + bb.y; o.z = acc.z + bb.z; o.w = acc.w + bb.w;
    o.x = (o.x > 0.f) ? o.x : expm1f(o.x);
    o.y = (o.y > 0.f) ? o.y : expm1f(o.y);
    o.z = (o.z > 0.f) ? o.z : expm1f(o.z);
    o.w = (o.w > 0.f) ? o.w : expm1f(o.w);
    *(float4*)(h1 + (size_t)d * 256 + 4 * t) = o;
}

__global__ void __launch_bounds__(64)
agg1_kernel(const int* __restrict__ rowptr, const int* __restrict__ adj,
            const float* __restrict__ el, const float* __restrict__ er,
            const float* __restrict__ ft, const float* __restrict__ h1,
            const float* __restrict__ b1, float* __restrict__ hout) {
    const int d = blockIdx.x;
    const int t = threadIdx.x;
    const int w = t >> 5;
    const int lane = t & 31;
    const int start = rowptr[d], end = rowptr[d + 1];

    __shared__ int   s_src[64];
    __shared__ float s_alpha[64];
    __shared__ float s_mw[2], s_sw[2];
    __shared__ float s_m, s_sum;

    float erd = er[d];

    {
        float m = NEGBIG, su = 0.f;
        for (int j = start + t; j < end; j += 64) {
            int s = adj[j];
            float v = el[s] + erd;
            v = (v >= 0.f) ? v : NEG * v;
            float mn = fmaxf(m, v);
            su = su * expf(m - mn) + expf(v - mn);
            m = mn;
        }
#pragma unroll
        for (int off = 16; off; off >>= 1) {
            float m2 = __shfl_xor_sync(0xffffffffu, m, off);
            float s2 = __shfl_xor_sync(0xffffffffu, su, off);
            float mn = fmaxf(m, m2);
            su = su * expf(m - mn) + s2 * expf(m2 - mn);
            m = mn;
        }
        if (lane == 0) { s_mw[w] = m; s_sw[w] = su; }
    }
    __syncthreads();
    if (t == 0) {
        float m0 = s_mw[0], m1 = s_mw[1];
        float mn = fmaxf(m0, m1);
        s_m = mn;
        s_sum = s_sw[0] * expf(m0 - mn) + s_sw[1] * expf(m1 - mn);
    }
    __syncthreads();

    float4 acc = make_float4(0.f, 0.f, 0.f, 0.f);
    for (int c = start; c < end; c += 64) {
        int nchunk = min(64, end - c);
        if (t < nchunk) {
            int s = adj[c + t];
            s_src[t] = s;
            float v = el[s] + erd;
            v = (v >= 0.f) ? v : NEG * v;
            s_alpha[t] = expf(v - s_m) / s_sum;
        }
        __syncthreads();
        int j = 0;
        for (; j + 4 <= nchunk; j += 4) {
            float a0 = s_alpha[j],     a1 = s_alpha[j + 1];
            float a2 = s_alpha[j + 2], a3 = s_alpha[j + 3];
            float4 f0 = *(const float4*)(ft + (size_t)s_src[j]     * 256 + 4 * t);
            float4 f1 = *(const float4*)(ft + (size_t)s_src[j + 1] * 256 + 4 * t);
            float4 f2 = *(const float4*)(ft + (size_t)s_src[j + 2] * 256 + 4 * t);
            float4 f3 = *(const float4*)(ft + (size_t)s_src[j + 3] * 256 + 4 * t);
            acc.x += a0 * f0.x + a1 * f1.x + a2 * f2.x + a3 * f3.x;
            acc.y += a0 * f0.y + a1 * f1.y + a2 * f2.y + a3 * f3.y;
            acc.z += a0 * f0.z + a1 * f1.z + a2 * f2.z + a3 * f3.z;
            acc.w += a0 * f0.w + a1 * f1.w + a2 * f2.w + a3 * f3.w;
        }
        for (; j < nchunk; j++) {
            float a = s_alpha[j];
            float4 f = *(const float4*)(ft + (size_t)s_src[j] * 256 + 4 * t);
            acc.x += a * f.x; acc.y += a * f.y; acc.z += a * f.z; acc.w += a * f.w;
        }
        __syncthreads();
    }
    float4 hr = *(const float4*)(h1 + (size_t)d * 256 + 4 * t);
    float4 bb = *(const float4*)(b1 + 4 * t);
    float4 o;
    o.x = acc.x + hr.x + bb.x;
    o.y = acc.y + hr.y + bb.y;
    o.z = acc.z + hr.z + bb.z;
    o.w = acc.w + hr.w + bb.w;
    *(float4*)(hout + (size_t)d * 256 + 4 * t) = o;
}

// =================== launch ==================================================
extern "C" void kernel_launch(void* const* d_in, const int* in_sizes, int n_in,
                              void* d_out, int out_size) {
    const float* x   = (const float*)d_in[0];
    const int*   src = (const int*)  d_in[1];
    const int*   dst = (const int*)  d_in[2];
    const float* W0  = (const float*)d_in[3];
    const float* al0 = (const float*)d_in[4];
    const float* ar0 = (const float*)d_in[5];
    const float* b0  = (const float*)d_in[6];
    const float* W1  = (const float*)d_in[7];
    const float* al1 = (const float*)d_in[8];
    const float* ar1 = (const float*)d_in[9];
    const float* b1  = (const float*)d_in[10];
    const float* Wl  = (const float*)d_in[11];
    const float* bl  = (const float*)d_in[12];

    float* out    = (float*)d_out;
    float* logits = out;
    float* hout   = out + (size_t)NN * NCLS;

    float *ft, *h1v, *el, *er, *wel0, *wel1;
    int *cnt, *rowptr, *bsum, *adj;
    cudaGetSymbolAddress((void**)&ft,     g_ft);
    cudaGetSymbolAddress((void**)&h1v,    g_h1);
    cudaGetSymbolAddress((void**)&el,     g_el);
    cudaGetSymbolAddress((void**)&er,     g_er);
    cudaGetSymbolAddress((void**)&wel0,   g_wel0);
    cudaGetSymbolAddress((void**)&wel1,   g_wel1);
    cudaGetSymbolAddress((void**)&cnt,    g_cnt);
    cudaGetSymbolAddress((void**)&rowptr, g_rowptr);
    cudaGetSymbolAddress((void**)&bsum,   g_bsum);
    cudaGetSymbolAddress((void**)&adj,    g_adj);

    static cudaStream_t s1 = nullptr, s2 = nullptr;
    static cudaEvent_t ev_fork = nullptr, ev_csr = nullptr, ev_el0 = nullptr,
                       ev_h1 = nullptr, ev_el1 = nullptr;
    if (s1 == nullptr) {
        cudaStreamCreateWithFlags(&s1, cudaStreamNonBlocking);
        cudaStreamCreateWithFlags(&s2, cudaStreamNonBlocking);
        cudaEventCreateWithFlags(&ev_fork, cudaEventDisableTiming);
        cudaEventCreateWithFlags(&ev_csr,  cudaEventDisableTiming);
        cudaEventCreateWithFlags(&ev_el0,  cudaEventDisableTiming);
        cudaEventCreateWithFlags(&ev_h1,   cudaEventDisableTiming);
        cudaEventCreateWithFlags(&ev_el1,  cudaEventDisableTiming);
    }

    const int T = 256;
    const int NB_SCAN = (NN + 1023) / 1024;

    cudaEventRecord(ev_fork, 0);

    // ---- s1: CSR build ----
    cudaStreamWaitEvent(s1, ev_fork, 0);
    cudaMemsetAsync(cnt, 0, NN * sizeof(int), s1);
    hist_kernel<<<(EE + T - 1) / T, T, 0, s1>>>(dst, cnt);
    scan_block_kernel<<<NB_SCAN, 1024, 0, s1>>>(cnt, rowptr, bsum);
    scan_bsum_kernel<<<1, 64, 0, s1>>>(bsum, NB_SCAN);
    scan_add_kernel<<<(NN + T - 1) / T, T, 0, s1>>>(rowptr, bsum, cnt);
    csr_fill_kernel<<<(EE + T - 1) / T, T, 0, s1>>>(src, dst, cnt, adj);
    cudaEventRecord(ev_csr, s1);

    // ---- s2: attention projections ----
    cudaStreamWaitEvent(s2, ev_fork, 0);
    prep_wel_kernel<<<2, 256, 0, s2>>>(W0, al0, ar0, W1, al1, ar1, wel0, wel1);
    eler_gemm_kernel<4><<<(NN + 7) / 8, 256, 0, s2>>>(x, wel0, el, er);
    cudaEventRecord(ev_el0, s2);

    // ---- main: layer 0 projection ----
    {
        dim3 grid(256 / 128, (NN + 127) / 128);
        gemm_bf16x3<128, 128, 2, 4><<<grid, 256>>>(x, W0, ft, NN, IND, 256, nullptr);
    }
    cudaStreamWaitEvent(0, ev_csr, 0);
    cudaStreamWaitEvent(0, ev_el0, 0);
    agg0_kernel<<<NN, 64>>>(rowptr, adj, el, er, ft, b0, h1v);
    cudaEventRecord(ev_h1, 0);

    // ---- s2: layer-1 el/er (needs h1v) ----
    cudaStreamWaitEvent(s2, ev_h1, 0);
    eler_gemm_kernel<1><<<(NN + 7) / 8, 256, 0, s2>>>(h1v, wel1, el, er);
    cudaEventRecord(ev_el1, s2);

    // ---- main: layer-1 projection ----
    {
        dim3 grid(256 / 128, (NN + 127) / 128);
        gemm_bf16x3<128, 128, 2, 4><<<grid, 256>>>(h1v, W1, ft, NN, 256, 256, nullptr);
    }
    cudaStreamWaitEvent(0, ev_el1, 0);
    agg1_kernel<<<NN, 64>>>(rowptr, adj, el, er, ft, h1v, b1, hout);

    // ---- classifier ----
    {
        dim3 grid(1, (NN + 127) / 128);
        gemm_bf16x3<128, 64, 4, 2><<<grid, 256>>>(hout, Wl, logits, NN, OUT1, NCLS, bl);
    }
}

// round 7
// speedup vs baseline: 6.0326x; 1.0290x over previous
#include <cuda_runtime.h>
#include <cuda_fp16.h>
#include <math.h>
#include <stdint.h>

#define NN 50000
#define EE 800000
#define IND 256
#define HIDD 64
#define H0 4
#define OUT1 256
#define NCLS 64
#define NEG 0.2f
#define NEGBIG -1e30f

// ---------------- scratch (device globals; no allocation allowed) ----------
__device__ __half g_ft16[NN * 256];   // projected features, fp16 (gather-only)
__device__ float  g_h1[NN * 256];
__device__ float  g_el[NN * H0];
__device__ float  g_er[NN * H0];
__device__ float  g_el1[NN];
__device__ float  g_er1[NN];
__device__ float  g_wel0[8 * 256];
__device__ float  g_wel1[2 * 256];
__device__ int    g_cnt[NN];
__device__ int    g_rowptr[NN + 1];
__device__ int    g_bsum[64];
__device__ int    g_adj[EE];

// =================== CSR build ==============================================
__global__ void hist_kernel(const int* __restrict__ dst, int* __restrict__ cnt) {
    int e = blockIdx.x * blockDim.x + threadIdx.x;
    if (e < EE) atomicAdd(&cnt[dst[e]], 1);
}

__global__ void scan_block_kernel(const int* __restrict__ cnt,
                                  int* __restrict__ rowptr,
                                  int* __restrict__ bsum) {
    __shared__ int sh[1024];
    int t = threadIdx.x;
    int i = blockIdx.x * 1024 + t;
    int v = (i < NN) ? cnt[i] : 0;
    sh[t] = v;
    __syncthreads();
    for (int off = 1; off < 1024; off <<= 1) {
        int add = (t >= off) ? sh[t - off] : 0;
        __syncthreads();
        sh[t] += add;
        __syncthreads();
    }
    if (i < NN) rowptr[i] = sh[t] - v;
    if (t == 1023) bsum[blockIdx.x] = sh[t];
}

__global__ void scan_bsum_kernel(int* __restrict__ bsum, int nb) {
    __shared__ int sh[64];
    int t = threadIdx.x;
    int v = (t < nb) ? bsum[t] : 0;
    sh[t] = v;
    __syncthreads();
    for (int off = 1; off < 64; off <<= 1) {
        int add = (t >= off) ? sh[t - off] : 0;
        __syncthreads();
        sh[t] += add;
        __syncthreads();
    }
    if (t < nb) bsum[t] = sh[t] - v;
}

__global__ void scan_add_kernel(int* __restrict__ rowptr,
                                const int* __restrict__ bsum,
                                int* __restrict__ cursor) {
    int i = blockIdx.x * blockDim.x + threadIdx.x;
    if (i < NN) {
        int r = rowptr[i] + bsum[i >> 10];
        rowptr[i] = r;
        cursor[i] = r;
    }
    if (i == 0) rowptr[NN] = EE;
}

__global__ void csr_fill_kernel(const int* __restrict__ src,
                                const int* __restrict__ dst,
                                int* __restrict__ cursor,
                                int* __restrict__ adj) {
    int e = blockIdx.x * blockDim.x + threadIdx.x;
    if (e >= EE) return;
    int pos = atomicAdd(&cursor[dst[e]], 1);
    adj[pos] = src[e];
}

// =================== attention projection prep ==============================
__global__ void prep_wel_kernel(const float* __restrict__ W0,
                                const float* __restrict__ al0,
                                const float* __restrict__ ar0,
                                const float* __restrict__ W1,
                                const float* __restrict__ al1,
                                const float* __restrict__ ar1,
                                float* __restrict__ wel0,
                                float* __restrict__ wel1) {
    int k = threadIdx.x;
    if (blockIdx.x == 0) {
#pragma unroll
        for (int j = 0; j < 4; j++) {
            float sl = 0.f, sr = 0.f;
            for (int d = 0; d < 64; d++) {
                float wv = W0[k * 256 + j * 64 + d];
                sl += wv * al0[j * 64 + d];
                sr += wv * ar0[j * 64 + d];
            }
            wel0[j * 256 + k] = sl;
            wel0[(4 + j) * 256 + k] = sr;
        }
    } else {
        float sl = 0.f, sr = 0.f;
        for (int d = 0; d < 256; d++) {
            float wv = W1[k * 256 + d];
            sl += wv * al1[d];
            sr += wv * ar1[d];
        }
        wel1[k] = sl;
        wel1[256 + k] = sr;
    }
}

// el/er = X @ WelT (skinny). One warp per node, 8 warps/block.
__global__ void __launch_bounds__(256)
eler0_kernel(const float* __restrict__ X, const float* __restrict__ WelT,
             float* __restrict__ el, float* __restrict__ er) {
    __shared__ float w[8][256];
    int tid = threadIdx.x;
    for (int i = tid; i < 8 * 256; i += 256) ((float*)w)[i] = WelT[i];
    __syncthreads();
    int n = blockIdx.x * 8 + (tid >> 5);
    int lane = tid & 31;
    if (n >= NN) return;
    const float* xr = X + (size_t)n * 256;
    float acc[8];
#pragma unroll
    for (int j = 0; j < 8; j++) acc[j] = 0.f;
#pragma unroll
    for (int it = 0; it < 8; it++) {
        float xv = xr[lane + it * 32];
#pragma unroll
        for (int j = 0; j < 8; j++) acc[j] += xv * w[j][lane + it * 32];
    }
#pragma unroll
    for (int o = 16; o; o >>= 1)
#pragma unroll
        for (int j = 0; j < 8; j++) acc[j] += __shfl_xor_sync(0xffffffffu, acc[j], o);
    if (lane == 0) {
#pragma unroll
        for (int j = 0; j < 4; j++) el[n * 4 + j] = acc[j];
#pragma unroll
        for (int j = 0; j < 4; j++) er[n * 4 + j] = acc[4 + j];
    }
}

// =================== BF16 3-term split tensor-core GEMM =====================
__device__ __forceinline__ uint32_t packbf(float f0, float f1) {
    uint32_t r;
    asm("cvt.rn.bf16x2.f32 %0, %1, %2;" : "=r"(r) : "f"(f1), "f"(f0));
    return r;
}
__device__ __forceinline__ void bfsplit2(float f0, float f1,
                                         uint32_t& h, uint32_t& l) {
    h = packbf(f0, f1);
    float h0 = __uint_as_float(h << 16);
    float h1 = __uint_as_float(h & 0xffff0000u);
    l = packbf(f0 - h0, f1 - h1);
}

#define MMA_BF16(d, a, b) \
    asm volatile("mma.sync.aligned.m16n8k16.row.col.f32.bf16.bf16.f32 " \
                 "{%0,%1,%2,%3}, {%4,%5,%6,%7}, {%8,%9}, {%0,%1,%2,%3};" \
                 : "+f"(d[0]), "+f"(d[1]), "+f"(d[2]), "+f"(d[3]) \
                 : "r"(a[0]), "r"(a[1]), "r"(a[2]), "r"(a[3]), \
                   "r"(b[0]), "r"(b[1]))

// C[Nr,M] = A[Nr,K] @ B[K,M] (+bias). HOUT: write fp16 (bias must be null).
template<int BM, int BN, int WARPS_M, int WARPS_N, bool HOUT>
__global__ void __launch_bounds__(256, 2)
gemm_bf16x3(const float* __restrict__ A, const float* __restrict__ B,
            void* __restrict__ Cv, int Nr, int K, int M,
            const float* __restrict__ bias) {
    constexpr int WM = BM / WARPS_M;
    constexpr int WN = BN / WARPS_N;
    constexpr int MF = WM / 16;
    constexpr int NF = WN / 8;
    constexpr int LD = 136;
    constexpr int STG = 8 * LD;
    constexpr int BQ = BN / 4;

    __shared__ uint32_t Ah[2][STG], Al[2][STG];
    __shared__ uint32_t Bh[2][STG], Bl[2][STG];

    const int tid  = threadIdx.x;
    const int lane = tid & 31;
    const int warp = tid >> 5;
    const int wm = warp / WARPS_N;
    const int wn = warp % WARPS_N;
    const int rowBase = blockIdx.y * BM;
    const int colBase = blockIdx.x * BN;
    const int g  = lane >> 2;
    const int tg = lane & 3;

    float acc[MF][NF][4];
#pragma unroll
    for (int i = 0; i < MF; i++)
#pragma unroll
        for (int j = 0; j < NF; j++)
#pragma unroll
            for (int k = 0; k < 4; k++) acc[i][j][k] = 0.0f;

    float4 ra[2];
    float4 rb0, rb1;
    const int am[2]  = { (tid) >> 2, (tid + 256) >> 2 };
    const int akq[2] = { (tid & 3) << 2, (tid & 3) << 2 };
    const bool bact = tid < 8 * BQ;
    const int bkp = bact ? tid / BQ : 0;
    const int bnq = bact ? (tid % BQ) << 2 : 0;

    auto ldg_tile = [&](int k0) {
#pragma unroll
        for (int i = 0; i < 2; i++) {
            int gr = rowBase + am[i];
            int grc = (gr < Nr) ? gr : (Nr - 1);
            ra[i] = *(const float4*)(A + (size_t)grc * K + k0 + akq[i]);
        }
        if (bact) {
            rb0 = *(const float4*)(B + (size_t)(k0 + 2 * bkp)     * M + colBase + bnq);
            rb1 = *(const float4*)(B + (size_t)(k0 + 2 * bkp + 1) * M + colBase + bnq);
        }
    };

    auto sts_tile = [&](int s) {
#pragma unroll
        for (int i = 0; i < 2; i++) {
            int kp0 = (akq[i] >> 1);
            uint32_t h, l;
            bfsplit2(ra[i].x, ra[i].y, h, l);
            Ah[s][kp0 * LD + am[i]] = h;
            Al[s][kp0 * LD + am[i]] = l;
            bfsplit2(ra[i].z, ra[i].w, h, l);
            Ah[s][(kp0 + 1) * LD + am[i]] = h;
            Al[s][(kp0 + 1) * LD + am[i]] = l;
        }
        if (bact) {
            const float* p0 = &rb0.x;
            const float* p1 = &rb1.x;
            uint32_t hh[4], ll[4];
#pragma unroll
            for (int j = 0; j < 4; j++) bfsplit2(p0[j], p1[j], hh[j], ll[j]);
            *(uint4*)&Bh[s][bkp * LD + bnq] = make_uint4(hh[0], hh[1], hh[2], hh[3]);
            *(uint4*)&Bl[s][bkp * LD + bnq] = make_uint4(ll[0], ll[1], ll[2], ll[3]);
        }
    };

    const int NIT = K / 16;
    ldg_tile(0);

    for (int it = 0; it < NIT; it++) {
        const int s = it & 1;
        sts_tile(s);
        __syncthreads();
        if (it + 1 < NIT) ldg_tile((it + 1) * 16);

        uint32_t bh[NF][2], bl[NF][2];
#pragma unroll
        for (int nf = 0; nf < NF; nf++) {
            int c0 = wn * WN + nf * 8 + g;
            bh[nf][0] = Bh[s][tg * LD + c0];
            bh[nf][1] = Bh[s][(tg + 4) * LD + c0];
            bl[nf][0] = Bl[s][tg * LD + c0];
            bl[nf][1] = Bl[s][(tg + 4) * LD + c0];
        }
#pragma unroll
        for (int mf = 0; mf < MF; mf++) {
            int r0 = wm * WM + mf * 16 + g;
            uint32_t ah[4], al[4];
            ah[0] = Ah[s][tg * LD + r0];
            ah[1] = Ah[s][tg * LD + r0 + 8];
            ah[2] = Ah[s][(tg + 4) * LD + r0];
            ah[3] = Ah[s][(tg + 4) * LD + r0 + 8];
            al[0] = Al[s][tg * LD + r0];
            al[1] = Al[s][tg * LD + r0 + 8];
            al[2] = Al[s][(tg + 4) * LD + r0];
            al[3] = Al[s][(tg + 4) * LD + r0 + 8];
#pragma unroll
            for (int nf = 0; nf < NF; nf++) {
                MMA_BF16(acc[mf][nf], al, bh[nf]);
                MMA_BF16(acc[mf][nf], ah, bl[nf]);
                MMA_BF16(acc[mf][nf], ah, bh[nf]);
            }
        }
    }

#pragma unroll
    for (int mf = 0; mf < MF; mf++) {
#pragma unroll
        for (int nf = 0; nf < NF; nf++) {
            int row = rowBase + wm * WM + mf * 16 + g;
            int col = colBase + wn * WN + nf * 8 + tg * 2;
            if (HOUT) {
                __half* C16 = (__half*)Cv;
                if (row < Nr)
                    *(half2*)(C16 + (size_t)row * M + col) =
                        __floats2half2_rn(acc[mf][nf][0], acc[mf][nf][1]);
                if (row + 8 < Nr)
                    *(half2*)(C16 + (size_t)(row + 8) * M + col) =
                        __floats2half2_rn(acc[mf][nf][2], acc[mf][nf][3]);
            } else {
                float* C = (float*)Cv;
                float b0v = bias ? bias[col]     : 0.0f;
                float b1v = bias ? bias[col + 1] : 0.0f;
                if (row < Nr) {
                    float2 o = make_float2(acc[mf][nf][0] + b0v, acc[mf][nf][1] + b1v);
                    *(float2*)(C + (size_t)row * M + col) = o;
                }
                if (row + 8 < Nr) {
                    float2 o = make_float2(acc[mf][nf][2] + b0v, acc[mf][nf][3] + b1v);
                    *(float2*)(C + (size_t)(row + 8) * M + col) = o;
                }
            }
        }
    }
}

// =================== aggregation =============================================
__device__ __forceinline__ float4 ld_ft4(const __half* p) {
    uint2 r = *(const uint2*)p;
    float2 f01 = __half22float2(*reinterpret_cast<const half2*>(&r.x));
    float2 f23 = __half22float2(*reinterpret_cast<const half2*>(&r.y));
    return make_float4(f01.x, f01.y, f23.x, f23.y);
}

// layer 0: fused bias+ELU, plus layer-1 el/er computed from the h1 row.
__global__ void __launch_bounds__(64)
agg0_kernel(const int* __restrict__ rowptr, const int* __restrict__ adj,
            const float* __restrict__ el, const float* __restrict__ er,
            const __half* __restrict__ ft, const float* __restrict__ b0,
            const float* __restrict__ wel1,
            float* __restrict__ h1,
            float* __restrict__ el1, float* __restrict__ er1) {
    const int d = blockIdx.x;
    const int t = threadIdx.x;
    const int w = t >> 5;
    const int lane = t & 31;
    const int h = t >> 4;
    const int start = rowptr[d], end = rowptr[d + 1];

    __shared__ int   s_src[64];
    __shared__ float s_alpha[64 * 4];
    __shared__ float s_mw[2][4], s_sw[2][4];
    __shared__ float s_m[4], s_sum[4];
    __shared__ float s_red[2][2];

    float4 erd = *(const float4*)(er + (size_t)d * 4);

    {
        float m[4] = {NEGBIG, NEGBIG, NEGBIG, NEGBIG};
        float su[4] = {0.f, 0.f, 0.f, 0.f};
        for (int j = start + t; j < end; j += 64) {
            int s = adj[j];
            float4 e4 = *(const float4*)(el + (size_t)s * 4);
            float v[4];
            v[0] = e4.x + erd.x; v[1] = e4.y + erd.y;
            v[2] = e4.z + erd.z; v[3] = e4.w + erd.w;
#pragma unroll
            for (int k = 0; k < 4; k++) {
                float vv = (v[k] >= 0.f) ? v[k] : NEG * v[k];
                float mn = fmaxf(m[k], vv);
                su[k] = su[k] * expf(m[k] - mn) + expf(vv - mn);
                m[k] = mn;
            }
        }
#pragma unroll
        for (int off = 16; off; off >>= 1) {
#pragma unroll
            for (int k = 0; k < 4; k++) {
                float m2 = __shfl_xor_sync(0xffffffffu, m[k], off);
                float s2 = __shfl_xor_sync(0xffffffffu, su[k], off);
                float mn = fmaxf(m[k], m2);
                su[k] = su[k] * expf(m[k] - mn) + s2 * expf(m2 - mn);
                m[k] = mn;
            }
        }
        if (lane == 0) {
#pragma unroll
            for (int k = 0; k < 4; k++) { s_mw[w][k] = m[k]; s_sw[w][k] = su[k]; }
        }
    }
    __syncthreads();
    if (t == 0) {
#pragma unroll
        for (int k = 0; k < 4; k++) {
            float m0 = s_mw[0][k], m1 = s_mw[1][k];
            float mn = fmaxf(m0, m1);
            s_m[k] = mn;
            s_sum[k] = s_sw[0][k] * expf(m0 - mn) + s_sw[1][k] * expf(m1 - mn);
        }
    }
    __syncthreads();

    float4 acc = make_float4(0.f, 0.f, 0.f, 0.f);
    for (int c = start; c < end; c += 64) {
        int nchunk = min(64, end - c);
        if (t < nchunk) {
            int s = adj[c + t];
            s_src[t] = s;
            float4 e4 = *(const float4*)(el + (size_t)s * 4);
            float v[4];
            v[0] = e4.x + erd.x; v[1] = e4.y + erd.y;
            v[2] = e4.z + erd.z; v[3] = e4.w + erd.w;
#pragma unroll
            for (int k = 0; k < 4; k++) {
                float vv = (v[k] >= 0.f) ? v[k] : NEG * v[k];
                s_alpha[t * 4 + k] = expf(vv - s_m[k]) / s_sum[k];
            }
        }
        __syncthreads();
        int j = 0;
        for (; j + 4 <= nchunk; j += 4) {
            float a0 = s_alpha[j * 4 + h],       a1 = s_alpha[(j + 1) * 4 + h];
            float a2 = s_alpha[(j + 2) * 4 + h], a3 = s_alpha[(j + 3) * 4 + h];
            float4 f0 = ld_ft4(ft + (size_t)s_src[j]     * 256 + 4 * t);
            float4 f1 = ld_ft4(ft + (size_t)s_src[j + 1] * 256 + 4 * t);
            float4 f2 = ld_ft4(ft + (size_t)s_src[j + 2] * 256 + 4 * t);
            float4 f3 = ld_ft4(ft + (size_t)s_src[j + 3] * 256 + 4 * t);
            acc.x += a0 * f0.x + a1 * f1.x + a2 * f2.x + a3 * f3.x;
            acc.y += a0 * f0.y + a1 * f1.y + a2 * f2.y + a3 * f3.y;
            acc.z += a0 * f0.z + a1 * f1.z + a2 * f2.z + a3 * f3.z;
            acc.w += a0 * f0.w + a1 * f1.w + a2 * f2.w + a3 * f3.w;
        }
        for (; j < nchunk; j++) {
            float a = s_alpha[j * 4 + h];
            float4 f = ld_ft4(ft + (size_t)s_src[j] * 256 + 4 * t);
            acc.x += a * f.x; acc.y += a * f.y; acc.z += a * f.z; acc.w += a * f.w;
        }
        __syncthreads();
    }
    float4 bb = *(const float4*)(b0 + 4 * t);
    float4 o;
    o.x = acc.x + bb.x; o.y = acc.y + bb.y; o.z = acc.z + bb.z; o.w = acc.w + bb.w;
    o.x = (o.x > 0.f) ? o.x : expm1f(o.x);
    o.y = (o.y > 0.f) ? o.y : expm1f(o.y);
    o.z = (o.z > 0.f) ? o.z : expm1f(o.z);
    o.w = (o.w > 0.f) ? o.w : expm1f(o.w);
    *(float4*)(h1 + (size_t)d * 256 + 4 * t) = o;

    // fused layer-1 el/er from the h1 row
    float4 wl = *(const float4*)(wel1 + 4 * t);
    float4 wr = *(const float4*)(wel1 + 256 + 4 * t);
    float sl = o.x * wl.x + o.y * wl.y + o.z * wl.z + o.w * wl.w;
    float sr = o.x * wr.x + o.y * wr.y + o.z * wr.z + o.w * wr.w;
#pragma unroll
    for (int off = 16; off; off >>= 1) {
        sl += __shfl_xor_sync(0xffffffffu, sl, off);
        sr += __shfl_xor_sync(0xffffffffu, sr, off);
    }
    if (lane == 0) { s_red[w][0] = sl; s_red[w][1] = sr; }
    __syncthreads();
    if (t == 0) {
        el1[d] = s_red[0][0] + s_red[1][0];
        er1[d] = s_red[0][1] + s_red[1][1];
    }
}

__global__ void __launch_bounds__(64)
agg1_kernel(const int* __restrict__ rowptr, const int* __restrict__ adj,
            const float* __restrict__ el, const float* __restrict__ er,
            const __half* __restrict__ ft, const float* __restrict__ h1,
            const float* __restrict__ b1, float* __restrict__ hout) {
    const int d = blockIdx.x;
    const int t = threadIdx.x;
    const int w = t >> 5;
    const int lane = t & 31;
    const int start = rowptr[d], end = rowptr[d + 1];

    __shared__ int   s_src[64];
    __shared__ float s_alpha[64];
    __shared__ float s_mw[2], s_sw[2];
    __shared__ float s_m, s_sum;

    float erd = er[d];

    {
        float m = NEGBIG, su = 0.f;
        for (int j = start + t; j < end; j += 64) {
            int s = adj[j];
            float v = el[s] + erd;
            v = (v >= 0.f) ? v : NEG * v;
            float mn = fmaxf(m, v);
            su = su * expf(m - mn) + expf(v - mn);
            m = mn;
        }
#pragma unroll
        for (int off = 16; off; off >>= 1) {
            float m2 = __shfl_xor_sync(0xffffffffu, m, off);
            float s2 = __shfl_xor_sync(0xffffffffu, su, off);
            float mn = fmaxf(m, m2);
            su = su * expf(m - mn) + s2 * expf(m2 - mn);
            m = mn;
        }
        if (lane == 0) { s_mw[w] = m; s_sw[w] = su; }
    }
    __syncthreads();
    if (t == 0) {
        float m0 = s_mw[0], m1 = s_mw[1];
        float mn = fmaxf(m0, m1);
        s_m = mn;
        s_sum = s_sw[0] * expf(m0 - mn) + s_sw[1] * expf(m1 - mn);
    }
    __syncthreads();

    float4 acc = make_float4(0.f, 0.f, 0.f, 0.f);
    for (int c = start; c < end; c += 64) {
        int nchunk = min(64, end - c);
        if (t < nchunk) {
            int s = adj[c + t];
            s_src[t] = s;
            float v = el[s] + erd;
            v = (v >= 0.f) ? v : NEG * v;
            s_alpha[t] = expf(v - s_m) / s_sum;
        }
        __syncthreads();
        int j = 0;
        for (; j + 4 <= nchunk; j += 4) {
            float a0 = s_alpha[j],     a1 = s_alpha[j + 1];
            float a2 = s_alpha[j + 2], a3 = s_alpha[j + 3];
            float4 f0 = ld_ft4(ft + (size_t)s_src[j]     * 256 + 4 * t);
            float4 f1 = ld_ft4(ft + (size_t)s_src[j + 1] * 256 + 4 * t);
            float4 f2 = ld_ft4(ft + (size_t)s_src[j + 2] * 256 + 4 * t);
            float4 f3 = ld_ft4(ft + (size_t)s_src[j + 3] * 256 + 4 * t);
            acc.x += a0 * f0.x + a1 * f1.x + a2 * f2.x + a3 * f3.x;
            acc.y += a0 * f0.y + a1 * f1.y + a2 * f2.y + a3 * f3.y;
            acc.z += a0 * f0.z + a1 * f1.z + a2 * f2.z + a3 * f3.z;
            acc.w += a0 * f0.w + a1 * f1.w + a2 * f2.w + a3 * f3.w;
        }
        for (; j < nchunk; j++) {
            float a = s_alpha[j];
            float4 f = ld_ft4(ft + (size_t)s_src[j] * 256 + 4 * t);
            acc.x += a * f.x; acc.y += a * f.y; acc.z += a * f.z; acc.w += a * f.w;
        }
        __syncthreads();
    }
    float4 hr = *(const float4*)(h1 + (size_t)d * 256 + 4 * t);
    float4 bb = *(const float4*)(b1 + 4 * t);
    float4 o;
    o.x = acc.x + hr.x + bb.x;
    o.y = acc.y + hr.y + bb.y;
    o.z = acc.z + hr.z + bb.z;
    o.w = acc.w + hr.w + bb.w;
    *(float4*)(hout + (size_t)d * 256 + 4 * t) = o;
}

// =================== launch ==================================================
extern "C" void kernel_launch(void* const* d_in, const int* in_sizes, int n_in,
                              void* d_out, int out_size) {
    const float* x   = (const float*)d_in[0];
    const int*   src = (const int*)  d_in[1];
    const int*   dst = (const int*)  d_in[2];
    const float* W0  = (const float*)d_in[3];
    const float* al0 = (const float*)d_in[4];
    const float* ar0 = (const float*)d_in[5];
    const float* b0  = (const float*)d_in[6];
    const float* W1  = (const float*)d_in[7];
    const float* al1 = (const float*)d_in[8];
    const float* ar1 = (const float*)d_in[9];
    const float* b1  = (const float*)d_in[10];
    const float* Wl  = (const float*)d_in[11];
    const float* bl  = (const float*)d_in[12];

    float* out    = (float*)d_out;
    float* logits = out;
    float* hout   = out + (size_t)NN * NCLS;

    __half* ft16;
    float *h1v, *el, *er, *el1, *er1, *wel0, *wel1;
    int *cnt, *rowptr, *bsum, *adj;
    cudaGetSymbolAddress((void**)&ft16,   g_ft16);
    cudaGetSymbolAddress((void**)&h1v,    g_h1);
    cudaGetSymbolAddress((void**)&el,     g_el);
    cudaGetSymbolAddress((void**)&er,     g_er);
    cudaGetSymbolAddress((void**)&el1,    g_el1);
    cudaGetSymbolAddress((void**)&er1,    g_er1);
    cudaGetSymbolAddress((void**)&wel0,   g_wel0);
    cudaGetSymbolAddress((void**)&wel1,   g_wel1);
    cudaGetSymbolAddress((void**)&cnt,    g_cnt);
    cudaGetSymbolAddress((void**)&rowptr, g_rowptr);
    cudaGetSymbolAddress((void**)&bsum,   g_bsum);
    cudaGetSymbolAddress((void**)&adj,    g_adj);

    static cudaStream_t s1 = nullptr, s2 = nullptr;
    static cudaEvent_t ev_fork = nullptr, ev_csr = nullptr, ev_el0 = nullptr;
    if (s1 == nullptr) {
        cudaStreamCreateWithFlags(&s1, cudaStreamNonBlocking);
        cudaStreamCreateWithFlags(&s2, cudaStreamNonBlocking);
        cudaEventCreateWithFlags(&ev_fork, cudaEventDisableTiming);
        cudaEventCreateWithFlags(&ev_csr,  cudaEventDisableTiming);
        cudaEventCreateWithFlags(&ev_el0,  cudaEventDisableTiming);
    }

    const int T = 256;
    const int NB_SCAN = (NN + 1023) / 1024;

    cudaEventRecord(ev_fork, 0);

    // ---- s1: CSR build ----
    cudaStreamWaitEvent(s1, ev_fork, 0);
    cudaMemsetAsync(cnt, 0, NN * sizeof(int), s1);
    hist_kernel<<<(EE + T - 1) / T, T, 0, s1>>>(dst, cnt);
    scan_block_kernel<<<NB_SCAN, 1024, 0, s1>>>(cnt, rowptr, bsum);
    scan_bsum_kernel<<<1, 64, 0, s1>>>(bsum, NB_SCAN);
    scan_add_kernel<<<(NN + T - 1) / T, T, 0, s1>>>(rowptr, bsum, cnt);
    csr_fill_kernel<<<(EE + T - 1) / T, T, 0, s1>>>(src, dst, cnt, adj);
    cudaEventRecord(ev_csr, s1);

    // ---- s2: attention projections ----
    cudaStreamWaitEvent(s2, ev_fork, 0);
    prep_wel_kernel<<<2, 256, 0, s2>>>(W0, al0, ar0, W1, al1, ar1, wel0, wel1);
    eler0_kernel<<<(NN + 7) / 8, 256, 0, s2>>>(x, wel0, el, er);
    cudaEventRecord(ev_el0, s2);

    // ---- main: layer 0 ----
    {
        dim3 grid(256 / 128, (NN + 127) / 128);
        gemm_bf16x3<128, 128, 2, 4, true><<<grid, 256>>>(x, W0, ft16, NN, IND, 256, nullptr);
    }
    cudaStreamWaitEvent(0, ev_csr, 0);
    cudaStreamWaitEvent(0, ev_el0, 0);
    agg0_kernel<<<NN, 64>>>(rowptr, adj, el, er, ft16, b0, wel1, h1v, el1, er1);

    // ---- layer 1 ----
    {
        dim3 grid(256 / 128, (NN + 127) / 128);
        gemm_bf16x3<128, 128, 2, 4, true><<<grid, 256>>>(h1v, W1, ft16, NN, 256, 256, nullptr);
    }
    agg1_kernel<<<NN, 64>>>(rowptr, adj, el1, er1, ft16, h1v, b1, hout);

    // ---- classifier ----
    {
        dim3 grid(1, (NN + 127) / 128);
        gemm_bf16x3<128, 64, 4, 2, false><<<grid, 256>>>(hout, Wl, logits, NN, OUT1, NCLS, bl);
    }
}

// round 8
// speedup vs baseline: 7.3469x; 1.2179x over previous
#include <cuda_runtime.h>
#include <cuda_fp16.h>
#include <math.h>
#include <stdint.h>

#define NN 50000
#define EE 800000
#define IND 256
#define HIDD 64
#define H0 4
#define OUT1 256
#define NCLS 64
#define NEG 0.2f

// ---------------- scratch (device globals; no allocation allowed) ----------
__device__ __half g_ft16[NN * 256];   // projected features, fp16 (gather-only)
__device__ float  g_h1[NN * 256];
__device__ float  g_el[NN * H0];
__device__ float  g_er[NN * H0];
__device__ float  g_el1[NN];
__device__ float  g_er1[NN];
__device__ float  g_wel0[8 * 256];
__device__ float  g_wel1[2 * 256];
__device__ int    g_cnt[NN];
__device__ int    g_rowptr[NN + 1];
__device__ int    g_bsum[64];
__device__ int    g_adj[EE];

// =================== CSR build ==============================================
__global__ void hist_kernel(const int* __restrict__ dst, int* __restrict__ cnt) {
    int e = blockIdx.x * blockDim.x + threadIdx.x;
    if (e < EE) atomicAdd(&cnt[dst[e]], 1);
}

__global__ void scan_block_kernel(const int* __restrict__ cnt,
                                  int* __restrict__ rowptr,
                                  int* __restrict__ bsum) {
    __shared__ int sh[1024];
    int t = threadIdx.x;
    int i = blockIdx.x * 1024 + t;
    int v = (i < NN) ? cnt[i] : 0;
    sh[t] = v;
    __syncthreads();
    for (int off = 1; off < 1024; off <<= 1) {
        int add = (t >= off) ? sh[t - off] : 0;
        __syncthreads();
        sh[t] += add;
        __syncthreads();
    }
    if (i < NN) rowptr[i] = sh[t] - v;
    if (t == 1023) bsum[blockIdx.x] = sh[t];
}

__global__ void scan_bsum_kernel(int* __restrict__ bsum, int nb) {
    __shared__ int sh[64];
    int t = threadIdx.x;
    int v = (t < nb) ? bsum[t] : 0;
    sh[t] = v;
    __syncthreads();
    for (int off = 1; off < 64; off <<= 1) {
        int add = (t >= off) ? sh[t - off] : 0;
        __syncthreads();
        sh[t] += add;
        __syncthreads();
    }
    if (t < nb) bsum[t] = sh[t] - v;
}

__global__ void scan_add_kernel(int* __restrict__ rowptr,
                                const int* __restrict__ bsum,
                                int* __restrict__ cursor) {
    int i = blockIdx.x * blockDim.x + threadIdx.x;
    if (i < NN) {
        int r = rowptr[i] + bsum[i >> 10];
        rowptr[i] = r;
        cursor[i] = r;
    }
    if (i == 0) rowptr[NN] = EE;
}

__global__ void csr_fill_kernel(const int* __restrict__ src,
                                const int* __restrict__ dst,
                                int* __restrict__ cursor,
                                int* __restrict__ adj) {
    int e = blockIdx.x * blockDim.x + threadIdx.x;
    if (e >= EE) return;
    int pos = atomicAdd(&cursor[dst[e]], 1);
    adj[pos] = src[e];
}

// =================== attention projection prep ==============================
__global__ void prep_wel_kernel(const float* __restrict__ W0,
                                const float* __restrict__ al0,
                                const float* __restrict__ ar0,
                                const float* __restrict__ W1,
                                const float* __restrict__ al1,
                                const float* __restrict__ ar1,
                                float* __restrict__ wel0,
                                float* __restrict__ wel1) {
    int k = threadIdx.x;
    if (blockIdx.x == 0) {
#pragma unroll
        for (int j = 0; j < 4; j++) {
            float sl = 0.f, sr = 0.f;
            for (int d = 0; d < 64; d++) {
                float wv = W0[k * 256 + j * 64 + d];
                sl += wv * al0[j * 64 + d];
                sr += wv * ar0[j * 64 + d];
            }
            wel0[j * 256 + k] = sl;
            wel0[(4 + j) * 256 + k] = sr;
        }
    } else {
        float sl = 0.f, sr = 0.f;
        for (int d = 0; d < 256; d++) {
            float wv = W1[k * 256 + d];
            sl += wv * al1[d];
            sr += wv * ar1[d];
        }
        wel1[k] = sl;
        wel1[256 + k] = sr;
    }
}

// el/er = X @ WelT (skinny). One warp per node, 8 warps/block.
__global__ void __launch_bounds__(256)
eler0_kernel(const float* __restrict__ X, const float* __restrict__ WelT,
             float* __restrict__ el, float* __restrict__ er) {
    __shared__ float w[8][256];
    int tid = threadIdx.x;
    for (int i = tid; i < 8 * 256; i += 256) ((float*)w)[i] = WelT[i];
    __syncthreads();
    int n = blockIdx.x * 8 + (tid >> 5);
    int lane = tid & 31;
    if (n >= NN) return;
    const float* xr = X + (size_t)n * 256;
    float acc[8];
#pragma unroll
    for (int j = 0; j < 8; j++) acc[j] = 0.f;
#pragma unroll
    for (int it = 0; it < 8; it++) {
        float xv = xr[lane + it * 32];
#pragma unroll
        for (int j = 0; j < 8; j++) acc[j] += xv * w[j][lane + it * 32];
    }
#pragma unroll
    for (int o = 16; o; o >>= 1)
#pragma unroll
        for (int j = 0; j < 8; j++) acc[j] += __shfl_xor_sync(0xffffffffu, acc[j], o);
    if (lane == 0) {
#pragma unroll
        for (int j = 0; j < 4; j++) el[n * 4 + j] = acc[j];
#pragma unroll
        for (int j = 0; j < 4; j++) er[n * 4 + j] = acc[4 + j];
    }
}

// =================== BF16 3-term split tensor-core GEMM =====================
__device__ __forceinline__ uint32_t packbf(float f0, float f1) {
    uint32_t r;
    asm("cvt.rn.bf16x2.f32 %0, %1, %2;" : "=r"(r) : "f"(f1), "f"(f0));
    return r;
}
__device__ __forceinline__ void bfsplit2(float f0, float f1,
                                         uint32_t& h, uint32_t& l) {
    h = packbf(f0, f1);
    float h0 = __uint_as_float(h << 16);
    float h1 = __uint_as_float(h & 0xffff0000u);
    l = packbf(f0 - h0, f1 - h1);
}

#define MMA_BF16(d, a, b) \
    asm volatile("mma.sync.aligned.m16n8k16.row.col.f32.bf16.bf16.f32 " \
                 "{%0,%1,%2,%3}, {%4,%5,%6,%7}, {%8,%9}, {%0,%1,%2,%3};" \
                 : "+f"(d[0]), "+f"(d[1]), "+f"(d[2]), "+f"(d[3]) \
                 : "r"(a[0]), "r"(a[1]), "r"(a[2]), "r"(a[3]), \
                   "r"(b[0]), "r"(b[1]))

template<int BM, int BN, int WARPS_M, int WARPS_N, bool HOUT>
__global__ void __launch_bounds__(256, 2)
gemm_bf16x3(const float* __restrict__ A, const float* __restrict__ B,
            void* __restrict__ Cv, int Nr, int K, int M,
            const float* __restrict__ bias) {
    constexpr int WM = BM / WARPS_M;
    constexpr int WN = BN / WARPS_N;
    constexpr int MF = WM / 16;
    constexpr int NF = WN / 8;
    constexpr int LD = 136;
    constexpr int STG = 8 * LD;
    constexpr int BQ = BN / 4;

    __shared__ uint32_t Ah[2][STG], Al[2][STG];
    __shared__ uint32_t Bh[2][STG], Bl[2][STG];

    const int tid  = threadIdx.x;
    const int lane = tid & 31;
    const int warp = tid >> 5;
    const int wm = warp / WARPS_N;
    const int wn = warp % WARPS_N;
    const int rowBase = blockIdx.y * BM;
    const int colBase = blockIdx.x * BN;
    const int g  = lane >> 2;
    const int tg = lane & 3;

    float acc[MF][NF][4];
#pragma unroll
    for (int i = 0; i < MF; i++)
#pragma unroll
        for (int j = 0; j < NF; j++)
#pragma unroll
            for (int k = 0; k < 4; k++) acc[i][j][k] = 0.0f;

    float4 ra[2];
    float4 rb0, rb1;
    const int am[2]  = { (tid) >> 2, (tid + 256) >> 2 };
    const int akq[2] = { (tid & 3) << 2, (tid & 3) << 2 };
    const bool bact = tid < 8 * BQ;
    const int bkp = bact ? tid / BQ : 0;
    const int bnq = bact ? (tid % BQ) << 2 : 0;

    auto ldg_tile = [&](int k0) {
#pragma unroll
        for (int i = 0; i < 2; i++) {
            int gr = rowBase + am[i];
            int grc = (gr < Nr) ? gr : (Nr - 1);
            ra[i] = *(const float4*)(A + (size_t)grc * K + k0 + akq[i]);
        }
        if (bact) {
            rb0 = *(const float4*)(B + (size_t)(k0 + 2 * bkp)     * M + colBase + bnq);
            rb1 = *(const float4*)(B + (size_t)(k0 + 2 * bkp + 1) * M + colBase + bnq);
        }
    };

    auto sts_tile = [&](int s) {
#pragma unroll
        for (int i = 0; i < 2; i++) {
            int kp0 = (akq[i] >> 1);
            uint32_t h, l;
            bfsplit2(ra[i].x, ra[i].y, h, l);
            Ah[s][kp0 * LD + am[i]] = h;
            Al[s][kp0 * LD + am[i]] = l;
            bfsplit2(ra[i].z, ra[i].w, h, l);
            Ah[s][(kp0 + 1) * LD + am[i]] = h;
            Al[s][(kp0 + 1) * LD + am[i]] = l;
        }
        if (bact) {
            const float* p0 = &rb0.x;
            const float* p1 = &rb1.x;
            uint32_t hh[4], ll[4];
#pragma unroll
            for (int j = 0; j < 4; j++) bfsplit2(p0[j], p1[j], hh[j], ll[j]);
            *(uint4*)&Bh[s][bkp * LD + bnq] = make_uint4(hh[0], hh[1], hh[2], hh[3]);
            *(uint4*)&Bl[s][bkp * LD + bnq] = make_uint4(ll[0], ll[1], ll[2], ll[3]);
        }
    };

    const int NIT = K / 16;
    ldg_tile(0);

    for (int it = 0; it < NIT; it++) {
        const int s = it & 1;
        sts_tile(s);
        __syncthreads();
        if (it + 1 < NIT) ldg_tile((it + 1) * 16);

        uint32_t bh[NF][2], bl[NF][2];
#pragma unroll
        for (int nf = 0; nf < NF; nf++) {
            int c0 = wn * WN + nf * 8 + g;
            bh[nf][0] = Bh[s][tg * LD + c0];
            bh[nf][1] = Bh[s][(tg + 4) * LD + c0];
            bl[nf][0] = Bl[s][tg * LD + c0];
            bl[nf][1] = Bl[s][(tg + 4) * LD + c0];
        }
#pragma unroll
        for (int mf = 0; mf < MF; mf++) {
            int r0 = wm * WM + mf * 16 + g;
            uint32_t ah[4], al[4];
            ah[0] = Ah[s][tg * LD + r0];
            ah[1] = Ah[s][tg * LD + r0 + 8];
            ah[2] = Ah[s][(tg + 4) * LD + r0];
            ah[3] = Ah[s][(tg + 4) * LD + r0 + 8];
            al[0] = Al[s][tg * LD + r0];
            al[1] = Al[s][tg * LD + r0 + 8];
            al[2] = Al[s][(tg + 4) * LD + r0];
            al[3] = Al[s][(tg + 4) * LD + r0 + 8];
#pragma unroll
            for (int nf = 0; nf < NF; nf++) {
                MMA_BF16(acc[mf][nf], al, bh[nf]);
                MMA_BF16(acc[mf][nf], ah, bl[nf]);
                MMA_BF16(acc[mf][nf], ah, bh[nf]);
            }
        }
    }

#pragma unroll
    for (int mf = 0; mf < MF; mf++) {
#pragma unroll
        for (int nf = 0; nf < NF; nf++) {
            int row = rowBase + wm * WM + mf * 16 + g;
            int col = colBase + wn * WN + nf * 8 + tg * 2;
            if (HOUT) {
                __half* C16 = (__half*)Cv;
                if (row < Nr)
                    *(half2*)(C16 + (size_t)row * M + col) =
                        __floats2half2_rn(acc[mf][nf][0], acc[mf][nf][1]);
                if (row + 8 < Nr)
                    *(half2*)(C16 + (size_t)(row + 8) * M + col) =
                        __floats2half2_rn(acc[mf][nf][2], acc[mf][nf][3]);
            } else {
                float* C = (float*)Cv;
                float b0v = bias ? bias[col]     : 0.0f;
                float b1v = bias ? bias[col + 1] : 0.0f;
                if (row < Nr) {
                    float2 o = make_float2(acc[mf][nf][0] + b0v, acc[mf][nf][1] + b1v);
                    *(float2*)(C + (size_t)row * M + col) = o;
                }
                if (row + 8 < Nr) {
                    float2 o = make_float2(acc[mf][nf][2] + b0v, acc[mf][nf][3] + b1v);
                    *(float2*)(C + (size_t)(row + 8) * M + col) = o;
                }
            }
        }
    }
}

// =================== aggregation (single pass, deferred divide) =============
__device__ __forceinline__ float4 ld_ft4(const __half* p) {
    uint2 r = *(const uint2*)p;
    float2 f01 = __half22float2(*reinterpret_cast<const half2*>(&r.x));
    float2 f23 = __half22float2(*reinterpret_cast<const half2*>(&r.y));
    return make_float4(f01.x, f01.y, f23.x, f23.y);
}

// layer 0: H=4. acc += exp(v)·ft in one pass; divide by sum at the end.
// Fused bias+ELU and layer-1 el/er.
__global__ void __launch_bounds__(64)
agg0_kernel(const int* __restrict__ rowptr, const int* __restrict__ adj,
            const float* __restrict__ el, const float* __restrict__ er,
            const __half* __restrict__ ft, const float* __restrict__ b0,
            const float* __restrict__ wel1,
            float* __restrict__ h1,
            float* __restrict__ el1, float* __restrict__ er1) {
    const int d = blockIdx.x;
    const int t = threadIdx.x;
    const int w = t >> 5;
    const int lane = t & 31;
    const int h = t >> 4;
    const int start = rowptr[d], end = rowptr[d + 1];

    __shared__ int   s_src[64];
    __shared__ float s_num[64 * 4];
    __shared__ float s_part[2][4];
    __shared__ float s_red[2][2];

    float4 erd = *(const float4*)(er + (size_t)d * 4);
    float lsum[4] = {0.f, 0.f, 0.f, 0.f};
    float4 acc = make_float4(0.f, 0.f, 0.f, 0.f);

    for (int c = start; c < end; c += 64) {
        int nchunk = min(64, end - c);
        if (t < nchunk) {
            int s = adj[c + t];
            s_src[t] = s;
            float4 e4 = *(const float4*)(el + (size_t)s * 4);
            float v[4];
            v[0] = e4.x + erd.x; v[1] = e4.y + erd.y;
            v[2] = e4.z + erd.z; v[3] = e4.w + erd.w;
#pragma unroll
            for (int k = 0; k < 4; k++) {
                float vv = (v[k] >= 0.f) ? v[k] : NEG * v[k];
                float nu = expf(vv);
                s_num[t * 4 + k] = nu;
                lsum[k] += nu;
            }
        }
        __syncthreads();
        int j = 0;
        for (; j + 4 <= nchunk; j += 4) {
            float a0 = s_num[j * 4 + h],       a1 = s_num[(j + 1) * 4 + h];
            float a2 = s_num[(j + 2) * 4 + h], a3 = s_num[(j + 3) * 4 + h];
            float4 f0 = ld_ft4(ft + (size_t)s_src[j]     * 256 + 4 * t);
            float4 f1 = ld_ft4(ft + (size_t)s_src[j + 1] * 256 + 4 * t);
            float4 f2 = ld_ft4(ft + (size_t)s_src[j + 2] * 256 + 4 * t);
            float4 f3 = ld_ft4(ft + (size_t)s_src[j + 3] * 256 + 4 * t);
            acc.x += a0 * f0.x + a1 * f1.x + a2 * f2.x + a3 * f3.x;
            acc.y += a0 * f0.y + a1 * f1.y + a2 * f2.y + a3 * f3.y;
            acc.z += a0 * f0.z + a1 * f1.z + a2 * f2.z + a3 * f3.z;
            acc.w += a0 * f0.w + a1 * f1.w + a2 * f2.w + a3 * f3.w;
        }
        for (; j < nchunk; j++) {
            float a = s_num[j * 4 + h];
            float4 f = ld_ft4(ft + (size_t)s_src[j] * 256 + 4 * t);
            acc.x += a * f.x; acc.y += a * f.y; acc.z += a * f.z; acc.w += a * f.w;
        }
        __syncthreads();
    }

    // block-reduce per-head sums
#pragma unroll
    for (int off = 16; off; off >>= 1)
#pragma unroll
        for (int k = 0; k < 4; k++)
            lsum[k] += __shfl_xor_sync(0xffffffffu, lsum[k], off);
    if (lane == 0) {
#pragma unroll
        for (int k = 0; k < 4; k++) s_part[w][k] = lsum[k];
    }
    __syncthreads();
    float tot = s_part[0][h] + s_part[1][h];
    float inv = (tot > 0.f) ? (1.0f / tot) : 0.0f;

    float4 bb = *(const float4*)(b0 + 4 * t);
    float4 o;
    o.x = acc.x * inv + bb.x; o.y = acc.y * inv + bb.y;
    o.z = acc.z * inv + bb.z; o.w = acc.w * inv + bb.w;
    o.x = (o.x > 0.f) ? o.x : expm1f(o.x);
    o.y = (o.y > 0.f) ? o.y : expm1f(o.y);
    o.z = (o.z > 0.f) ? o.z : expm1f(o.z);
    o.w = (o.w > 0.f) ? o.w : expm1f(o.w);
    *(float4*)(h1 + (size_t)d * 256 + 4 * t) = o;

    // fused layer-1 el/er from the h1 row
    float4 wl = *(const float4*)(wel1 + 4 * t);
    float4 wr = *(const float4*)(wel1 + 256 + 4 * t);
    float sl = o.x * wl.x + o.y * wl.y + o.z * wl.z + o.w * wl.w;
    float sr = o.x * wr.x + o.y * wr.y + o.z * wr.z + o.w * wr.w;
#pragma unroll
    for (int off = 16; off; off >>= 1) {
        sl += __shfl_xor_sync(0xffffffffu, sl, off);
        sr += __shfl_xor_sync(0xffffffffu, sr, off);
    }
    if (lane == 0) { s_red[w][0] = sl; s_red[w][1] = sr; }
    __syncthreads();
    if (t == 0) {
        el1[d] = s_red[0][0] + s_red[1][0];
        er1[d] = s_red[0][1] + s_red[1][1];
    }
}

// layer 1: H=1, fused residual + bias.
__global__ void __launch_bounds__(64)
agg1_kernel(const int* __restrict__ rowptr, const int* __restrict__ adj,
            const float* __restrict__ el, const float* __restrict__ er,
            const __half* __restrict__ ft, const float* __restrict__ h1,
            const float* __restrict__ b1, float* __restrict__ hout) {
    const int d = blockIdx.x;
    const int t = threadIdx.x;
    const int w = t >> 5;
    const int lane = t & 31;
    const int start = rowptr[d], end = rowptr[d + 1];

    __shared__ int   s_src[64];
    __shared__ float s_num[64];
    __shared__ float s_part[2];

    float erd = er[d];
    float lsum = 0.f;
    float4 acc = make_float4(0.f, 0.f, 0.f, 0.f);

    for (int c = start; c < end; c += 64) {
        int nchunk = min(64, end - c);
        if (t < nchunk) {
            int s = adj[c + t];
            s_src[t] = s;
            float v = el[s] + erd;
            v = (v >= 0.f) ? v : NEG * v;
            float nu = expf(v);
            s_num[t] = nu;
            lsum += nu;
        }
        __syncthreads();
        int j = 0;
        for (; j + 4 <= nchunk; j += 4) {
            float a0 = s_num[j],     a1 = s_num[j + 1];
            float a2 = s_num[j + 2], a3 = s_num[j + 3];
            float4 f0 = ld_ft4(ft + (size_t)s_src[j]     * 256 + 4 * t);
            float4 f1 = ld_ft4(ft + (size_t)s_src[j + 1] * 256 + 4 * t);
            float4 f2 = ld_ft4(ft + (size_t)s_src[j + 2] * 256 + 4 * t);
            float4 f3 = ld_ft4(ft + (size_t)s_src[j + 3] * 256 + 4 * t);
            acc.x += a0 * f0.x + a1 * f1.x + a2 * f2.x + a3 * f3.x;
            acc.y += a0 * f0.y + a1 * f1.y + a2 * f2.y + a3 * f3.y;
            acc.z += a0 * f0.z + a1 * f1.z + a2 * f2.z + a3 * f3.z;
            acc.w += a0 * f0.w + a1 * f1.w + a2 * f2.w + a3 * f3.w;
        }
        for (; j < nchunk; j++) {
            float a = s_num[j];
            float4 f = ld_ft4(ft + (size_t)s_src[j] * 256 + 4 * t);
            acc.x += a * f.x; acc.y += a * f.y; acc.z += a * f.z; acc.w += a * f.w;
        }
        __syncthreads();
    }

#pragma unroll
    for (int off = 16; off; off >>= 1)
        lsum += __shfl_xor_sync(0xffffffffu, lsum, off);
    if (lane == 0) s_part[w] = lsum;
    __syncthreads();
    float tot = s_part[0] + s_part[1];
    float inv = (tot > 0.f) ? (1.0f / tot) : 0.0f;

    float4 hr = *(const float4*)(h1 + (size_t)d * 256 + 4 * t);
    float4 bb = *(const float4*)(b1 + 4 * t);
    float4 o;
    o.x = acc.x * inv + hr.x + bb.x;
    o.y = acc.y * inv + hr.y + bb.y;
    o.z = acc.z * inv + hr.z + bb.z;
    o.w = acc.w * inv + hr.w + bb.w;
    *(float4*)(hout + (size_t)d * 256 + 4 * t) = o;
}

// =================== launch ==================================================
extern "C" void kernel_launch(void* const* d_in, const int* in_sizes, int n_in,
                              void* d_out, int out_size) {
    const float* x   = (const float*)d_in[0];
    const int*   src = (const int*)  d_in[1];
    const int*   dst = (const int*)  d_in[2];
    const float* W0  = (const float*)d_in[3];
    const float* al0 = (const float*)d_in[4];
    const float* ar0 = (const float*)d_in[5];
    const float* b0  = (const float*)d_in[6];
    const float* W1  = (const float*)d_in[7];
    const float* al1 = (const float*)d_in[8];
    const float* ar1 = (const float*)d_in[9];
    const float* b1  = (const float*)d_in[10];
    const float* Wl  = (const float*)d_in[11];
    const float* bl  = (const float*)d_in[12];

    float* out    = (float*)d_out;
    float* logits = out;
    float* hout   = out + (size_t)NN * NCLS;

    __half* ft16;
    float *h1v, *el, *er, *el1, *er1, *wel0, *wel1;
    int *cnt, *rowptr, *bsum, *adj;
    cudaGetSymbolAddress((void**)&ft16,   g_ft16);
    cudaGetSymbolAddress((void**)&h1v,    g_h1);
    cudaGetSymbolAddress((void**)&el,     g_el);
    cudaGetSymbolAddress((void**)&er,     g_er);
    cudaGetSymbolAddress((void**)&el1,    g_el1);
    cudaGetSymbolAddress((void**)&er1,    g_er1);
    cudaGetSymbolAddress((void**)&wel0,   g_wel0);
    cudaGetSymbolAddress((void**)&wel1,   g_wel1);
    cudaGetSymbolAddress((void**)&cnt,    g_cnt);
    cudaGetSymbolAddress((void**)&rowptr, g_rowptr);
    cudaGetSymbolAddress((void**)&bsum,   g_bsum);
    cudaGetSymbolAddress((void**)&adj,    g_adj);

    static cudaStream_t s1 = nullptr, s2 = nullptr;
    static cudaEvent_t ev_fork = nullptr, ev_csr = nullptr, ev_el0 = nullptr;
    if (s1 == nullptr) {
        cudaStreamCreateWithFlags(&s1, cudaStreamNonBlocking);
        cudaStreamCreateWithFlags(&s2, cudaStreamNonBlocking);
        cudaEventCreateWithFlags(&ev_fork, cudaEventDisableTiming);
        cudaEventCreateWithFlags(&ev_csr,  cudaEventDisableTiming);
        cudaEventCreateWithFlags(&ev_el0,  cudaEventDisableTiming);
    }

    const int T = 256;
    const int NB_SCAN = (NN + 1023) / 1024;

    cudaEventRecord(ev_fork, 0);

    // ---- s1: CSR build ----
    cudaStreamWaitEvent(s1, ev_fork, 0);
    cudaMemsetAsync(cnt, 0, NN * sizeof(int), s1);
    hist_kernel<<<(EE + T - 1) / T, T, 0, s1>>>(dst, cnt);
    scan_block_kernel<<<NB_SCAN, 1024, 0, s1>>>(cnt, rowptr, bsum);
    scan_bsum_kernel<<<1, 64, 0, s1>>>(bsum, NB_SCAN);
    scan_add_kernel<<<(NN + T - 1) / T, T, 0, s1>>>(rowptr, bsum, cnt);
    csr_fill_kernel<<<(EE + T - 1) / T, T, 0, s1>>>(src, dst, cnt, adj);
    cudaEventRecord(ev_csr, s1);

    // ---- s2: attention projections ----
    cudaStreamWaitEvent(s2, ev_fork, 0);
    prep_wel_kernel<<<2, 256, 0, s2>>>(W0, al0, ar0, W1, al1, ar1, wel0, wel1);
    eler0_kernel<<<(NN + 7) / 8, 256, 0, s2>>>(x, wel0, el, er);
    cudaEventRecord(ev_el0, s2);

    // ---- main: layer 0 ----
    {
        dim3 grid(256 / 128, (NN + 127) / 128);
        gemm_bf16x3<128, 128, 2, 4, true><<<grid, 256>>>(x, W0, ft16, NN, IND, 256, nullptr);
    }
    cudaStreamWaitEvent(0, ev_csr, 0);
    cudaStreamWaitEvent(0, ev_el0, 0);
    agg0_kernel<<<NN, 64>>>(rowptr, adj, el, er, ft16, b0, wel1, h1v, el1, er1);

    // ---- layer 1 ----
    {
        dim3 grid(256 / 128, (NN + 127) / 128);
        gemm_bf16x3<128, 128, 2, 4, true><<<grid, 256>>>(h1v, W1, ft16, NN, 256, 256, nullptr);
    }
    agg1_kernel<<<NN, 64>>>(rowptr, adj, el1, er1, ft16, h1v, b1, hout);

    // ---- classifier ----
    {
        dim3 grid(1, (NN + 127) / 128);
        gemm_bf16x3<128, 64, 4, 2, false><<<grid, 256>>>(hout, Wl, logits, NN, OUT1, NCLS, bl);
    }
}

// round 9
// speedup vs baseline: 7.6810x; 1.0455x over previous
#include <cuda_runtime.h>
#include <cuda_fp16.h>
#include <math.h>
#include <stdint.h>

#define NN 50000
#define EE 800000
#define IND 256
#define HIDD 64
#define H0 4
#define OUT1 256
#define NCLS 64
#define NEG 0.2f
#define NA_SPLIT 25088   // agg0 / GEMM1 pipeline split (multiple of 128)

// ---------------- scratch (device globals; no allocation allowed) ----------
__device__ __half g_ft16[NN * 256];
__device__ float  g_h1[NN * 256];
__device__ float  g_el[NN * H0];
__device__ float  g_er[NN * H0];
__device__ float  g_el1[NN];
__device__ float  g_er1[NN];
__device__ float  g_wel0[8 * 256];
__device__ float  g_wel1[2 * 256];
__device__ int    g_cnt[NN];
__device__ int    g_rowptr[NN + 1];
__device__ int    g_bsum[64];
__device__ int    g_adj[EE];

// =================== CSR build ==============================================
__global__ void hist_kernel(const int* __restrict__ dst, int* __restrict__ cnt) {
    int e = blockIdx.x * blockDim.x + threadIdx.x;
    if (e < EE) atomicAdd(&cnt[dst[e]], 1);
}

__global__ void scan_block_kernel(const int* __restrict__ cnt,
                                  int* __restrict__ rowptr,
                                  int* __restrict__ bsum) {
    __shared__ int sh[1024];
    int t = threadIdx.x;
    int i = blockIdx.x * 1024 + t;
    int v = (i < NN) ? cnt[i] : 0;
    sh[t] = v;
    __syncthreads();
    for (int off = 1; off < 1024; off <<= 1) {
        int add = (t >= off) ? sh[t - off] : 0;
        __syncthreads();
        sh[t] += add;
        __syncthreads();
    }
    if (i < NN) rowptr[i] = sh[t] - v;
    if (t == 1023) bsum[blockIdx.x] = sh[t];
}

__global__ void scan_bsum_kernel(int* __restrict__ bsum, int nb) {
    __shared__ int sh[64];
    int t = threadIdx.x;
    int v = (t < nb) ? bsum[t] : 0;
    sh[t] = v;
    __syncthreads();
    for (int off = 1; off < 64; off <<= 1) {
        int add = (t >= off) ? sh[t - off] : 0;
        __syncthreads();
        sh[t] += add;
        __syncthreads();
    }
    if (t < nb) bsum[t] = sh[t] - v;
}

__global__ void scan_add_kernel(int* __restrict__ rowptr,
                                const int* __restrict__ bsum,
                                int* __restrict__ cursor) {
    int i = blockIdx.x * blockDim.x + threadIdx.x;
    if (i < NN) {
        int r = rowptr[i] + bsum[i >> 10];
        rowptr[i] = r;
        cursor[i] = r;
    }
    if (i == 0) rowptr[NN] = EE;
}

__global__ void csr_fill_kernel(const int* __restrict__ src,
                                const int* __restrict__ dst,
                                int* __restrict__ cursor,
                                int* __restrict__ adj) {
    int e = blockIdx.x * blockDim.x + threadIdx.x;
    if (e >= EE) return;
    int pos = atomicAdd(&cursor[dst[e]], 1);
    adj[pos] = src[e];
}

// =================== attention projection prep ==============================
__global__ void prep_wel_kernel(const float* __restrict__ W0,
                                const float* __restrict__ al0,
                                const float* __restrict__ ar0,
                                const float* __restrict__ W1,
                                const float* __restrict__ al1,
                                const float* __restrict__ ar1,
                                float* __restrict__ wel0,
                                float* __restrict__ wel1) {
    int k = threadIdx.x;
    if (blockIdx.x == 0) {
#pragma unroll
        for (int j = 0; j < 4; j++) {
            float sl = 0.f, sr = 0.f;
            for (int d = 0; d < 64; d++) {
                float wv = W0[k * 256 + j * 64 + d];
                sl += wv * al0[j * 64 + d];
                sr += wv * ar0[j * 64 + d];
            }
            wel0[j * 256 + k] = sl;
            wel0[(4 + j) * 256 + k] = sr;
        }
    } else {
        float sl = 0.f, sr = 0.f;
        for (int d = 0; d < 256; d++) {
            float wv = W1[k * 256 + d];
            sl += wv * al1[d];
            sr += wv * ar1[d];
        }
        wel1[k] = sl;
        wel1[256 + k] = sr;
    }
}

__global__ void __launch_bounds__(256)
eler0_kernel(const float* __restrict__ X, const float* __restrict__ WelT,
             float* __restrict__ el, float* __restrict__ er) {
    __shared__ float w[8][256];
    int tid = threadIdx.x;
    for (int i = tid; i < 8 * 256; i += 256) ((float*)w)[i] = WelT[i];
    __syncthreads();
    int n = blockIdx.x * 8 + (tid >> 5);
    int lane = tid & 31;
    if (n >= NN) return;
    const float* xr = X + (size_t)n * 256;
    float acc[8];
#pragma unroll
    for (int j = 0; j < 8; j++) acc[j] = 0.f;
#pragma unroll
    for (int it = 0; it < 8; it++) {
        float xv = xr[lane + it * 32];
#pragma unroll
        for (int j = 0; j < 8; j++) acc[j] += xv * w[j][lane + it * 32];
    }
#pragma unroll
    for (int o = 16; o; o >>= 1)
#pragma unroll
        for (int j = 0; j < 8; j++) acc[j] += __shfl_xor_sync(0xffffffffu, acc[j], o);
    if (lane == 0) {
#pragma unroll
        for (int j = 0; j < 4; j++) el[n * 4 + j] = acc[j];
#pragma unroll
        for (int j = 0; j < 4; j++) er[n * 4 + j] = acc[4 + j];
    }
}

// =================== BF16 3-term split tensor-core GEMM =====================
__device__ __forceinline__ uint32_t packbf(float f0, float f1) {
    uint32_t r;
    asm("cvt.rn.bf16x2.f32 %0, %1, %2;" : "=r"(r) : "f"(f1), "f"(f0));
    return r;
}
__device__ __forceinline__ void bfsplit2(float f0, float f1,
                                         uint32_t& h, uint32_t& l) {
    h = packbf(f0, f1);
    float h0 = __uint_as_float(h << 16);
    float h1 = __uint_as_float(h & 0xffff0000u);
    l = packbf(f0 - h0, f1 - h1);
}

#define MMA_BF16(d, a, b) \
    asm volatile("mma.sync.aligned.m16n8k16.row.col.f32.bf16.bf16.f32 " \
                 "{%0,%1,%2,%3}, {%4,%5,%6,%7}, {%8,%9}, {%0,%1,%2,%3};" \
                 : "+f"(d[0]), "+f"(d[1]), "+f"(d[2]), "+f"(d[3]) \
                 : "r"(a[0]), "r"(a[1]), "r"(a[2]), "r"(a[3]), \
                   "r"(b[0]), "r"(b[1]))

template<int BM, int BN, int WARPS_M, int WARPS_N, bool HOUT>
__global__ void __launch_bounds__(256, 2)
gemm_bf16x3(const float* __restrict__ A, const float* __restrict__ B,
            void* __restrict__ Cv, int Nr, int K, int M,
            const float* __restrict__ bias) {
    constexpr int WM = BM / WARPS_M;
    constexpr int WN = BN / WARPS_N;
    constexpr int MF = WM / 16;
    constexpr int NF = WN / 8;
    constexpr int LD = 136;
    constexpr int STG = 8 * LD;
    constexpr int BQ = BN / 4;

    __shared__ uint32_t Ah[2][STG], Al[2][STG];
    __shared__ uint32_t Bh[2][STG], Bl[2][STG];

    const int tid  = threadIdx.x;
    const int lane = tid & 31;
    const int warp = tid >> 5;
    const int wm = warp / WARPS_N;
    const int wn = warp % WARPS_N;
    const int rowBase = blockIdx.y * BM;
    const int colBase = blockIdx.x * BN;
    const int g  = lane >> 2;
    const int tg = lane & 3;

    float acc[MF][NF][4];
#pragma unroll
    for (int i = 0; i < MF; i++)
#pragma unroll
        for (int j = 0; j < NF; j++)
#pragma unroll
            for (int k = 0; k < 4; k++) acc[i][j][k] = 0.0f;

    float4 ra[2];
    float4 rb0, rb1;
    const int am[2]  = { (tid) >> 2, (tid + 256) >> 2 };
    const int akq[2] = { (tid & 3) << 2, (tid & 3) << 2 };
    const bool bact = tid < 8 * BQ;
    const int bkp = bact ? tid / BQ : 0;
    const int bnq = bact ? (tid % BQ) << 2 : 0;

    auto ldg_tile = [&](int k0) {
#pragma unroll
        for (int i = 0; i < 2; i++) {
            int gr = rowBase + am[i];
            int grc = (gr < Nr) ? gr : (Nr - 1);
            ra[i] = *(const float4*)(A + (size_t)grc * K + k0 + akq[i]);
        }
        if (bact) {
            rb0 = *(const float4*)(B + (size_t)(k0 + 2 * bkp)     * M + colBase + bnq);
            rb1 = *(const float4*)(B + (size_t)(k0 + 2 * bkp + 1) * M + colBase + bnq);
        }
    };

    auto sts_tile = [&](int s) {
#pragma unroll
        for (int i = 0; i < 2; i++) {
            int kp0 = (akq[i] >> 1);
            uint32_t h, l;
            bfsplit2(ra[i].x, ra[i].y, h, l);
            Ah[s][kp0 * LD + am[i]] = h;
            Al[s][kp0 * LD + am[i]] = l;
            bfsplit2(ra[i].z, ra[i].w, h, l);
            Ah[s][(kp0 + 1) * LD + am[i]] = h;
            Al[s][(kp0 + 1) * LD + am[i]] = l;
        }
        if (bact) {
            const float* p0 = &rb0.x;
            const float* p1 = &rb1.x;
            uint32_t hh[4], ll[4];
#pragma unroll
            for (int j = 0; j < 4; j++) bfsplit2(p0[j], p1[j], hh[j], ll[j]);
            *(uint4*)&Bh[s][bkp * LD + bnq] = make_uint4(hh[0], hh[1], hh[2], hh[3]);
            *(uint4*)&Bl[s][bkp * LD + bnq] = make_uint4(ll[0], ll[1], ll[2], ll[3]);
        }
    };

    const int NIT = K / 16;
    ldg_tile(0);

    for (int it = 0; it < NIT; it++) {
        const int s = it & 1;
        sts_tile(s);
        __syncthreads();
        if (it + 1 < NIT) ldg_tile((it + 1) * 16);

        uint32_t bh[NF][2], bl[NF][2];
#pragma unroll
        for (int nf = 0; nf < NF; nf++) {
            int c0 = wn * WN + nf * 8 + g;
            bh[nf][0] = Bh[s][tg * LD + c0];
            bh[nf][1] = Bh[s][(tg + 4) * LD + c0];
            bl[nf][0] = Bl[s][tg * LD + c0];
            bl[nf][1] = Bl[s][(tg + 4) * LD + c0];
        }
#pragma unroll
        for (int mf = 0; mf < MF; mf++) {
            int r0 = wm * WM + mf * 16 + g;
            uint32_t ah[4], al[4];
            ah[0] = Ah[s][tg * LD + r0];
            ah[1] = Ah[s][tg * LD + r0 + 8];
            ah[2] = Ah[s][(tg + 4) * LD + r0];
            ah[3] = Ah[s][(tg + 4) * LD + r0 + 8];
            al[0] = Al[s][tg * LD + r0];
            al[1] = Al[s][tg * LD + r0 + 8];
            al[2] = Al[s][(tg + 4) * LD + r0];
            al[3] = Al[s][(tg + 4) * LD + r0 + 8];
#pragma unroll
            for (int nf = 0; nf < NF; nf++) {
                MMA_BF16(acc[mf][nf], al, bh[nf]);
                MMA_BF16(acc[mf][nf], ah, bl[nf]);
                MMA_BF16(acc[mf][nf], ah, bh[nf]);
            }
        }
    }

#pragma unroll
    for (int mf = 0; mf < MF; mf++) {
#pragma unroll
        for (int nf = 0; nf < NF; nf++) {
            int row = rowBase + wm * WM + mf * 16 + g;
            int col = colBase + wn * WN + nf * 8 + tg * 2;
            if (HOUT) {
                __half* C16 = (__half*)Cv;
                if (row < Nr)
                    *(half2*)(C16 + (size_t)row * M + col) =
                        __floats2half2_rn(acc[mf][nf][0], acc[mf][nf][1]);
                if (row + 8 < Nr)
                    *(half2*)(C16 + (size_t)(row + 8) * M + col) =
                        __floats2half2_rn(acc[mf][nf][2], acc[mf][nf][3]);
            } else {
                float* C = (float*)Cv;
                float b0v = bias ? bias[col]     : 0.0f;
                float b1v = bias ? bias[col + 1] : 0.0f;
                if (row < Nr) {
                    float2 o = make_float2(acc[mf][nf][0] + b0v, acc[mf][nf][1] + b1v);
                    *(float2*)(C + (size_t)row * M + col) = o;
                }
                if (row + 8 < Nr) {
                    float2 o = make_float2(acc[mf][nf][2] + b0v, acc[mf][nf][3] + b1v);
                    *(float2*)(C + (size_t)(row + 8) * M + col) = o;
                }
            }
        }
    }
}

// =================== aggregation: one WARP per dst node =====================
// lane owns 8 features (one uint4 of fp16). 8 nodes per 256-thread block.
__device__ __forceinline__ void acc8(float* acc, float a, uint4 r) {
    float2 f0 = __half22float2(*reinterpret_cast<const half2*>(&r.x));
    float2 f1 = __half22float2(*reinterpret_cast<const half2*>(&r.y));
    float2 f2 = __half22float2(*reinterpret_cast<const half2*>(&r.z));
    float2 f3 = __half22float2(*reinterpret_cast<const half2*>(&r.w));
    acc[0] += a * f0.x; acc[1] += a * f0.y;
    acc[2] += a * f1.x; acc[3] += a * f1.y;
    acc[4] += a * f2.x; acc[5] += a * f2.y;
    acc[6] += a * f3.x; acc[7] += a * f3.y;
}

// layer 0: H=4. Fused bias+ELU and layer-1 el/er. Node range [nbase, nend).
__global__ void __launch_bounds__(256)
agg0_kernel(const int* __restrict__ rowptr, const int* __restrict__ adj,
            const float* __restrict__ el, const float* __restrict__ er,
            const __half* __restrict__ ft, const float* __restrict__ b0,
            const float* __restrict__ wel1,
            float* __restrict__ h1,
            float* __restrict__ el1, float* __restrict__ er1,
            int nbase, int nend) {
    const int w = threadIdx.x >> 5;
    const int lane = threadIdx.x & 31;
    const int d = nbase + blockIdx.x * 8 + w;
    if (d >= nend) return;
    const int h = lane >> 3;            // head of this lane's features
    const int start = rowptr[d], end = rowptr[d + 1];

    __shared__ float s_num[8][32][4];

    float4 erd = *(const float4*)(er + (size_t)d * 4);
    float lsum[4] = {0.f, 0.f, 0.f, 0.f};
    float acc[8] = {0.f, 0.f, 0.f, 0.f, 0.f, 0.f, 0.f, 0.f};

    for (int c = start; c < end; c += 32) {
        int n = min(32, end - c);
        int sidx = 0;
        if (lane < n) {
            sidx = adj[c + lane];
            float4 e4 = *(const float4*)(el + (size_t)sidx * 4);
            float v[4];
            v[0] = e4.x + erd.x; v[1] = e4.y + erd.y;
            v[2] = e4.z + erd.z; v[3] = e4.w + erd.w;
#pragma unroll
            for (int k = 0; k < 4; k++) {
                float vv = (v[k] >= 0.f) ? v[k] : NEG * v[k];
                float nu = expf(vv);
                s_num[w][lane][k] = nu;
                lsum[k] += nu;
            }
        }
        __syncwarp();
        int j = 0;
        for (; j + 2 <= n; j += 2) {
            int s0 = __shfl_sync(0xffffffffu, sidx, j);
            int s1 = __shfl_sync(0xffffffffu, sidx, j + 1);
            float a0 = s_num[w][j][h];
            float a1 = s_num[w][j + 1][h];
            uint4 r0 = *(const uint4*)(ft + (size_t)s0 * 256 + lane * 8);
            uint4 r1 = *(const uint4*)(ft + (size_t)s1 * 256 + lane * 8);
            acc8(acc, a0, r0);
            acc8(acc, a1, r1);
        }
        if (j < n) {
            int s0 = __shfl_sync(0xffffffffu, sidx, j);
            float a0 = s_num[w][j][h];
            uint4 r0 = *(const uint4*)(ft + (size_t)s0 * 256 + lane * 8);
            acc8(acc, a0, r0);
        }
        __syncwarp();
    }

    // warp-reduce the 4 head sums (all lanes get totals)
#pragma unroll
    for (int off = 16; off; off >>= 1)
#pragma unroll
        for (int k = 0; k < 4; k++)
            lsum[k] += __shfl_xor_sync(0xffffffffu, lsum[k], off);
    float tot = lsum[h];
    float inv = (tot > 0.f) ? (1.0f / tot) : 0.0f;

    // epilogue: bias + ELU, store, fused layer-1 el/er
    float o[8];
    float sl = 0.f, sr = 0.f;
    const float* bb = b0 + lane * 8;
    const float* wl = wel1 + lane * 8;
    const float* wr = wel1 + 256 + lane * 8;
#pragma unroll
    for (int i = 0; i < 8; i++) {
        float v = acc[i] * inv + bb[i];
        v = (v > 0.f) ? v : expm1f(v);
        o[i] = v;
        sl += v * wl[i];
        sr += v * wr[i];
    }
    *(float4*)(h1 + (size_t)d * 256 + lane * 8)     = make_float4(o[0], o[1], o[2], o[3]);
    *(float4*)(h1 + (size_t)d * 256 + lane * 8 + 4) = make_float4(o[4], o[5], o[6], o[7]);
#pragma unroll
    for (int off = 16; off; off >>= 1) {
        sl += __shfl_xor_sync(0xffffffffu, sl, off);
        sr += __shfl_xor_sync(0xffffffffu, sr, off);
    }
    if (lane == 0) { el1[d] = sl; er1[d] = sr; }
}

// layer 1: H=1, fused residual + bias. No smem (alpha via shuffle).
__global__ void __launch_bounds__(256)
agg1_kernel(const int* __restrict__ rowptr, const int* __restrict__ adj,
            const float* __restrict__ el, const float* __restrict__ er,
            const __half* __restrict__ ft, const float* __restrict__ h1,
            const float* __restrict__ b1, float* __restrict__ hout) {
    const int w = threadIdx.x >> 5;
    const int lane = threadIdx.x & 31;
    const int d = blockIdx.x * 8 + w;
    if (d >= NN) return;
    const int start = rowptr[d], end = rowptr[d + 1];

    float erd = er[d];
    float lsum = 0.f;
    float acc[8] = {0.f, 0.f, 0.f, 0.f, 0.f, 0.f, 0.f, 0.f};

    for (int c = start; c < end; c += 32) {
        int n = min(32, end - c);
        int sidx = 0;
        float nu = 0.f;
        if (lane < n) {
            sidx = adj[c + lane];
            float v = el[sidx] + erd;
            v = (v >= 0.f) ? v : NEG * v;
            nu = expf(v);
            lsum += nu;
        }
        int j = 0;
        for (; j + 2 <= n; j += 2) {
            int s0 = __shfl_sync(0xffffffffu, sidx, j);
            int s1 = __shfl_sync(0xffffffffu, sidx, j + 1);
            float a0 = __shfl_sync(0xffffffffu, nu, j);
            float a1 = __shfl_sync(0xffffffffu, nu, j + 1);
            uint4 r0 = *(const uint4*)(ft + (size_t)s0 * 256 + lane * 8);
            uint4 r1 = *(const uint4*)(ft + (size_t)s1 * 256 + lane * 8);
            acc8(acc, a0, r0);
            acc8(acc, a1, r1);
        }
        if (j < n) {
            int s0 = __shfl_sync(0xffffffffu, sidx, j);
            float a0 = __shfl_sync(0xffffffffu, nu, j);
            uint4 r0 = *(const uint4*)(ft + (size_t)s0 * 256 + lane * 8);
            acc8(acc, a0, r0);
        }
    }

#pragma unroll
    for (int off = 16; off; off >>= 1)
        lsum += __shfl_xor_sync(0xffffffffu, lsum, off);
    float inv = (lsum > 0.f) ? (1.0f / lsum) : 0.0f;

    float4 hr0 = *(const float4*)(h1 + (size_t)d * 256 + lane * 8);
    float4 hr1 = *(const float4*)(h1 + (size_t)d * 256 + lane * 8 + 4);
    float4 bb0 = *(const float4*)(b1 + lane * 8);
    float4 bb1 = *(const float4*)(b1 + lane * 8 + 4);
    float4 o0, o1;
    o0.x = acc[0] * inv + hr0.x + bb0.x;
    o0.y = acc[1] * inv + hr0.y + bb0.y;
    o0.z = acc[2] * inv + hr0.z + bb0.z;
    o0.w = acc[3] * inv + hr0.w + bb0.w;
    o1.x = acc[4] * inv + hr1.x + bb1.x;
    o1.y = acc[5] * inv + hr1.y + bb1.y;
    o1.z = acc[6] * inv + hr1.z + bb1.z;
    o1.w = acc[7] * inv + hr1.w + bb1.w;
    *(float4*)(hout + (size_t)d * 256 + lane * 8)     = o0;
    *(float4*)(hout + (size_t)d * 256 + lane * 8 + 4) = o1;
}

// =================== launch ==================================================
extern "C" void kernel_launch(void* const* d_in, const int* in_sizes, int n_in,
                              void* d_out, int out_size) {
    const float* x   = (const float*)d_in[0];
    const int*   src = (const int*)  d_in[1];
    const int*   dst = (const int*)  d_in[2];
    const float* W0  = (const float*)d_in[3];
    const float* al0 = (const float*)d_in[4];
    const float* ar0 = (const float*)d_in[5];
    const float* b0  = (const float*)d_in[6];
    const float* W1  = (const float*)d_in[7];
    const float* al1 = (const float*)d_in[8];
    const float* ar1 = (const float*)d_in[9];
    const float* b1  = (const float*)d_in[10];
    const float* Wl  = (const float*)d_in[11];
    const float* bl  = (const float*)d_in[12];

    float* out    = (float*)d_out;
    float* logits = out;
    float* hout   = out + (size_t)NN * NCLS;

    __half* ft16;
    float *h1v, *el, *er, *el1, *er1, *wel0, *wel1;
    int *cnt, *rowptr, *bsum, *adj;
    cudaGetSymbolAddress((void**)&ft16,   g_ft16);
    cudaGetSymbolAddress((void**)&h1v,    g_h1);
    cudaGetSymbolAddress((void**)&el,     g_el);
    cudaGetSymbolAddress((void**)&er,     g_er);
    cudaGetSymbolAddress((void**)&el1,    g_el1);
    cudaGetSymbolAddress((void**)&er1,    g_er1);
    cudaGetSymbolAddress((void**)&wel0,   g_wel0);
    cudaGetSymbolAddress((void**)&wel1,   g_wel1);
    cudaGetSymbolAddress((void**)&cnt,    g_cnt);
    cudaGetSymbolAddress((void**)&rowptr, g_rowptr);
    cudaGetSymbolAddress((void**)&bsum,   g_bsum);
    cudaGetSymbolAddress((void**)&adj,    g_adj);

    static cudaStream_t s1 = nullptr, s2 = nullptr;
    static cudaEvent_t ev_fork = nullptr, ev_csr = nullptr, ev_el0 = nullptr,
                       ev_g0 = nullptr, ev_a0b = nullptr;
    if (s1 == nullptr) {
        cudaStreamCreateWithFlags(&s1, cudaStreamNonBlocking);
        cudaStreamCreateWithFlags(&s2, cudaStreamNonBlocking);
        cudaEventCreateWithFlags(&ev_fork, cudaEventDisableTiming);
        cudaEventCreateWithFlags(&ev_csr,  cudaEventDisableTiming);
        cudaEventCreateWithFlags(&ev_el0,  cudaEventDisableTiming);
        cudaEventCreateWithFlags(&ev_g0,   cudaEventDisableTiming);
        cudaEventCreateWithFlags(&ev_a0b,  cudaEventDisableTiming);
    }

    const int T = 256;
    const int NB_SCAN = (NN + 1023) / 1024;

    cudaEventRecord(ev_fork, 0);

    // ---- s1: CSR build ----
    cudaStreamWaitEvent(s1, ev_fork, 0);
    cudaMemsetAsync(cnt, 0, NN * sizeof(int), s1);
    hist_kernel<<<(EE + T - 1) / T, T, 0, s1>>>(dst, cnt);
    scan_block_kernel<<<NB_SCAN, 1024, 0, s1>>>(cnt, rowptr, bsum);
    scan_bsum_kernel<<<1, 64, 0, s1>>>(bsum, NB_SCAN);
    scan_add_kernel<<<(NN + T - 1) / T, T, 0, s1>>>(rowptr, bsum, cnt);
    csr_fill_kernel<<<(EE + T - 1) / T, T, 0, s1>>>(src, dst, cnt, adj);
    cudaEventRecord(ev_csr, s1);

    // ---- s2: attention projections ----
    cudaStreamWaitEvent(s2, ev_fork, 0);
    prep_wel_kernel<<<2, 256, 0, s2>>>(W0, al0, ar0, W1, al1, ar1, wel0, wel1);
    eler0_kernel<<<(NN + 7) / 8, 256, 0, s2>>>(x, wel0, el, er);
    cudaEventRecord(ev_el0, s2);

    // ---- main: layer 0 projection ----
    {
        dim3 grid(256 / 128, (NN + 127) / 128);
        gemm_bf16x3<128, 128, 2, 4, true><<<grid, 256>>>(x, W0, ft16, NN, IND, 256, nullptr);
    }
    cudaEventRecord(ev_g0, 0);

    // ---- agg0 chunk B on s2 (concurrent with agg0_A + GEMM1_A on main) ----
    cudaStreamWaitEvent(s2, ev_g0, 0);
    cudaStreamWaitEvent(s2, ev_csr, 0);   // el0 already ordered on s2
    {
        int nb = NN - NA_SPLIT;
        agg0_kernel<<<(nb + 7) / 8, 256, 0, s2>>>(rowptr, adj, el, er, ft16, b0,
                                                  wel1, h1v, el1, er1, NA_SPLIT, NN);
    }
    cudaEventRecord(ev_a0b, s2);

    // ---- main: agg0 chunk A, then GEMM1_A ----
    cudaStreamWaitEvent(0, ev_csr, 0);
    cudaStreamWaitEvent(0, ev_el0, 0);
    agg0_kernel<<<NA_SPLIT / 8, 256>>>(rowptr, adj, el, er, ft16, b0,
                                       wel1, h1v, el1, er1, 0, NA_SPLIT);
    {
        dim3 grid(256 / 128, NA_SPLIT / 128);
        gemm_bf16x3<128, 128, 2, 4, true><<<grid, 256>>>(h1v, W1, ft16, NA_SPLIT, 256, 256, nullptr);
    }

    // ---- main: GEMM1_B after agg0_B ----
    cudaStreamWaitEvent(0, ev_a0b, 0);
    {
        int nb = NN - NA_SPLIT;
        dim3 grid(256 / 128, (nb + 127) / 128);
        gemm_bf16x3<128, 128, 2, 4, true><<<grid, 256>>>(
            h1v + (size_t)NA_SPLIT * 256, W1,
            ft16 + (size_t)NA_SPLIT * 256, nb, 256, 256, nullptr);
    }

    // ---- agg1 + classifier ----
    agg1_kernel<<<(NN + 7) / 8, 256>>>(rowptr, adj, el1, er1, ft16, h1v, b1, hout);
    {
        dim3 grid(1, (NN + 127) / 128);
        gemm_bf16x3<128, 64, 4, 2, false><<<grid, 256>>>(hout, Wl, logits, NN, OUT1, NCLS, bl);
    }
}